// round 6
// baseline (speedup 1.0000x reference)
#include <cuda_runtime.h>
#include <cuda_bf16.h>
#include <cstdint>
#include <cstddef>

// Problem constants (fixed shapes)
#define NMAX 100000
#define GCNT 512
#define NLAYER 4

// tcgen05 only exists in the arch-specific (sm_103a) device pass.
#if defined(__CUDA_ARCH__) && defined(__CUDA_ARCH_FEAT_SM103_ALL)
#define HAS_TC 1
#else
#define HAS_TC 0
#endif

// ---------------- device scratch ----------------
__device__ float g_agg[NMAX * 128];   // neighbor aggregation (zeroed per layer)
__device__ float g_y  [NMAX * 256];   // GEMM1 output (pre-BN)
__device__ float g_h2 [NMAX * 128];   // GEMM2 output (pre-BN)
__device__ float g_ssum [256];   // stats of y  (inner BN)
__device__ float g_ssq  [256];
__device__ float g_ssum2[128];   // stats of h2 (outer BN)
__device__ float g_ssq2 [128];
__device__ float g_scale[256];   // outer BN affine (also reused by classifier)
__device__ float g_shift[256];
__device__ float g_ps [GCNT * 128];
__device__ float g_pmx[GCNT * 128];
__device__ float g_cnt[GCNT];
__device__ float g_z1 [GCNT * 128];
__device__ int   g_i64flag;

// pre-split weights, B layout: [layer][n(out)][k(in)] bf16, K-major rows
__device__ __nv_bfloat16 g_b1hi[NLAYER * 256 * 128];
__device__ __nv_bfloat16 g_b1lo[NLAYER * 256 * 128];
__device__ __nv_bfloat16 g_b2hi[NLAYER * 128 * 256];
__device__ __nv_bfloat16 g_b2lo[NLAYER * 128 * 256];

// ---------------- PTX helpers ----------------
__device__ __forceinline__ uint32_t smem_u32(const void* p) {
    uint32_t a;
    asm("{ .reg .u64 t; cvta.to.shared.u64 t, %1; cvt.u32.u64 %0, t; }" : "=r"(a) : "l"(p));
    return a;
}
__device__ __forceinline__ uint32_t elect_one() {
    uint32_t p;
    asm volatile("{ .reg .pred p; elect.sync _|p, 0xFFFFFFFF; selp.b32 %0, 1, 0, p; }" : "=r"(p));
    return p;
}
#define SW128(o) ((o) ^ (((o) >> 3) & 0x70))
static __device__ __forceinline__ uint64_t make_desc(uint32_t addr) {
    // SW128, version=1 (Blackwell), SBO=64, LBO=1
    return ((uint64_t)2 << 61) | ((uint64_t)1 << 46) | ((uint64_t)64 << 32) |
           ((uint64_t)1 << 16) | ((uint64_t)(addr >> 4) & 0x3FFF);
}

#if HAS_TC
__device__ __forceinline__ void mma_bf16_ss(uint32_t d, uint64_t a, uint64_t b,
                                            uint32_t idesc, uint32_t en) {
    asm volatile(
        "{\n\t.reg .pred p;\n\tsetp.ne.u32 p, %4, 0;\n\t"
        "tcgen05.mma.cta_group::1.kind::f16 [%0], %1, %2, %3, {%5, %5, %5, %5}, p;\n\t}"
        :: "r"(d), "l"(a), "l"(b), "r"(idesc), "r"(en), "r"(0u) : "memory");
}
#define TC_ALLOC(sm, n)  asm volatile("tcgen05.alloc.cta_group::1.sync.aligned.shared::cta.b32 [%0], %1;" :: "r"(sm), "r"((uint32_t)(n)) : "memory")
#define TC_DEALLOC(t, n) asm volatile("tcgen05.dealloc.cta_group::1.sync.aligned.b32 %0, %1;" :: "r"(t), "r"((uint32_t)(n)))
#define TC_COMMIT(mb)    asm volatile("tcgen05.commit.cta_group::1.mbarrier::arrive::one.shared::cluster.b64 [%0];" :: "r"(mb) : "memory")
#define TC_FENCE_AFTER() asm volatile("tcgen05.fence::after_thread_sync;" ::: "memory")
#define TC_FENCE_BEFORE() asm volatile("tcgen05.fence::before_thread_sync;" ::: "memory")
#define TC_WAIT_LD()     asm volatile("tcgen05.wait::ld.sync.aligned;" ::: "memory")
#define LDTM32(r, a)                                                            \
    asm volatile("tcgen05.ld.sync.aligned.32x32b.x32.b32 "                      \
        "{%0,%1,%2,%3,%4,%5,%6,%7,%8,%9,%10,%11,%12,%13,%14,%15,"               \
        "%16,%17,%18,%19,%20,%21,%22,%23,%24,%25,%26,%27,%28,%29,%30,%31}, [%32];" \
        : "=r"((r)[0]),"=r"((r)[1]),"=r"((r)[2]),"=r"((r)[3]),                  \
          "=r"((r)[4]),"=r"((r)[5]),"=r"((r)[6]),"=r"((r)[7]),                  \
          "=r"((r)[8]),"=r"((r)[9]),"=r"((r)[10]),"=r"((r)[11]),                \
          "=r"((r)[12]),"=r"((r)[13]),"=r"((r)[14]),"=r"((r)[15]),              \
          "=r"((r)[16]),"=r"((r)[17]),"=r"((r)[18]),"=r"((r)[19]),              \
          "=r"((r)[20]),"=r"((r)[21]),"=r"((r)[22]),"=r"((r)[23]),              \
          "=r"((r)[24]),"=r"((r)[25]),"=r"((r)[26]),"=r"((r)[27]),              \
          "=r"((r)[28]),"=r"((r)[29]),"=r"((r)[30]),"=r"((r)[31])               \
        : "r"(a))
#define MB_WAIT(mb, par) do {                                                   \
    uint32_t _m = (mb), _p = (par), _d;                                         \
    asm volatile("{ .reg .pred p; mbarrier.try_wait.parity.acquire.cta.shared::cta.b64 p, [%1], %2; selp.b32 %0, 1, 0, p; }" \
                 : "=r"(_d) : "r"(_m), "r"(_p) : "memory");                     \
    if (!_d) {                                                                  \
        asm volatile("{ .reg .pred P1; W%=: mbarrier.try_wait.parity.acquire.cta.shared::cta.b64 P1, [%0], %1, 0x989680; @P1 bra.uni D%=; bra.uni W%=; D%=: }" \
                     :: "r"(_m), "r"(_p) : "memory");                           \
    }                                                                           \
} while (0)
#else
// compute_103 (non-'a') pass: stubs. Never executed (sm_103a cubin selected).
__device__ __forceinline__ void mma_bf16_ss(uint32_t, uint64_t, uint64_t, uint32_t, uint32_t) {}
#define TC_ALLOC(sm, n)   ((void)0)
#define TC_DEALLOC(t, n)  ((void)0)
#define TC_COMMIT(mb)     ((void)0)
#define TC_FENCE_AFTER()  ((void)0)
#define TC_FENCE_BEFORE() ((void)0)
#define TC_WAIT_LD()      ((void)0)
#define LDTM32(r, a)      do { _Pragma("unroll") for (int _i = 0; _i < 32; _i++) (r)[_i] = 0u; } while (0)
#define MB_WAIT(mb, par)  ((void)0)
#endif

#define MB_INIT(mb, c)   asm volatile("mbarrier.init.shared.b64 [%0], %1;" :: "r"(mb), "r"((uint32_t)(c)) : "memory")
#define MB_INVAL(mb)     asm volatile("mbarrier.inval.shared.b64 [%0];" :: "r"(mb) : "memory")
#define FENCE_ASYNC()    asm volatile("fence.proxy.async.shared::cta;" ::: "memory")
#define CP_ASYNC16(dst, src) asm volatile("cp.async.ca.shared.global [%0], [%1], 16;" :: "r"(dst), "l"(src) : "memory")
#define CP_COMMIT()      asm volatile("cp.async.commit_group;" ::: "memory")
#define CP_WAIT0()       asm volatile("cp.async.wait_group 0;" ::: "memory")

// ---------------- dtype detection (int32 vs int64 indices) ----------------
__global__ void detect_k(const unsigned int* __restrict__ e) {
    unsigned acc = 0;
    for (int i = 1; i < 128; i += 2) acc |= e[i];
    g_i64flag = (acc == 0u) ? 1 : 0;
}

// ---------------- weight split fp32 -> bf16 hi/lo ----------------
__global__ void wconv_k(const float* __restrict__ W1, const float* __restrict__ W2) {
    int i = blockIdx.x * 256 + threadIdx.x;
    const int tot = NLAYER * 256 * 128;
    if (i >= tot) return;
    int l = i / (256 * 128), rem = i % (256 * 128);
    {   // W1: [l][k(128)][n(256)] -> B1 [l][n][k]
        int n = rem / 128, k = rem % 128;
        float w = W1[l * 32768 + k * 256 + n];
        __nv_bfloat16 h = __float2bfloat16(w);
        g_b1hi[i] = h;
        g_b1lo[i] = __float2bfloat16(w - __bfloat162float(h));
    }
    {   // W2: [l][k(256)][n(128)] -> B2 [l][n][k]
        int n = rem / 256, k = rem % 256;
        float w = W2[l * 32768 + k * 128 + n];
        __nv_bfloat16 h = __float2bfloat16(w);
        g_b2hi[i] = h;
        g_b2lo[i] = __float2bfloat16(w - __bfloat162float(h));
    }
}

// ---------------- zero stats + pool accumulators (once) ----------------
__global__ void zero_k(int tot) {
    int i = blockIdx.x * blockDim.x + threadIdx.x;
    if (i < 256) { g_ssum[i] = 0.f; g_ssq[i] = 0.f; }
    if (i < 128) { g_ssum2[i] = 0.f; g_ssq2[i] = 0.f; }
    if (i < GCNT * 128) { g_ps[i] = 0.f; g_pmx[i] = 0.f; }
    if (i < GCNT) g_cnt[i] = 0.f;
    (void)tot;
}

// ---------------- edge scatter-add: agg[dst] += f(SRC[src]) ----------------
// 8 edges per warp (MLP=8). BN: apply relu(v*scale+shift) to gathered rows.
template<bool BN>
__global__ void __launch_bounds__(256) scatter_k(
    const void* __restrict__ ei, const float* __restrict__ SRC, long long E) {
    long long w = ((long long)blockIdx.x * blockDim.x + threadIdx.x) >> 5;
    int lane = threadIdx.x & 31;
    long long e0 = w * 8;
    if (e0 >= E) return;
    int cnt = (int)((E - e0 < 8) ? (E - e0) : 8);

    int s[8], d[8];
    if (g_i64flag) {
        const long long* p = (const long long*)ei;
#pragma unroll
        for (int j = 0; j < 8; j++)
            if (j < cnt) { s[j] = (int)p[e0 + j]; d[j] = (int)p[E + e0 + j]; }
    } else {
        const int* p = (const int*)ei;
#pragma unroll
        for (int j = 0; j < 8; j++)
            if (j < cnt) { s[j] = p[e0 + j]; d[j] = p[E + e0 + j]; }
    }

    float4 v[8];
#pragma unroll
    for (int j = 0; j < 8; j++)
        if (j < cnt) v[j] = ((const float4*)SRC)[(size_t)s[j] * 32 + lane];

    float sc0, sc1, sc2, sc3, sh0, sh1, sh2, sh3;
    if (BN) {
        int c = lane * 4;
        sc0 = g_scale[c]; sc1 = g_scale[c + 1]; sc2 = g_scale[c + 2]; sc3 = g_scale[c + 3];
        sh0 = g_shift[c]; sh1 = g_shift[c + 1]; sh2 = g_shift[c + 2]; sh3 = g_shift[c + 3];
    }

#pragma unroll
    for (int j = 0; j < 8; j++) {
        if (j < cnt) {
            float r0 = v[j].x, r1 = v[j].y, r2 = v[j].z, r3 = v[j].w;
            if (BN) {
                r0 = fmaxf(fmaf(r0, sc0, sh0), 0.f);
                r1 = fmaxf(fmaf(r1, sc1, sh1), 0.f);
                r2 = fmaxf(fmaf(r2, sc2, sh2), 0.f);
                r3 = fmaxf(fmaf(r3, sc3, sh3), 0.f);
            }
            float* dst = g_agg + (size_t)d[j] * 128 + lane * 4;
            asm volatile("red.global.add.v4.f32 [%0], {%1, %2, %3, %4};"
                         :: "l"(dst), "f"(r0), "f"(r1), "f"(r2), "f"(r3) : "memory");
        }
    }
}

// ============ pipelined tcgen05 bf16x3 GEMM with fused BN-stats ============
// MODE 0 (GEMM1, l=0):  A_eff = (1+eps)*x       + agg ; stats -> g_ssum
// MODE 1 (GEMM1, l>0):  A_eff = (1+eps)*bnrelu(h2) + agg ; BN = outer (g_scale/g_shift)
// MODE 2 (GEMM2):       A_eff = bnrelu_y(y) with scale/shift computed in-kernel
//                        from g_ssum/g_ssq ; stats -> g_ssum2
#define SOFF_PTR  0
#define SOFF_MBAR 16
#define SOFF_SC   32                 // 256 floats
#define SOFF_SH   1056               // 256 floats
#define T_AHI 4096
#define T_ALO 20480
#define T_BHI0 36864
#define T_BLO0 53248
#define T_BHI1 69632
#define T_BLO1 86016
#define TG_SMEM 102400
// idesc kind::f16: dtype=F32(1<<4), atype=BF16(1<<7), btype=BF16(1<<10),
// N=128 (16<<17), M=128 (8<<24)
#define TG_IDESC 0x8200490u

__device__ __forceinline__ uint32_t pack_bf16x2(float a, float b) {
    __nv_bfloat162 h = __float22bfloat162_rn(make_float2(a, b));
    return *reinterpret_cast<uint32_t*>(&h);
}

template<int MODE>
__global__ void __launch_bounds__(256, 2) tgemm_k(
    const float* __restrict__ A, const float* __restrict__ AGG,
    const __nv_bfloat16* __restrict__ Bhi, const __nv_bfloat16* __restrict__ Blo,
    const float* __restrict__ bias, float* __restrict__ C,
    const float* __restrict__ gamma, const float* __restrict__ beta, float invM,
    const float* __restrict__ epsp, int layer,
    int M, int K, int NC)
{
    extern __shared__ char smem[];
    const uint32_t sb = smem_u32(smem);
    const int t = threadIdx.x, wid = t >> 5, lid = t & 31;
    const int bm = blockIdx.x * 128, bn = blockIdx.y * 128;
    float* sSc = reinterpret_cast<float*>(smem + SOFF_SC);
    float* sSh = reinterpret_cast<float*>(smem + SOFF_SH);

    if (wid == 0) TC_ALLOC(sb + SOFF_PTR, 128);
    if (t == 0) MB_INIT(sb + SOFF_MBAR, 1);
    if (MODE == 2) {          // t indexes all K=256 channels
        float m   = g_ssum[t] * invM;
        float var = g_ssq[t] * invM - m * m;
        float sc  = gamma[t] * rsqrtf(var + 1e-5f);
        sSc[t] = sc;
        sSh[t] = beta[t] - m * sc;
    } else if (MODE == 1) {
        if (t < 128) { sSc[t] = g_scale[t]; sSh[t] = g_shift[t]; }
    }
    const float eW = (MODE < 2) ? (1.0f + epsp[layer]) : 0.f;
    __syncthreads();
    uint32_t tmem;
    asm volatile("ld.shared.b32 %0, [%1];" : "=r"(tmem) : "r"(sb + SOFF_PTR));

    const uint64_t dAhi = make_desc(sb + T_AHI);
    const uint64_t dAlo = make_desc(sb + T_ALO);
    const uint64_t dBhi[2] = { make_desc(sb + T_BHI0), make_desc(sb + T_BHI1) };
    const uint64_t dBlo[2] = { make_desc(sb + T_BLO0), make_desc(sb + T_BLO1) };
    const int nch = K >> 6;

    float4 apf[8];   // A prefetch: 4 its x 8 floats
    float4 agf[8];   // agg prefetch (MODE < 2)

#define PREF_A(CH)                                                              \
    {                                                                           \
        int kbase_ = (CH) * 64;                                                 \
        _Pragma("unroll")                                                       \
        for (int it = 0; it < 4; it++) {                                        \
            int idx = t + it * 256;                                             \
            int r_ = idx >> 3, kg_ = idx & 7;                                   \
            int grow_ = bm + r_;                                                \
            if (grow_ < M) {                                                    \
                const float* ap = A + (size_t)grow_ * K + kbase_ + kg_ * 8;     \
                apf[it * 2]     = *(const float4*)ap;                           \
                apf[it * 2 + 1] = *(const float4*)(ap + 4);                     \
                if (MODE < 2) {                                                 \
                    const float* gp = AGG + (size_t)grow_ * K + kbase_ + kg_ * 8; \
                    agf[it * 2]     = *(const float4*)gp;                       \
                    agf[it * 2 + 1] = *(const float4*)(gp + 4);                 \
                }                                                               \
            } else {                                                            \
                apf[it * 2] = apf[it * 2 + 1] = make_float4(0.f, 0.f, 0.f, 0.f); \
                if (MODE < 2) agf[it * 2] = agf[it * 2 + 1] = make_float4(0.f, 0.f, 0.f, 0.f); \
            }                                                                   \
        }                                                                       \
    }

#define CPASYNC_B(CH, BUF)                                                      \
    {                                                                           \
        int kbase_ = (CH) * 64;                                                 \
        uint32_t bhi_ = sb + ((BUF) ? T_BHI1 : T_BHI0);                         \
        uint32_t blo_ = sb + ((BUF) ? T_BLO1 : T_BLO0);                         \
        _Pragma("unroll")                                                       \
        for (int it = 0; it < 4; it++) {                                        \
            int idx = t + it * 256;                                             \
            int r_ = idx >> 3, kg_ = idx & 7;                                   \
            uint32_t so_ = SW128((uint32_t)(r_ * 128 + kg_ * 16));              \
            size_t bo_ = (size_t)(bn + r_) * K + kbase_ + kg_ * 8;              \
            CP_ASYNC16(bhi_ + so_, Bhi + bo_);                                  \
            CP_ASYNC16(blo_ + so_, Blo + bo_);                                  \
        }                                                                       \
        CP_COMMIT();                                                            \
    }

#define STORE_A(CH)                                                             \
    {                                                                           \
        int kbase_ = (CH) * 64;                                                 \
        _Pragma("unroll")                                                       \
        for (int it = 0; it < 4; it++) {                                        \
            int idx = t + it * 256;                                             \
            int r_ = idx >> 3, kg_ = idx & 7;                                   \
            uint32_t so_ = SW128((uint32_t)(r_ * 128 + kg_ * 16));              \
            int cb_ = kbase_ + kg_ * 8;                                         \
            float f[8], gg[8];                                                  \
            *(float4*)(f)     = apf[it * 2];                                    \
            *(float4*)(f + 4) = apf[it * 2 + 1];                                \
            if (MODE < 2) {                                                     \
                *(float4*)(gg)     = agf[it * 2];                               \
                *(float4*)(gg + 4) = agf[it * 2 + 1];                           \
            }                                                                   \
            _Pragma("unroll")                                                   \
            for (int j = 0; j < 8; j++) {                                       \
                if (MODE == 0)      f[j] = fmaf(f[j], eW, gg[j]);               \
                else if (MODE == 1) f[j] = fmaf(fmaxf(fmaf(f[j], sSc[cb_ + j], sSh[cb_ + j]), 0.f), eW, gg[j]); \
                else                f[j] = fmaxf(fmaf(f[j], sSc[cb_ + j], sSh[cb_ + j]), 0.f); \
            }                                                                   \
            uint32_t h[4], lo[4];                                               \
            _Pragma("unroll")                                                   \
            for (int j = 0; j < 4; j++) {                                       \
                h[j] = pack_bf16x2(f[2 * j], f[2 * j + 1]);                     \
                __nv_bfloat162 hb = *reinterpret_cast<__nv_bfloat162*>(&h[j]);  \
                float2 hr = __bfloat1622float2(hb);                             \
                lo[j] = pack_bf16x2(f[2 * j] - hr.x, f[2 * j + 1] - hr.y);      \
            }                                                                   \
            *(uint4*)(smem + T_AHI + so_) = make_uint4(h[0], h[1], h[2], h[3]); \
            *(uint4*)(smem + T_ALO + so_) = make_uint4(lo[0], lo[1], lo[2], lo[3]); \
        }                                                                       \
    }

    // ---- prologue: chunk 0 ----
    PREF_A(0);
    CPASYNC_B(0, 0);
    STORE_A(0);
    CP_WAIT0();
    FENCE_ASYNC();
    __syncthreads();
    if (wid == 0 && elect_one()) {
#pragma unroll
        for (int s = 0; s < 4; s++)
            mma_bf16_ss(tmem, dAhi + s * 2, dBhi[0] + s * 2, TG_IDESC, s == 0 ? 0u : 1u);
#pragma unroll
        for (int s = 0; s < 4; s++)
            mma_bf16_ss(tmem, dAhi + s * 2, dBlo[0] + s * 2, TG_IDESC, 1u);
#pragma unroll
        for (int s = 0; s < 4; s++)
            mma_bf16_ss(tmem, dAlo + s * 2, dBhi[0] + s * 2, TG_IDESC, 1u);
        TC_COMMIT(sb + SOFF_MBAR);
    }

    // ---- pipelined chunks ----
    for (int ch = 1; ch < nch; ch++) {
        int buf = ch & 1;
        PREF_A(ch);
        CPASYNC_B(ch, buf);
        MB_WAIT(sb + SOFF_MBAR, (ch - 1) & 1);   // MMA(ch-1) done: A smem free
        STORE_A(ch);
        CP_WAIT0();
        FENCE_ASYNC();
        __syncthreads();
        if (wid == 0 && elect_one()) {
#pragma unroll
            for (int s = 0; s < 4; s++)
                mma_bf16_ss(tmem, dAhi + s * 2, dBhi[buf] + s * 2, TG_IDESC, 1u);
#pragma unroll
            for (int s = 0; s < 4; s++)
                mma_bf16_ss(tmem, dAhi + s * 2, dBlo[buf] + s * 2, TG_IDESC, 1u);
#pragma unroll
            for (int s = 0; s < 4; s++)
                mma_bf16_ss(tmem, dAlo + s * 2, dBhi[buf] + s * 2, TG_IDESC, 1u);
            TC_COMMIT(sb + SOFF_MBAR);
        }
    }
    MB_WAIT(sb + SOFF_MBAR, (nch - 1) & 1);
    TC_FENCE_AFTER();

#undef PREF_A
#undef CPASYNC_B
#undef STORE_A

    // ---- epilogue: bias, store C, stash rows in smem for stats ----
    float* buf = reinterpret_cast<float*>(smem + T_AHI);   // [128][129]
    if (wid < 4) {
        int r = wid * 32 + lid;
        int grow = bm + r;
#pragma unroll
        for (int b = 0; b < 4; b++) {
            uint32_t rg[32];
            LDTM32(rg, tmem + b * 32);
            TC_WAIT_LD();
            float v[32];
#pragma unroll
            for (int i = 0; i < 32; i++)
                v[i] = __uint_as_float(rg[i]) + bias[bn + b * 32 + i];
            if (grow < M) {
#pragma unroll
                for (int q = 0; q < 8; q++)
                    *(float4*)(C + (size_t)grow * NC + bn + b * 32 + q * 4) = *(float4*)(v + q * 4);
            }
#pragma unroll
            for (int i = 0; i < 32; i++)
                buf[r * 129 + b * 32 + i] = v[i];
        }
        TC_FENCE_BEFORE();
    }
    __syncthreads();

    // ---- column stats ----
    {
        float* ssum_t = (MODE == 2) ? g_ssum2 : g_ssum;
        float* ssq_t  = (MODE == 2) ? g_ssq2  : g_ssq;
        int c = t & 127, h = t >> 7;
        float s = 0.f, q = 0.f;
#pragma unroll 8
        for (int rr = 0; rr < 64; rr++) {
            int r = h * 64 + rr;
            if (bm + r < M) {
                float v = buf[r * 129 + c];
                s += v;
                q = fmaf(v, v, q);
            }
        }
        atomicAdd(&ssum_t[bn + c], s);
        atomicAdd(&ssq_t[bn + c], q);
    }
    __syncthreads();
    if (t == 0) MB_INVAL(sb + SOFF_MBAR);
    if (wid == 0) TC_DEALLOC(tmem, 128);
}

// outer BN finalize: scale/shift for h2; zero both stats sets for next layer
__global__ void finalize_k(const float* __restrict__ gamma, const float* __restrict__ beta,
                           float invM) {
    int t = threadIdx.x;  // 256
    if (t < 128) {
        float m   = g_ssum2[t] * invM;
        float var = g_ssq2[t] * invM - m * m;
        float sc  = gamma[t] * rsqrtf(var + 1e-5f);
        g_scale[t] = sc;
        g_shift[t] = beta[t] - m * sc;
        g_ssum2[t] = 0.f;
        g_ssq2[t]  = 0.f;
    }
    g_ssum[t] = 0.f;
    g_ssq[t]  = 0.f;
}

// ---------------- readout pooling ----------------
__global__ void pool_k(const void* __restrict__ batch, int n) {
    long long t = (long long)blockIdx.x * blockDim.x + threadIdx.x;
    long long i = t >> 5;
    if (i >= n) return;
    int lane = (int)(t & 31);
    long long g;
    if (g_i64flag) g = ((const long long*)batch)[i];
    else           g = (long long)((const int*)batch)[i];
    int c = lane * 4;
    float4 v = ((const float4*)g_h2)[i * 32 + lane];
    float r0 = fmaxf(fmaf(v.x, g_scale[c + 0], g_shift[c + 0]), 0.f);
    float r1 = fmaxf(fmaf(v.y, g_scale[c + 1], g_shift[c + 1]), 0.f);
    float r2 = fmaxf(fmaf(v.z, g_scale[c + 2], g_shift[c + 2]), 0.f);
    float r3 = fmaxf(fmaf(v.w, g_scale[c + 3], g_shift[c + 3]), 0.f);
    float* ps = g_ps + g * 128 + c;
    asm volatile("red.global.add.v4.f32 [%0], {%1, %2, %3, %4};"
                 :: "l"(ps), "f"(r0), "f"(r1), "f"(r2), "f"(r3) : "memory");
    unsigned int* mx = (unsigned int*)(g_pmx + g * 128 + c);
    atomicMax(mx + 0, __float_as_uint(r0));
    atomicMax(mx + 1, __float_as_uint(r1));
    atomicMax(mx + 2, __float_as_uint(r2));
    atomicMax(mx + 3, __float_as_uint(r3));
    if (lane == 0) atomicAdd(&g_cnt[g], 1.0f);
}

// ---------------- classifier ----------------
__global__ void cgemm1_k(const float* __restrict__ cW1, const float* __restrict__ cb1) {
    int g = blockIdx.x;
    int j = threadIdx.x;  // 128
    __shared__ float z[384];
    float cnt = fmaxf(g_cnt[g], 1.0f);
    float sv = g_ps[g * 128 + j];
    z[j]       = sv;
    z[128 + j] = sv / cnt;
    z[256 + j] = g_pmx[g * 128 + j];
    __syncthreads();
    float acc = cb1[j];
#pragma unroll 8
    for (int k = 0; k < 384; k++)
        acc = fmaf(z[k], cW1[k * 128 + j], acc);
    g_z1[g * 128 + j] = acc;
}

__global__ void cstats_k(const float* __restrict__ cg, const float* __restrict__ cbeta) {
    int j = threadIdx.x;  // 128
    float s = 0.f, q = 0.f;
    for (int g = 0; g < GCNT; g++) {
        float v = g_z1[g * 128 + j];
        s += v; q += v * v;
    }
    float m   = s * (1.0f / GCNT);
    float var = q * (1.0f / GCNT) - m * m;
    float sc  = cg[j] * rsqrtf(var + 1e-5f);
    g_scale[j] = sc;
    g_shift[j] = cbeta[j] - m * sc;
}

__global__ void chead_k(const float* __restrict__ cW2, const float* __restrict__ cb2,
                        const float* __restrict__ cW3, const float* __restrict__ cb3,
                        float* __restrict__ out) {
    int g = blockIdx.x;
    int j = threadIdx.x;  // 64
    __shared__ float a[128];
    __shared__ float z2[64];
    for (int k = j; k < 128; k += 64)
        a[k] = fmaxf(fmaf(g_z1[g * 128 + k], g_scale[k], g_shift[k]), 0.f);
    __syncthreads();
    float acc = cb2[j];
#pragma unroll 8
    for (int k = 0; k < 128; k++)
        acc = fmaf(a[k], cW2[k * 64 + j], acc);
    z2[j] = fmaxf(acc, 0.f);
    __syncthreads();
    if (j < 2) {
        float o = cb3[j];
#pragma unroll 8
        for (int k = 0; k < 64; k++)
            o = fmaf(z2[k], cW3[k * 2 + j], o);
        out[g * 2 + j] = o;
    }
}

// ---------------- launcher ----------------
extern "C" void kernel_launch(void* const* d_in, const int* in_sizes, int n_in,
                              void* d_out, int out_size) {
    const float* x     = (const float*)d_in[0];
    const void*  ei    = d_in[1];
    const void*  batch = d_in[2];
    int base = (in_sizes[3] == 1) ? 4 : 3;
    const float* W1    = (const float*)d_in[base + 0];
    const float* b1    = (const float*)d_in[base + 1];
    const float* g1    = (const float*)d_in[base + 2];
    const float* be1   = (const float*)d_in[base + 3];
    const float* W2    = (const float*)d_in[base + 4];
    const float* b2    = (const float*)d_in[base + 5];
    const float* gbn   = (const float*)d_in[base + 6];
    const float* bbn   = (const float*)d_in[base + 7];
    const float* eps   = (const float*)d_in[base + 8];
    const float* cW1   = (const float*)d_in[base + 9];
    const float* cb1   = (const float*)d_in[base + 10];
    const float* cg    = (const float*)d_in[base + 11];
    const float* cbeta = (const float*)d_in[base + 12];
    const float* cW2   = (const float*)d_in[base + 13];
    const float* cb2   = (const float*)d_in[base + 14];
    const float* cW3   = (const float*)d_in[base + 15];
    const float* cb3   = (const float*)d_in[base + 16];

    int n = in_sizes[0] / 128;
    long long E = (long long)in_sizes[1] / 2;
    int n32 = n * 32;
    int nb = (n32 + 255) / 256;
    int gx = (n + 127) / 128;
    long long nwarp = (E + 7) / 8;
    int sblk = (int)((nwarp * 32 + 255) / 256);
    float invM = 1.0f / (float)n;

    static int smem_set = 0;
    if (!smem_set) {
        cudaFuncSetAttribute(tgemm_k<0>, cudaFuncAttributeMaxDynamicSharedMemorySize, TG_SMEM);
        cudaFuncSetAttribute(tgemm_k<1>, cudaFuncAttributeMaxDynamicSharedMemorySize, TG_SMEM);
        cudaFuncSetAttribute(tgemm_k<2>, cudaFuncAttributeMaxDynamicSharedMemorySize, TG_SMEM);
        smem_set = 1;
    }

    float *p_agg, *p_y, *p_h2;
    __nv_bfloat16 *p_b1hi, *p_b1lo, *p_b2hi, *p_b2lo;
    cudaGetSymbolAddress((void**)&p_agg, g_agg);
    cudaGetSymbolAddress((void**)&p_y,   g_y);
    cudaGetSymbolAddress((void**)&p_h2,  g_h2);
    cudaGetSymbolAddress((void**)&p_b1hi, g_b1hi);
    cudaGetSymbolAddress((void**)&p_b1lo, g_b1lo);
    cudaGetSymbolAddress((void**)&p_b2hi, g_b2hi);
    cudaGetSymbolAddress((void**)&p_b2lo, g_b2lo);

    detect_k<<<1, 1>>>((const unsigned int*)ei);
    wconv_k<<<(NLAYER * 256 * 128 + 255) / 256, 256>>>(W1, W2);
    zero_k<<<256, 256>>>(0);

    for (int l = 0; l < 4; l++) {
        cudaMemsetAsync(p_agg, 0, (size_t)n * 128 * sizeof(float), 0);
        if (l == 0) scatter_k<false><<<sblk, 256>>>(ei, x, E);
        else        scatter_k<true><<<sblk, 256>>>(ei, p_h2, E);

        if (l == 0)
            tgemm_k<0><<<dim3(gx, 2), 256, TG_SMEM>>>(
                x, p_agg, p_b1hi + (size_t)l * 32768, p_b1lo + (size_t)l * 32768,
                b1 + l * 256, p_y, nullptr, nullptr, invM, eps, l, n, 128, 256);
        else
            tgemm_k<1><<<dim3(gx, 2), 256, TG_SMEM>>>(
                p_h2, p_agg, p_b1hi + (size_t)l * 32768, p_b1lo + (size_t)l * 32768,
                b1 + l * 256, p_y, nullptr, nullptr, invM, eps, l, n, 128, 256);

        tgemm_k<2><<<dim3(gx, 1), 256, TG_SMEM>>>(
            p_y, nullptr, p_b2hi + (size_t)l * 32768, p_b2lo + (size_t)l * 32768,
            b2 + l * 128, p_h2, g1 + l * 256, be1 + l * 256, invM, eps, l, n, 256, 128);

        finalize_k<<<1, 256>>>(gbn + l * 128, bbn + l * 128, invM);
    }

    pool_k<<<nb, 256>>>(batch, n);
    cgemm1_k<<<GCNT, 128>>>(cW1, cb1);
    cstats_k<<<1, 128>>>(cg, cbeta);
    chead_k<<<GCNT, 64>>>(cW2, cb2, cW3, cb3, (float*)d_out);
}

// round 7
// speedup vs baseline: 1.0676x; 1.0676x over previous
#include <cuda_runtime.h>
#include <cuda_bf16.h>
#include <cstdint>
#include <cstddef>

// Problem constants (fixed shapes)
#define NMAX 100000
#define GCNT 512
#define NLAYER 4

// tcgen05 only exists in the arch-specific (sm_103a) device pass.
#if defined(__CUDA_ARCH__) && defined(__CUDA_ARCH_FEAT_SM103_ALL)
#define HAS_TC 1
#else
#define HAS_TC 0
#endif

// ---------------- device scratch ----------------
__device__ float g_hin[NMAX * 128];
__device__ float g_y  [NMAX * 256];
__device__ float g_h2 [NMAX * 128];
__device__ float g_ssum [256];   // stats of y  (inner BN)
__device__ float g_ssq  [256];
__device__ float g_ssum2[128];   // stats of h2 (outer BN)
__device__ float g_ssq2 [128];
__device__ float g_scale[256];   // outer BN affine (also reused by classifier)
__device__ float g_shift[256];
__device__ float g_ps [GCNT * 128];
__device__ float g_pmx[GCNT * 128];
__device__ float g_cnt[GCNT];
__device__ float g_z1 [GCNT * 128];
__device__ int   g_i64flag;

// pre-split weights, B layout: [layer][n(out)][k(in)] bf16, K-major rows
__device__ __nv_bfloat16 g_b1hi[NLAYER * 256 * 128];
__device__ __nv_bfloat16 g_b1lo[NLAYER * 256 * 128];
__device__ __nv_bfloat16 g_b2hi[NLAYER * 128 * 256];
__device__ __nv_bfloat16 g_b2lo[NLAYER * 128 * 256];

// ---------------- PTX helpers ----------------
__device__ __forceinline__ uint32_t smem_u32(const void* p) {
    uint32_t a;
    asm("{ .reg .u64 t; cvta.to.shared.u64 t, %1; cvt.u32.u64 %0, t; }" : "=r"(a) : "l"(p));
    return a;
}
__device__ __forceinline__ uint32_t elect_one() {
    uint32_t p;
    asm volatile("{ .reg .pred p; elect.sync _|p, 0xFFFFFFFF; selp.b32 %0, 1, 0, p; }" : "=r"(p));
    return p;
}
#define SW128(o) ((o) ^ (((o) >> 3) & 0x70))
static __device__ __forceinline__ uint64_t make_desc(uint32_t addr) {
    // SW128, version=1 (Blackwell), SBO=64, LBO=1
    return ((uint64_t)2 << 61) | ((uint64_t)1 << 46) | ((uint64_t)64 << 32) |
           ((uint64_t)1 << 16) | ((uint64_t)(addr >> 4) & 0x3FFF);
}

#if HAS_TC
__device__ __forceinline__ void mma_bf16_ss(uint32_t d, uint64_t a, uint64_t b,
                                            uint32_t idesc, uint32_t en) {
    asm volatile(
        "{\n\t.reg .pred p;\n\tsetp.ne.u32 p, %4, 0;\n\t"
        "tcgen05.mma.cta_group::1.kind::f16 [%0], %1, %2, %3, {%5, %5, %5, %5}, p;\n\t}"
        :: "r"(d), "l"(a), "l"(b), "r"(idesc), "r"(en), "r"(0u) : "memory");
}
#define TC_ALLOC(sm, n)  asm volatile("tcgen05.alloc.cta_group::1.sync.aligned.shared::cta.b32 [%0], %1;" :: "r"(sm), "r"((uint32_t)(n)) : "memory")
#define TC_DEALLOC(t, n) asm volatile("tcgen05.dealloc.cta_group::1.sync.aligned.b32 %0, %1;" :: "r"(t), "r"((uint32_t)(n)))
#define TC_COMMIT(mb)    asm volatile("tcgen05.commit.cta_group::1.mbarrier::arrive::one.shared::cluster.b64 [%0];" :: "r"(mb) : "memory")
#define TC_FENCE_AFTER() asm volatile("tcgen05.fence::after_thread_sync;" ::: "memory")
#define TC_FENCE_BEFORE() asm volatile("tcgen05.fence::before_thread_sync;" ::: "memory")
#define TC_WAIT_LD()     asm volatile("tcgen05.wait::ld.sync.aligned;" ::: "memory")
#define LDTM32(r, a)                                                            \
    asm volatile("tcgen05.ld.sync.aligned.32x32b.x32.b32 "                      \
        "{%0,%1,%2,%3,%4,%5,%6,%7,%8,%9,%10,%11,%12,%13,%14,%15,"               \
        "%16,%17,%18,%19,%20,%21,%22,%23,%24,%25,%26,%27,%28,%29,%30,%31}, [%32];" \
        : "=r"((r)[0]),"=r"((r)[1]),"=r"((r)[2]),"=r"((r)[3]),                  \
          "=r"((r)[4]),"=r"((r)[5]),"=r"((r)[6]),"=r"((r)[7]),                  \
          "=r"((r)[8]),"=r"((r)[9]),"=r"((r)[10]),"=r"((r)[11]),                \
          "=r"((r)[12]),"=r"((r)[13]),"=r"((r)[14]),"=r"((r)[15]),              \
          "=r"((r)[16]),"=r"((r)[17]),"=r"((r)[18]),"=r"((r)[19]),              \
          "=r"((r)[20]),"=r"((r)[21]),"=r"((r)[22]),"=r"((r)[23]),              \
          "=r"((r)[24]),"=r"((r)[25]),"=r"((r)[26]),"=r"((r)[27]),              \
          "=r"((r)[28]),"=r"((r)[29]),"=r"((r)[30]),"=r"((r)[31])               \
        : "r"(a))
#define MB_WAIT(mb, par) do {                                                   \
    uint32_t _m = (mb), _p = (par), _d;                                         \
    asm volatile("{ .reg .pred p; mbarrier.try_wait.parity.acquire.cta.shared::cta.b64 p, [%1], %2; selp.b32 %0, 1, 0, p; }" \
                 : "=r"(_d) : "r"(_m), "r"(_p) : "memory");                     \
    if (!_d) {                                                                  \
        asm volatile("{ .reg .pred P1; W%=: mbarrier.try_wait.parity.acquire.cta.shared::cta.b64 P1, [%0], %1, 0x989680; @P1 bra.uni D%=; bra.uni W%=; D%=: }" \
                     :: "r"(_m), "r"(_p) : "memory");                           \
    }                                                                           \
} while (0)
#else
// compute_103 (non-'a') pass: stubs. Never executed (sm_103a cubin selected).
__device__ __forceinline__ void mma_bf16_ss(uint32_t, uint64_t, uint64_t, uint32_t, uint32_t) {}
#define TC_ALLOC(sm, n)   ((void)0)
#define TC_DEALLOC(t, n)  ((void)0)
#define TC_COMMIT(mb)     ((void)0)
#define TC_FENCE_AFTER()  ((void)0)
#define TC_FENCE_BEFORE() ((void)0)
#define TC_WAIT_LD()      ((void)0)
#define LDTM32(r, a)      do { _Pragma("unroll") for (int _i = 0; _i < 32; _i++) (r)[_i] = 0u; } while (0)
#define MB_WAIT(mb, par)  ((void)0)
#endif

#define MB_INIT(mb, c)   asm volatile("mbarrier.init.shared.b64 [%0], %1;" :: "r"(mb), "r"((uint32_t)(c)) : "memory")
#define MB_INVAL(mb)     asm volatile("mbarrier.inval.shared.b64 [%0];" :: "r"(mb) : "memory")
#define FENCE_ASYNC()    asm volatile("fence.proxy.async.shared::cta;" ::: "memory")
#define CP_ASYNC16(dst, src) asm volatile("cp.async.ca.shared.global [%0], [%1], 16;" :: "r"(dst), "l"(src) : "memory")
#define CP_COMMIT()      asm volatile("cp.async.commit_group;" ::: "memory")
#define CP_WAIT0()       asm volatile("cp.async.wait_group 0;" ::: "memory")

// ---------------- dtype detection (int32 vs int64 indices) ----------------
__global__ void detect_k(const unsigned int* __restrict__ e) {
    unsigned acc = 0;
    for (int i = 1; i < 128; i += 2) acc |= e[i];
    g_i64flag = (acc == 0u) ? 1 : 0;
}

// ---------------- weight split fp32 -> bf16 hi/lo ----------------
__global__ void wconv_k(const float* __restrict__ W1, const float* __restrict__ W2) {
    int i = blockIdx.x * 256 + threadIdx.x;
    const int tot = NLAYER * 256 * 128;
    if (i >= tot) return;
    int l = i / (256 * 128), rem = i % (256 * 128);
    {   // W1: [l][k(128)][n(256)] -> B1 [l][n][k]
        int n = rem / 128, k = rem % 128;
        float w = W1[l * 32768 + k * 256 + n];
        __nv_bfloat16 h = __float2bfloat16(w);
        g_b1hi[i] = h;
        g_b1lo[i] = __float2bfloat16(w - __bfloat162float(h));
    }
    {   // W2: [l][k(256)][n(128)] -> B2 [l][n][k]
        int n = rem / 256, k = rem % 256;
        float w = W2[l * 32768 + k * 128 + n];
        __nv_bfloat16 h = __float2bfloat16(w);
        g_b2hi[i] = h;
        g_b2lo[i] = __float2bfloat16(w - __bfloat162float(h));
    }
}

// ---------------- prep kernels ----------------
// prep0: hin = (1+eps0)*x ; zero all stats + pool accumulators
__global__ void prep0_k(const float4* __restrict__ x, const float* __restrict__ epsp, int n32) {
    int i = blockIdx.x * blockDim.x + threadIdx.x;
    if (i < n32) {
        float e = 1.0f + epsp[0];
        float4 v = x[i];
        ((float4*)g_hin)[i] = make_float4(v.x * e, v.y * e, v.z * e, v.w * e);
    }
    if (i < 256) { g_ssum[i] = 0.f; g_ssq[i] = 0.f; }
    if (i < 128) { g_ssum2[i] = 0.f; g_ssq2[i] = 0.f; }
    if (i < GCNT * 128) { g_ps[i] = 0.f; g_pmx[i] = 0.f; }
    if (i < GCNT) g_cnt[i] = 0.f;
}

// l>0: hin = (1+eps_l)*relu(bn(h2))
__global__ void prep_k(const float* __restrict__ epsp, int l, int n32) {
    int i = blockIdx.x * blockDim.x + threadIdx.x;
    if (i < n32) {
        float e = 1.0f + epsp[l];
        int c = (i & 31) * 4;
        float4 v = ((const float4*)g_h2)[i];
        float4 r;
        r.x = fmaxf(fmaf(v.x, g_scale[c + 0], g_shift[c + 0]), 0.f) * e;
        r.y = fmaxf(fmaf(v.y, g_scale[c + 1], g_shift[c + 1]), 0.f) * e;
        r.z = fmaxf(fmaf(v.z, g_scale[c + 2], g_shift[c + 2]), 0.f) * e;
        r.w = fmaxf(fmaf(v.w, g_scale[c + 3], g_shift[c + 3]), 0.f) * e;
        ((float4*)g_hin)[i] = r;
    }
}

// ---------------- edge scatter-add: hin[dst] += f(SRC[src]) ----------------
// 4 edges per warp (MLP=4). BN: apply relu(v*scale+shift) to gathered rows.
template<bool BN>
__global__ void scatter_k(const void* __restrict__ ei, const float* __restrict__ SRC,
                          long long E) {
    long long w = ((long long)blockIdx.x * blockDim.x + threadIdx.x) >> 5;
    int lane = threadIdx.x & 31;
    long long e0 = w * 4;
    if (e0 >= E) return;
    int cnt = (int)((E - e0 < 4) ? (E - e0) : 4);

    long long s[4], d[4];
    if (g_i64flag) {
        const long long* p = (const long long*)ei;
#pragma unroll
        for (int j = 0; j < 4; j++)
            if (j < cnt) { s[j] = p[e0 + j]; d[j] = p[E + e0 + j]; }
    } else {
        const int* p = (const int*)ei;
#pragma unroll
        for (int j = 0; j < 4; j++)
            if (j < cnt) { s[j] = (long long)p[e0 + j]; d[j] = (long long)p[E + e0 + j]; }
    }

    float4 v[4];
#pragma unroll
    for (int j = 0; j < 4; j++)
        if (j < cnt) v[j] = ((const float4*)SRC)[s[j] * 32 + lane];

    float sc0, sc1, sc2, sc3, sh0, sh1, sh2, sh3;
    if (BN) {
        int c = lane * 4;
        sc0 = g_scale[c]; sc1 = g_scale[c + 1]; sc2 = g_scale[c + 2]; sc3 = g_scale[c + 3];
        sh0 = g_shift[c]; sh1 = g_shift[c + 1]; sh2 = g_shift[c + 2]; sh3 = g_shift[c + 3];
    }

#pragma unroll
    for (int j = 0; j < 4; j++) {
        if (j < cnt) {
            float r0 = v[j].x, r1 = v[j].y, r2 = v[j].z, r3 = v[j].w;
            if (BN) {
                r0 = fmaxf(fmaf(r0, sc0, sh0), 0.f);
                r1 = fmaxf(fmaf(r1, sc1, sh1), 0.f);
                r2 = fmaxf(fmaf(r2, sc2, sh2), 0.f);
                r3 = fmaxf(fmaf(r3, sc3, sh3), 0.f);
            }
            float* dst = g_hin + d[j] * 128 + lane * 4;
            asm volatile("red.global.add.v4.f32 [%0], {%1, %2, %3, %4};"
                         :: "l"(dst), "f"(r0), "f"(r1), "f"(r2), "f"(r3) : "memory");
        }
    }
}

// ---------------- common tgemm constants ----------------
#define SOFF_PTR  0
#define SOFF_MBAR 16
#define SOFF_SC   32                 // 256 floats
#define SOFF_SH   1056               // 256 floats
// idesc kind::f16: dtype=F32, atype=BF16, btype=BF16, N=128, M=128
#define TG_IDESC 0x8200490u

__device__ __forceinline__ uint32_t pack_bf16x2(float a, float b) {
    __nv_bfloat162 h = __float22bfloat162_rn(make_float2(a, b));
    return *reinterpret_cast<uint32_t*>(&h);
}

// ============ GEMM1: y[M,256] = hin[M,128] @ W1 + b1 ; single CTA per M-tile ============
// All 256 output cols in one CTA: A staged/split ONCE. TMEM D: cols 0..255.
#define T1_PSUM 2080
#define T1_PSQ  3104
#define T1_SSL  4128
#define T1_SQL  5152
#define T1_AHI  8192                 // 16 KB
#define T1_ALO  24576                // 16 KB
#define T1_BHI  40960                // 32 KB (256 rows x 128B)
#define T1_BLO  73728                // 32 KB
#define TG1_SMEM 106496

__global__ void __launch_bounds__(256, 2) tgemm1_k(
    const float* __restrict__ A,
    const __nv_bfloat16* __restrict__ Bhi, const __nv_bfloat16* __restrict__ Blo,
    const float* __restrict__ bias, float* __restrict__ C, int M)
{
    extern __shared__ char smem[];
    const uint32_t sb = smem_u32(smem);
    const int t = threadIdx.x, wid = t >> 5, lid = t & 31;
    const int bm = blockIdx.x * 128;
    const int K = 128, NC = 256;

    if (wid == 0) TC_ALLOC(sb + SOFF_PTR, 256);
    if (t == 0) MB_INIT(sb + SOFF_MBAR, 1);
    {   // bias into smem
        float* sB = reinterpret_cast<float*>(smem + SOFF_SC);
        sB[t] = bias[t];
    }
    __syncthreads();
    uint32_t tmem;
    asm volatile("ld.shared.b32 %0, [%1];" : "=r"(tmem) : "r"(sb + SOFF_PTR));

    const uint64_t dAhi = make_desc(sb + T1_AHI);
    const uint64_t dAlo = make_desc(sb + T1_ALO);
    const uint64_t dBhi = make_desc(sb + T1_BHI);
    const uint64_t dBlo = make_desc(sb + T1_BLO);

    float4 apf[8];

#define PREF_A1(CH)                                                             \
    {                                                                           \
        int kbase_ = (CH) * 64;                                                 \
        _Pragma("unroll")                                                       \
        for (int it = 0; it < 4; it++) {                                        \
            int idx = t + it * 256;                                             \
            int r_ = idx >> 3, kg_ = idx & 7;                                   \
            int grow_ = bm + r_;                                                \
            if (grow_ < M) {                                                    \
                const float* ap = A + (size_t)grow_ * K + kbase_ + kg_ * 8;     \
                apf[it * 2]     = *(const float4*)ap;                           \
                apf[it * 2 + 1] = *(const float4*)(ap + 4);                     \
            } else {                                                            \
                apf[it * 2] = apf[it * 2 + 1] = make_float4(0.f, 0.f, 0.f, 0.f); \
            }                                                                   \
        }                                                                       \
    }

#define CPASYNC_B1(CH)                                                          \
    {                                                                           \
        int kbase_ = (CH) * 64;                                                 \
        _Pragma("unroll")                                                       \
        for (int it = 0; it < 8; it++) {                                        \
            int idx = t + it * 256;                                             \
            int r_ = idx >> 3, kg_ = idx & 7;                                   \
            uint32_t so_ = SW128((uint32_t)(r_ * 128 + kg_ * 16));              \
            size_t bo_ = (size_t)r_ * K + kbase_ + kg_ * 8;                     \
            CP_ASYNC16(sb + T1_BHI + so_, Bhi + bo_);                           \
            CP_ASYNC16(sb + T1_BLO + so_, Blo + bo_);                           \
        }                                                                       \
        CP_COMMIT();                                                            \
    }

#define STORE_A1()                                                              \
    {                                                                           \
        _Pragma("unroll")                                                       \
        for (int it = 0; it < 4; it++) {                                        \
            int idx = t + it * 256;                                             \
            int r_ = idx >> 3, kg_ = idx & 7;                                   \
            uint32_t so_ = SW128((uint32_t)(r_ * 128 + kg_ * 16));              \
            float f[8];                                                         \
            *(float4*)(f)     = apf[it * 2];                                    \
            *(float4*)(f + 4) = apf[it * 2 + 1];                                \
            uint32_t h[4], lo[4];                                               \
            _Pragma("unroll")                                                   \
            for (int j = 0; j < 4; j++) {                                       \
                h[j] = pack_bf16x2(f[2 * j], f[2 * j + 1]);                     \
                __nv_bfloat162 hb = *reinterpret_cast<__nv_bfloat162*>(&h[j]);  \
                float2 hr = __bfloat1622float2(hb);                             \
                lo[j] = pack_bf16x2(f[2 * j] - hr.x, f[2 * j + 1] - hr.y);      \
            }                                                                   \
            *(uint4*)(smem + T1_AHI + so_) = make_uint4(h[0], h[1], h[2], h[3]); \
            *(uint4*)(smem + T1_ALO + so_) = make_uint4(lo[0], lo[1], lo[2], lo[3]); \
        }                                                                       \
    }

#define MMA_CHUNK1(FIRST)                                                       \
    if (wid == 0 && elect_one()) {                                              \
        _Pragma("unroll")                                                       \
        for (int T = 0; T < 2; T++) {                                           \
            uint64_t bh = dBhi + T * 1024;                                      \
            uint64_t bl = dBlo + T * 1024;                                      \
            uint32_t dt = tmem + T * 128;                                       \
            _Pragma("unroll")                                                   \
            for (int s = 0; s < 4; s++)                                         \
                mma_bf16_ss(dt, dAhi + s * 2, bh + s * 2, TG_IDESC,             \
                            ((FIRST) && s == 0) ? 0u : 1u);                     \
            _Pragma("unroll")                                                   \
            for (int s = 0; s < 4; s++)                                         \
                mma_bf16_ss(dt, dAhi + s * 2, bl + s * 2, TG_IDESC, 1u);        \
            _Pragma("unroll")                                                   \
            for (int s = 0; s < 4; s++)                                         \
                mma_bf16_ss(dt, dAlo + s * 2, bh + s * 2, TG_IDESC, 1u);        \
        }                                                                       \
        TC_COMMIT(sb + SOFF_MBAR);                                              \
    }

    // ---- chunk 0 ----
    PREF_A1(0);
    CPASYNC_B1(0);
    STORE_A1();
    CP_WAIT0();
    FENCE_ASYNC();
    __syncthreads();
    MMA_CHUNK1(true);
    // ---- chunk 1 (A prefetch overlaps MMA0) ----
    PREF_A1(1);
    MB_WAIT(sb + SOFF_MBAR, 0);
    CPASYNC_B1(1);
    STORE_A1();
    CP_WAIT0();
    FENCE_ASYNC();
    __syncthreads();
    MMA_CHUNK1(false);
    MB_WAIT(sb + SOFF_MBAR, 1);
    TC_FENCE_AFTER();

#undef PREF_A1
#undef CPASYNC_B1
#undef STORE_A1
#undef MMA_CHUNK1

    // ---- epilogue: 4 pairs of 32-col blocks ----
    float* buf  = reinterpret_cast<float*>(smem + T1_BHI);   // [128][66]
    float* psum = reinterpret_cast<float*>(smem + T1_PSUM);  // [4][64]
    float* psq  = reinterpret_cast<float*>(smem + T1_PSQ);
    float* ssl  = reinterpret_cast<float*>(smem + T1_SSL);   // [256]
    float* sql  = reinterpret_cast<float*>(smem + T1_SQL);
    float* sB   = reinterpret_cast<float*>(smem + SOFF_SC);

    for (int pr = 0; pr < 4; pr++) {
        if (wid < 4) {
            int r = wid * 32 + lid;
            int grow = bm + r;
            uint32_t r0[32], r1[32];
            LDTM32(r0, tmem + pr * 64);
            LDTM32(r1, tmem + pr * 64 + 32);
            TC_WAIT_LD();
            float v0[32], v1[32];
#pragma unroll
            for (int i = 0; i < 32; i++) {
                v0[i] = __uint_as_float(r0[i]) + sB[pr * 64 + i];
                v1[i] = __uint_as_float(r1[i]) + sB[pr * 64 + 32 + i];
            }
            if (grow < M) {
                float* cp = C + (size_t)grow * NC + pr * 64;
#pragma unroll
                for (int q = 0; q < 8; q++) {
                    *(float4*)(cp + q * 4)      = *(float4*)(v0 + q * 4);
                    *(float4*)(cp + 32 + q * 4) = *(float4*)(v1 + q * 4);
                }
            } else {
#pragma unroll
                for (int i = 0; i < 32; i++) { v0[i] = 0.f; v1[i] = 0.f; }
            }
#pragma unroll
            for (int i = 0; i < 32; i++) {
                buf[r * 66 + i]      = v0[i];
                buf[r * 66 + 32 + i] = v1[i];
            }
        }
        __syncthreads();
        {
            int c = t & 63, h = t >> 6;
            float s = 0.f, q = 0.f;
#pragma unroll 8
            for (int rr = 0; rr < 32; rr++) {
                float v = buf[(h * 32 + rr) * 66 + c];
                s += v;
                q = fmaf(v, v, q);
            }
            psum[h * 64 + c] = s;
            psq[h * 64 + c]  = q;
        }
        __syncthreads();
        if (t < 64) {
            ssl[pr * 64 + t] = psum[t] + psum[64 + t] + psum[128 + t] + psum[192 + t];
            sql[pr * 64 + t] = psq[t]  + psq[64 + t]  + psq[128 + t]  + psq[192 + t];
        }
    }
    if (wid < 4) TC_FENCE_BEFORE();
    __syncthreads();
    atomicAdd(&g_ssum[t], ssl[t]);
    atomicAdd(&g_ssq[t],  sql[t]);
    if (t == 0) MB_INVAL(sb + SOFF_MBAR);
    if (wid == 0) TC_DEALLOC(tmem, 256);
}

// ============ GEMM2: h2[M,128] = bnrelu_y(y)[M,256] @ W2 + b2 (R5 structure) ============
#define T_AHI 4096
#define T_ALO 20480
#define T_BHI0 36864
#define T_BLO0 53248
#define T_BHI1 69632
#define T_BLO1 86016
#define TG_SMEM 102400

__global__ void __launch_bounds__(256, 2) tgemm2_k(
    const float* __restrict__ A,
    const __nv_bfloat16* __restrict__ Bhi, const __nv_bfloat16* __restrict__ Blo,
    const float* __restrict__ bias, float* __restrict__ C,
    const float* __restrict__ gamma, const float* __restrict__ beta, float invM,
    int M)
{
    extern __shared__ char smem[];
    const uint32_t sb = smem_u32(smem);
    const int t = threadIdx.x, wid = t >> 5, lid = t & 31;
    const int bm = blockIdx.x * 128;
    const int K = 256, NC = 128;
    float* sSc = reinterpret_cast<float*>(smem + SOFF_SC);
    float* sSh = reinterpret_cast<float*>(smem + SOFF_SH);

    if (wid == 0) TC_ALLOC(sb + SOFF_PTR, 128);
    if (t == 0) MB_INIT(sb + SOFF_MBAR, 1);
    {   // y-BN scale/shift for all 256 input channels
        float m   = g_ssum[t] * invM;
        float var = g_ssq[t] * invM - m * m;
        float sc  = gamma[t] * rsqrtf(var + 1e-5f);
        sSc[t] = sc;
        sSh[t] = beta[t] - m * sc;
    }
    __syncthreads();
    uint32_t tmem;
    asm volatile("ld.shared.b32 %0, [%1];" : "=r"(tmem) : "r"(sb + SOFF_PTR));

    const uint64_t dAhi = make_desc(sb + T_AHI);
    const uint64_t dAlo = make_desc(sb + T_ALO);
    const uint64_t dBhi[2] = { make_desc(sb + T_BHI0), make_desc(sb + T_BHI1) };
    const uint64_t dBlo[2] = { make_desc(sb + T_BLO0), make_desc(sb + T_BLO1) };
    const int nch = 4;

    float4 apf[8];

#define PREF_A2(CH)                                                             \
    {                                                                           \
        int kbase_ = (CH) * 64;                                                 \
        _Pragma("unroll")                                                       \
        for (int it = 0; it < 4; it++) {                                        \
            int idx = t + it * 256;                                             \
            int r_ = idx >> 3, kg_ = idx & 7;                                   \
            int grow_ = bm + r_;                                                \
            if (grow_ < M) {                                                    \
                const float* ap = A + (size_t)grow_ * K + kbase_ + kg_ * 8;     \
                apf[it * 2]     = *(const float4*)ap;                           \
                apf[it * 2 + 1] = *(const float4*)(ap + 4);                     \
            } else {                                                            \
                apf[it * 2] = apf[it * 2 + 1] = make_float4(0.f, 0.f, 0.f, 0.f); \
            }                                                                   \
        }                                                                       \
    }

#define CPASYNC_B2(CH, BUF)                                                     \
    {                                                                           \
        int kbase_ = (CH) * 64;                                                 \
        uint32_t bhi_ = sb + ((BUF) ? T_BHI1 : T_BHI0);                         \
        uint32_t blo_ = sb + ((BUF) ? T_BLO1 : T_BLO0);                         \
        _Pragma("unroll")                                                       \
        for (int it = 0; it < 4; it++) {                                        \
            int idx = t + it * 256;                                             \
            int r_ = idx >> 3, kg_ = idx & 7;                                   \
            uint32_t so_ = SW128((uint32_t)(r_ * 128 + kg_ * 16));              \
            size_t bo_ = (size_t)r_ * K + kbase_ + kg_ * 8;                     \
            CP_ASYNC16(bhi_ + so_, Bhi + bo_);                                  \
            CP_ASYNC16(blo_ + so_, Blo + bo_);                                  \
        }                                                                       \
        CP_COMMIT();                                                            \
    }

#define STORE_A2(CH)                                                            \
    {                                                                           \
        int kbase_ = (CH) * 64;                                                 \
        _Pragma("unroll")                                                       \
        for (int it = 0; it < 4; it++) {                                        \
            int idx = t + it * 256;                                             \
            int r_ = idx >> 3, kg_ = idx & 7;                                   \
            uint32_t so_ = SW128((uint32_t)(r_ * 128 + kg_ * 16));              \
            int cb_ = kbase_ + kg_ * 8;                                         \
            float f[8];                                                         \
            *(float4*)(f)     = apf[it * 2];                                    \
            *(float4*)(f + 4) = apf[it * 2 + 1];                                \
            _Pragma("unroll")                                                   \
            for (int j = 0; j < 8; j++)                                         \
                f[j] = fmaxf(fmaf(f[j], sSc[cb_ + j], sSh[cb_ + j]), 0.f);      \
            uint32_t h[4], lo[4];                                               \
            _Pragma("unroll")                                                   \
            for (int j = 0; j < 4; j++) {                                       \
                h[j] = pack_bf16x2(f[2 * j], f[2 * j + 1]);                     \
                __nv_bfloat162 hb = *reinterpret_cast<__nv_bfloat162*>(&h[j]);  \
                float2 hr = __bfloat1622float2(hb);                             \
                lo[j] = pack_bf16x2(f[2 * j] - hr.x, f[2 * j + 1] - hr.y);      \
            }                                                                   \
            *(uint4*)(smem + T_AHI + so_) = make_uint4(h[0], h[1], h[2], h[3]); \
            *(uint4*)(smem + T_ALO + so_) = make_uint4(lo[0], lo[1], lo[2], lo[3]); \
        }                                                                       \
    }

    // ---- prologue: chunk 0 ----
    PREF_A2(0);
    CPASYNC_B2(0, 0);
    STORE_A2(0);
    CP_WAIT0();
    FENCE_ASYNC();
    __syncthreads();
    if (wid == 0 && elect_one()) {
#pragma unroll
        for (int s = 0; s < 4; s++)
            mma_bf16_ss(tmem, dAhi + s * 2, dBhi[0] + s * 2, TG_IDESC, s == 0 ? 0u : 1u);
#pragma unroll
        for (int s = 0; s < 4; s++)
            mma_bf16_ss(tmem, dAhi + s * 2, dBlo[0] + s * 2, TG_IDESC, 1u);
#pragma unroll
        for (int s = 0; s < 4; s++)
            mma_bf16_ss(tmem, dAlo + s * 2, dBhi[0] + s * 2, TG_IDESC, 1u);
        TC_COMMIT(sb + SOFF_MBAR);
    }

    for (int ch = 1; ch < nch; ch++) {
        int buf = ch & 1;
        PREF_A2(ch);
        CPASYNC_B2(ch, buf);
        MB_WAIT(sb + SOFF_MBAR, (ch - 1) & 1);
        STORE_A2(ch);
        CP_WAIT0();
        FENCE_ASYNC();
        __syncthreads();
        if (wid == 0 && elect_one()) {
#pragma unroll
            for (int s = 0; s < 4; s++)
                mma_bf16_ss(tmem, dAhi + s * 2, dBhi[buf] + s * 2, TG_IDESC, 1u);
#pragma unroll
            for (int s = 0; s < 4; s++)
                mma_bf16_ss(tmem, dAhi + s * 2, dBlo[buf] + s * 2, TG_IDESC, 1u);
#pragma unroll
            for (int s = 0; s < 4; s++)
                mma_bf16_ss(tmem, dAlo + s * 2, dBhi[buf] + s * 2, TG_IDESC, 1u);
            TC_COMMIT(sb + SOFF_MBAR);
        }
    }
    MB_WAIT(sb + SOFF_MBAR, (nch - 1) & 1);
    TC_FENCE_AFTER();

#undef PREF_A2
#undef CPASYNC_B2
#undef STORE_A2

    // ---- epilogue: 2 pairs of 32-col blocks ----
    float* buf = reinterpret_cast<float*>(smem + T_AHI);   // [128][129]
    if (wid < 4) {
        int r = wid * 32 + lid;
        int grow = bm + r;
#pragma unroll
        for (int pb = 0; pb < 2; pb++) {
            uint32_t r0[32], r1[32];
            LDTM32(r0, tmem + pb * 64);
            LDTM32(r1, tmem + pb * 64 + 32);
            TC_WAIT_LD();
            float v0[32], v1[32];
#pragma unroll
            for (int i = 0; i < 32; i++) {
                v0[i] = __uint_as_float(r0[i]) + bias[pb * 64 + i];
                v1[i] = __uint_as_float(r1[i]) + bias[pb * 64 + 32 + i];
            }
            if (grow < M) {
                float* cp = C + (size_t)grow * NC + pb * 64;
#pragma unroll
                for (int q = 0; q < 8; q++) {
                    *(float4*)(cp + q * 4)      = *(float4*)(v0 + q * 4);
                    *(float4*)(cp + 32 + q * 4) = *(float4*)(v1 + q * 4);
                }
            }
#pragma unroll
            for (int i = 0; i < 32; i++) {
                buf[r * 129 + pb * 64 + i]      = v0[i];
                buf[r * 129 + pb * 64 + 32 + i] = v1[i];
            }
        }
        TC_FENCE_BEFORE();
    }
    __syncthreads();

    {   // column stats -> g_ssum2/g_ssq2
        int c = t & 127, h = t >> 7;
        float s = 0.f, q = 0.f;
#pragma unroll 8
        for (int rr = 0; rr < 64; rr++) {
            int r = h * 64 + rr;
            if (bm + r < M) {
                float v = buf[r * 129 + c];
                s += v;
                q = fmaf(v, v, q);
            }
        }
        atomicAdd(&g_ssum2[c], s);
        atomicAdd(&g_ssq2[c], q);
    }
    __syncthreads();
    if (t == 0) MB_INVAL(sb + SOFF_MBAR);
    if (wid == 0) TC_DEALLOC(tmem, 128);
}

// outer BN finalize: scale/shift for h2; zero both stats sets for next layer
__global__ void finalize_k(const float* __restrict__ gamma, const float* __restrict__ beta,
                           float invM) {
    int t = threadIdx.x;  // 256
    if (t < 128) {
        float m   = g_ssum2[t] * invM;
        float var = g_ssq2[t] * invM - m * m;
        float sc  = gamma[t] * rsqrtf(var + 1e-5f);
        g_scale[t] = sc;
        g_shift[t] = beta[t] - m * sc;
        g_ssum2[t] = 0.f;
        g_ssq2[t]  = 0.f;
    }
    g_ssum[t] = 0.f;
    g_ssq[t]  = 0.f;
}

// ---------------- readout pooling ----------------
__global__ void pool_k(const void* __restrict__ batch, int n) {
    long long t = (long long)blockIdx.x * blockDim.x + threadIdx.x;
    long long i = t >> 5;
    if (i >= n) return;
    int lane = (int)(t & 31);
    long long g;
    if (g_i64flag) g = ((const long long*)batch)[i];
    else           g = (long long)((const int*)batch)[i];
    int c = lane * 4;
    float4 v = ((const float4*)g_h2)[i * 32 + lane];
    float r0 = fmaxf(fmaf(v.x, g_scale[c + 0], g_shift[c + 0]), 0.f);
    float r1 = fmaxf(fmaf(v.y, g_scale[c + 1], g_shift[c + 1]), 0.f);
    float r2 = fmaxf(fmaf(v.z, g_scale[c + 2], g_shift[c + 2]), 0.f);
    float r3 = fmaxf(fmaf(v.w, g_scale[c + 3], g_shift[c + 3]), 0.f);
    float* ps = g_ps + g * 128 + c;
    asm volatile("red.global.add.v4.f32 [%0], {%1, %2, %3, %4};"
                 :: "l"(ps), "f"(r0), "f"(r1), "f"(r2), "f"(r3) : "memory");
    unsigned int* mx = (unsigned int*)(g_pmx + g * 128 + c);
    atomicMax(mx + 0, __float_as_uint(r0));
    atomicMax(mx + 1, __float_as_uint(r1));
    atomicMax(mx + 2, __float_as_uint(r2));
    atomicMax(mx + 3, __float_as_uint(r3));
    if (lane == 0) atomicAdd(&g_cnt[g], 1.0f);
}

// ---------------- classifier ----------------
__global__ void cgemm1_k(const float* __restrict__ cW1, const float* __restrict__ cb1) {
    int g = blockIdx.x;
    int j = threadIdx.x;  // 128
    __shared__ float z[384];
    float cnt = fmaxf(g_cnt[g], 1.0f);
    float sv = g_ps[g * 128 + j];
    z[j]       = sv;
    z[128 + j] = sv / cnt;
    z[256 + j] = g_pmx[g * 128 + j];
    __syncthreads();
    float acc = cb1[j];
#pragma unroll 8
    for (int k = 0; k < 384; k++)
        acc = fmaf(z[k], cW1[k * 128 + j], acc);
    g_z1[g * 128 + j] = acc;
}

__global__ void cstats_k(const float* __restrict__ cg, const float* __restrict__ cbeta) {
    int j = threadIdx.x;  // 128
    float s = 0.f, q = 0.f;
    for (int g = 0; g < GCNT; g++) {
        float v = g_z1[g * 128 + j];
        s += v; q += v * v;
    }
    float m   = s * (1.0f / GCNT);
    float var = q * (1.0f / GCNT) - m * m;
    float sc  = cg[j] * rsqrtf(var + 1e-5f);
    g_scale[j] = sc;
    g_shift[j] = cbeta[j] - m * sc;
}

__global__ void chead_k(const float* __restrict__ cW2, const float* __restrict__ cb2,
                        const float* __restrict__ cW3, const float* __restrict__ cb3,
                        float* __restrict__ out) {
    int g = blockIdx.x;
    int j = threadIdx.x;  // 64
    __shared__ float a[128];
    __shared__ float z2[64];
    for (int k = j; k < 128; k += 64)
        a[k] = fmaxf(fmaf(g_z1[g * 128 + k], g_scale[k], g_shift[k]), 0.f);
    __syncthreads();
    float acc = cb2[j];
#pragma unroll 8
    for (int k = 0; k < 128; k++)
        acc = fmaf(a[k], cW2[k * 64 + j], acc);
    z2[j] = fmaxf(acc, 0.f);
    __syncthreads();
    if (j < 2) {
        float o = cb3[j];
#pragma unroll 8
        for (int k = 0; k < 64; k++)
            o = fmaf(z2[k], cW3[k * 2 + j], o);
        out[g * 2 + j] = o;
    }
}

// ---------------- launcher ----------------
extern "C" void kernel_launch(void* const* d_in, const int* in_sizes, int n_in,
                              void* d_out, int out_size) {
    const float* x     = (const float*)d_in[0];
    const void*  ei    = d_in[1];
    const void*  batch = d_in[2];
    int base = (in_sizes[3] == 1) ? 4 : 3;
    const float* W1    = (const float*)d_in[base + 0];
    const float* b1    = (const float*)d_in[base + 1];
    const float* g1    = (const float*)d_in[base + 2];
    const float* be1   = (const float*)d_in[base + 3];
    const float* W2    = (const float*)d_in[base + 4];
    const float* b2    = (const float*)d_in[base + 5];
    const float* gbn   = (const float*)d_in[base + 6];
    const float* bbn   = (const float*)d_in[base + 7];
    const float* eps   = (const float*)d_in[base + 8];
    const float* cW1   = (const float*)d_in[base + 9];
    const float* cb1   = (const float*)d_in[base + 10];
    const float* cg    = (const float*)d_in[base + 11];
    const float* cbeta = (const float*)d_in[base + 12];
    const float* cW2   = (const float*)d_in[base + 13];
    const float* cb2   = (const float*)d_in[base + 14];
    const float* cW3   = (const float*)d_in[base + 15];
    const float* cb3   = (const float*)d_in[base + 16];

    int n = in_sizes[0] / 128;
    long long E = (long long)in_sizes[1] / 2;
    int n32 = n * 32;
    int nb = (n32 + 255) / 256;
    int gx = (n + 127) / 128;
    long long nwarp = (E + 3) / 4;
    int sblk = (int)((nwarp * 32 + 255) / 256);
    float invM = 1.0f / (float)n;

    static int smem_set = 0;
    if (!smem_set) {
        cudaFuncSetAttribute(tgemm1_k, cudaFuncAttributeMaxDynamicSharedMemorySize, TG1_SMEM);
        cudaFuncSetAttribute(tgemm2_k, cudaFuncAttributeMaxDynamicSharedMemorySize, TG_SMEM);
        smem_set = 1;
    }

    float *p_hin, *p_y, *p_h2;
    __nv_bfloat16 *p_b1hi, *p_b1lo, *p_b2hi, *p_b2lo;
    cudaGetSymbolAddress((void**)&p_hin, g_hin);
    cudaGetSymbolAddress((void**)&p_y,   g_y);
    cudaGetSymbolAddress((void**)&p_h2,  g_h2);
    cudaGetSymbolAddress((void**)&p_b1hi, g_b1hi);
    cudaGetSymbolAddress((void**)&p_b1lo, g_b1lo);
    cudaGetSymbolAddress((void**)&p_b2hi, g_b2hi);
    cudaGetSymbolAddress((void**)&p_b2lo, g_b2lo);

    detect_k<<<1, 1>>>((const unsigned int*)ei);
    wconv_k<<<(NLAYER * 256 * 128 + 255) / 256, 256>>>(W1, W2);
    prep0_k<<<nb, 256>>>((const float4*)x, eps, n32);

    for (int l = 0; l < 4; l++) {
        if (l > 0) {
            prep_k<<<nb, 256>>>(eps, l, n32);
            scatter_k<true><<<sblk, 256>>>(ei, p_h2, E);
        } else {
            scatter_k<false><<<sblk, 256>>>(ei, x, E);
        }
        tgemm1_k<<<gx, 256, TG1_SMEM>>>(
            p_hin, p_b1hi + (size_t)l * 32768, p_b1lo + (size_t)l * 32768,
            b1 + l * 256, p_y, n);
        tgemm2_k<<<gx, 256, TG_SMEM>>>(
            p_y, p_b2hi + (size_t)l * 32768, p_b2lo + (size_t)l * 32768,
            b2 + l * 128, p_h2, g1 + l * 256, be1 + l * 256, invM, n);
        finalize_k<<<1, 256>>>(gbn + l * 128, bbn + l * 128, invM);
    }

    pool_k<<<nb, 256>>>(batch, n);
    cgemm1_k<<<GCNT, 128>>>(cW1, cb1);
    cstats_k<<<1, 128>>>(cg, cbeta);
    chead_k<<<GCNT, 64>>>(cW2, cb2, cW3, cb3, (float*)d_out);
}

// round 8
// speedup vs baseline: 1.1624x; 1.0888x over previous
#include <cuda_runtime.h>
#include <cuda_bf16.h>
#include <cstdint>
#include <cstddef>

// Problem constants (fixed shapes)
#define NMAX 100000
#define GCNT 512
#define NLAYER 4

// tcgen05 only exists in the arch-specific (sm_103a) device pass.
#if defined(__CUDA_ARCH__) && defined(__CUDA_ARCH_FEAT_SM103_ALL)
#define HAS_TC 1
#else
#define HAS_TC 0
#endif

// ---------------- device scratch ----------------
__device__ float g_hin[NMAX * 128];
__device__ float g_h2 [NMAX * 128];
__device__ float g_ssum [256];   // stats of y  (inner BN)
__device__ float g_ssq  [256];
__device__ float g_ssum2[128];   // stats of h2 (outer BN)
__device__ float g_ssq2 [128];
__device__ float g_scale[256];   // outer BN affine (also reused by classifier)
__device__ float g_shift[256];
__device__ float g_ps [GCNT * 128];
__device__ float g_pmx[GCNT * 128];
__device__ float g_cnt[GCNT];
__device__ float g_z1 [GCNT * 128];
__device__ int   g_i64flag;

// pre-split weights, B layout: [layer][n(out)][k(in)] bf16, K-major rows
__device__ __nv_bfloat16 g_b1hi[NLAYER * 256 * 128];
__device__ __nv_bfloat16 g_b1lo[NLAYER * 256 * 128];
__device__ __nv_bfloat16 g_b2hi[NLAYER * 128 * 256];
__device__ __nv_bfloat16 g_b2lo[NLAYER * 128 * 256];

// ---------------- PTX helpers ----------------
__device__ __forceinline__ uint32_t smem_u32(const void* p) {
    uint32_t a;
    asm("{ .reg .u64 t; cvta.to.shared.u64 t, %1; cvt.u32.u64 %0, t; }" : "=r"(a) : "l"(p));
    return a;
}
__device__ __forceinline__ uint32_t elect_one() {
    uint32_t p;
    asm volatile("{ .reg .pred p; elect.sync _|p, 0xFFFFFFFF; selp.b32 %0, 1, 0, p; }" : "=r"(p));
    return p;
}
#define SW128(o) ((o) ^ (((o) >> 3) & 0x70))
static __device__ __forceinline__ uint64_t make_desc(uint32_t addr) {
    // SW128, version=1 (Blackwell), SBO=64, LBO=1
    return ((uint64_t)2 << 61) | ((uint64_t)1 << 46) | ((uint64_t)64 << 32) |
           ((uint64_t)1 << 16) | ((uint64_t)(addr >> 4) & 0x3FFF);
}

#if HAS_TC
__device__ __forceinline__ void mma_bf16_ss(uint32_t d, uint64_t a, uint64_t b,
                                            uint32_t idesc, uint32_t en) {
    asm volatile(
        "{\n\t.reg .pred p;\n\tsetp.ne.u32 p, %4, 0;\n\t"
        "tcgen05.mma.cta_group::1.kind::f16 [%0], %1, %2, %3, {%5, %5, %5, %5}, p;\n\t}"
        :: "r"(d), "l"(a), "l"(b), "r"(idesc), "r"(en), "r"(0u) : "memory");
}
#define TC_ALLOC(sm, n)  asm volatile("tcgen05.alloc.cta_group::1.sync.aligned.shared::cta.b32 [%0], %1;" :: "r"(sm), "r"((uint32_t)(n)) : "memory")
#define TC_DEALLOC(t, n) asm volatile("tcgen05.dealloc.cta_group::1.sync.aligned.b32 %0, %1;" :: "r"(t), "r"((uint32_t)(n)))
#define TC_COMMIT(mb)    asm volatile("tcgen05.commit.cta_group::1.mbarrier::arrive::one.shared::cluster.b64 [%0];" :: "r"(mb) : "memory")
#define TC_FENCE_AFTER() asm volatile("tcgen05.fence::after_thread_sync;" ::: "memory")
#define TC_FENCE_BEFORE() asm volatile("tcgen05.fence::before_thread_sync;" ::: "memory")
#define TC_WAIT_LD()     asm volatile("tcgen05.wait::ld.sync.aligned;" ::: "memory")
#define LDTM32(r, a)                                                            \
    asm volatile("tcgen05.ld.sync.aligned.32x32b.x32.b32 "                      \
        "{%0,%1,%2,%3,%4,%5,%6,%7,%8,%9,%10,%11,%12,%13,%14,%15,"               \
        "%16,%17,%18,%19,%20,%21,%22,%23,%24,%25,%26,%27,%28,%29,%30,%31}, [%32];" \
        : "=r"((r)[0]),"=r"((r)[1]),"=r"((r)[2]),"=r"((r)[3]),                  \
          "=r"((r)[4]),"=r"((r)[5]),"=r"((r)[6]),"=r"((r)[7]),                  \
          "=r"((r)[8]),"=r"((r)[9]),"=r"((r)[10]),"=r"((r)[11]),                \
          "=r"((r)[12]),"=r"((r)[13]),"=r"((r)[14]),"=r"((r)[15]),              \
          "=r"((r)[16]),"=r"((r)[17]),"=r"((r)[18]),"=r"((r)[19]),              \
          "=r"((r)[20]),"=r"((r)[21]),"=r"((r)[22]),"=r"((r)[23]),              \
          "=r"((r)[24]),"=r"((r)[25]),"=r"((r)[26]),"=r"((r)[27]),              \
          "=r"((r)[28]),"=r"((r)[29]),"=r"((r)[30]),"=r"((r)[31])               \
        : "r"(a))
#define MB_WAIT(mb, par) do {                                                   \
    uint32_t _m = (mb), _p = (par), _d;                                         \
    asm volatile("{ .reg .pred p; mbarrier.try_wait.parity.acquire.cta.shared::cta.b64 p, [%1], %2; selp.b32 %0, 1, 0, p; }" \
                 : "=r"(_d) : "r"(_m), "r"(_p) : "memory");                     \
    if (!_d) {                                                                  \
        asm volatile("{ .reg .pred P1; W%=: mbarrier.try_wait.parity.acquire.cta.shared::cta.b64 P1, [%0], %1, 0x989680; @P1 bra.uni D%=; bra.uni W%=; D%=: }" \
                     :: "r"(_m), "r"(_p) : "memory");                           \
    }                                                                           \
} while (0)
#else
// compute_103 (non-'a') pass: stubs. Never executed (sm_103a cubin selected).
__device__ __forceinline__ void mma_bf16_ss(uint32_t, uint64_t, uint64_t, uint32_t, uint32_t) {}
#define TC_ALLOC(sm, n)   ((void)0)
#define TC_DEALLOC(t, n)  ((void)0)
#define TC_COMMIT(mb)     ((void)0)
#define TC_FENCE_AFTER()  ((void)0)
#define TC_FENCE_BEFORE() ((void)0)
#define TC_WAIT_LD()      ((void)0)
#define LDTM32(r, a)      do { _Pragma("unroll") for (int _i = 0; _i < 32; _i++) (r)[_i] = 0u; } while (0)
#define MB_WAIT(mb, par)  ((void)0)
#endif

#define MB_INIT(mb, c)   asm volatile("mbarrier.init.shared.b64 [%0], %1;" :: "r"(mb), "r"((uint32_t)(c)) : "memory")
#define MB_INVAL(mb)     asm volatile("mbarrier.inval.shared.b64 [%0];" :: "r"(mb) : "memory")
#define FENCE_ASYNC()    asm volatile("fence.proxy.async.shared::cta;" ::: "memory")
#define CP_ASYNC16(dst, src) asm volatile("cp.async.ca.shared.global [%0], [%1], 16;" :: "r"(dst), "l"(src) : "memory")
#define CP_COMMIT()      asm volatile("cp.async.commit_group;" ::: "memory")
#define CP_WAIT0()       asm volatile("cp.async.wait_group 0;" ::: "memory")

// ---------------- dtype detection (int32 vs int64 indices) ----------------
__global__ void detect_k(const unsigned int* __restrict__ e) {
    unsigned acc = 0;
    for (int i = 1; i < 128; i += 2) acc |= e[i];
    g_i64flag = (acc == 0u) ? 1 : 0;
}

// ---------------- weight split fp32 -> bf16 hi/lo ----------------
__global__ void wconv_k(const float* __restrict__ W1, const float* __restrict__ W2) {
    int i = blockIdx.x * 256 + threadIdx.x;
    const int tot = NLAYER * 256 * 128;
    if (i >= tot) return;
    int l = i / (256 * 128), rem = i % (256 * 128);
    {   // W1: [l][k(128)][n(256)] -> B1 [l][n][k]
        int n = rem / 128, k = rem % 128;
        float w = W1[l * 32768 + k * 256 + n];
        __nv_bfloat16 h = __float2bfloat16(w);
        g_b1hi[i] = h;
        g_b1lo[i] = __float2bfloat16(w - __bfloat162float(h));
    }
    {   // W2: [l][k(256)][n(128)] -> B2 [l][n][k]
        int n = rem / 256, k = rem % 256;
        float w = W2[l * 32768 + k * 128 + n];
        __nv_bfloat16 h = __float2bfloat16(w);
        g_b2hi[i] = h;
        g_b2lo[i] = __float2bfloat16(w - __bfloat162float(h));
    }
}

// ---------------- prep kernels ----------------
__global__ void prep0_k(const float4* __restrict__ x, const float* __restrict__ epsp, int n32) {
    int i = blockIdx.x * blockDim.x + threadIdx.x;
    if (i < n32) {
        float e = 1.0f + epsp[0];
        float4 v = x[i];
        ((float4*)g_hin)[i] = make_float4(v.x * e, v.y * e, v.z * e, v.w * e);
    }
    if (i < 256) { g_ssum[i] = 0.f; g_ssq[i] = 0.f; }
    if (i < 128) { g_ssum2[i] = 0.f; g_ssq2[i] = 0.f; }
    if (i < GCNT * 128) { g_ps[i] = 0.f; g_pmx[i] = 0.f; }
    if (i < GCNT) g_cnt[i] = 0.f;
}

__global__ void prep_k(const float* __restrict__ epsp, int l, int n32) {
    int i = blockIdx.x * blockDim.x + threadIdx.x;
    if (i < n32) {
        float e = 1.0f + epsp[l];
        int c = (i & 31) * 4;
        float4 v = ((const float4*)g_h2)[i];
        float4 r;
        r.x = fmaxf(fmaf(v.x, g_scale[c + 0], g_shift[c + 0]), 0.f) * e;
        r.y = fmaxf(fmaf(v.y, g_scale[c + 1], g_shift[c + 1]), 0.f) * e;
        r.z = fmaxf(fmaf(v.z, g_scale[c + 2], g_shift[c + 2]), 0.f) * e;
        r.w = fmaxf(fmaf(v.w, g_scale[c + 3], g_shift[c + 3]), 0.f) * e;
        ((float4*)g_hin)[i] = r;
    }
}

// ---------------- edge scatter-add: hin[dst] += f(SRC[src]) ----------------
template<bool BN>
__global__ void scatter_k(const void* __restrict__ ei, const float* __restrict__ SRC,
                          long long E) {
    long long w = ((long long)blockIdx.x * blockDim.x + threadIdx.x) >> 5;
    int lane = threadIdx.x & 31;
    long long e0 = w * 4;
    if (e0 >= E) return;
    int cnt = (int)((E - e0 < 4) ? (E - e0) : 4);

    long long s[4], d[4];
    if (g_i64flag) {
        const long long* p = (const long long*)ei;
#pragma unroll
        for (int j = 0; j < 4; j++)
            if (j < cnt) { s[j] = p[e0 + j]; d[j] = p[E + e0 + j]; }
    } else {
        const int* p = (const int*)ei;
#pragma unroll
        for (int j = 0; j < 4; j++)
            if (j < cnt) { s[j] = (long long)p[e0 + j]; d[j] = (long long)p[E + e0 + j]; }
    }

    float4 v[4];
#pragma unroll
    for (int j = 0; j < 4; j++)
        if (j < cnt) v[j] = ((const float4*)SRC)[s[j] * 32 + lane];

    float sc0, sc1, sc2, sc3, sh0, sh1, sh2, sh3;
    if (BN) {
        int c = lane * 4;
        sc0 = g_scale[c]; sc1 = g_scale[c + 1]; sc2 = g_scale[c + 2]; sc3 = g_scale[c + 3];
        sh0 = g_shift[c]; sh1 = g_shift[c + 1]; sh2 = g_shift[c + 2]; sh3 = g_shift[c + 3];
    }

#pragma unroll
    for (int j = 0; j < 4; j++) {
        if (j < cnt) {
            float r0 = v[j].x, r1 = v[j].y, r2 = v[j].z, r3 = v[j].w;
            if (BN) {
                r0 = fmaxf(fmaf(r0, sc0, sh0), 0.f);
                r1 = fmaxf(fmaf(r1, sc1, sh1), 0.f);
                r2 = fmaxf(fmaf(r2, sc2, sh2), 0.f);
                r3 = fmaxf(fmaf(r3, sc3, sh3), 0.f);
            }
            float* dst = g_hin + d[j] * 128 + lane * 4;
            asm volatile("red.global.add.v4.f32 [%0], {%1, %2, %3, %4};"
                         :: "l"(dst), "f"(r0), "f"(r1), "f"(r2), "f"(r3) : "memory");
        }
    }
}

// ================== fused layer kernel ==================
// PASS 1: y = hin@W1 + b1 computed in TMEM; per-channel stats -> g_ssum/g_ssq. y NOT stored.
// PASS 2: recompute y, apply y-BN+ReLU in-register (stats from g_ssum), feed bf16 hi/lo
//         A-tiles of GEMM2 through smem, h2 = bnrelu(y)@W2 + b2 -> C + stats (g_ssum2).
//
// smem layout (bytes):
#define P_PTR   0
#define P_MBAR  16
#define P_SC    32      // 256 f
#define P_SH    1056    // 256 f
#define P_SB    2080    // 256 f bias (pass1: b1 ; pass2: b2 in [0,128))
#define P_SSL   3104    // 256 f
#define P_SQL   4128    // 256 f
#define P_PSUM  5152    // 256 f scratch
#define P_PSQ   6176    // 256 f scratch
#define P_A1HI  8192    // 16 KB (phase2: B2HI)
#define P_A1LO  24576   // 16 KB (phase2: B2LO)
#define P_B1HI  40960   // 32 KB (phase2: A2HI slots @40960,@57344 ; final: statbuf 128x66)
#define P_B1LO  73728   // 32 KB (phase2: A2LO slots @73728,@90112)
#define P_SMEM  106496
#define TG_IDESC 0x8200490u   // F32 acc, BF16xBF16, N=128, M=128

__device__ __forceinline__ uint32_t pack_bf16x2(float a, float b) {
    __nv_bfloat162 h = __float22bfloat162_rn(make_float2(a, b));
    return *reinterpret_cast<uint32_t*>(&h);
}

template<int PASS>
__global__ void __launch_bounds__(256, 2) pass_k(
    const float* __restrict__ A,
    const __nv_bfloat16* __restrict__ B1hi, const __nv_bfloat16* __restrict__ B1lo,
    const __nv_bfloat16* __restrict__ B2hi, const __nv_bfloat16* __restrict__ B2lo,
    const float* __restrict__ b1, const float* __restrict__ b2,
    const float* __restrict__ g1, const float* __restrict__ be1, float invM,
    float* __restrict__ C, int M)
{
    extern __shared__ char smem[];
    const uint32_t sb = smem_u32(smem);
    const int t = threadIdx.x, wid = t >> 5, lid = t & 31;
    const int bm = blockIdx.x * 128;
    float* sSc = reinterpret_cast<float*>(smem + P_SC);
    float* sSh = reinterpret_cast<float*>(smem + P_SH);
    float* sB  = reinterpret_cast<float*>(smem + P_SB);
    float* ssl = reinterpret_cast<float*>(smem + P_SSL);
    float* sql = reinterpret_cast<float*>(smem + P_SQL);
    float* psum = reinterpret_cast<float*>(smem + P_PSUM);
    float* psq  = reinterpret_cast<float*>(smem + P_PSQ);
    float* statbuf = reinterpret_cast<float*>(smem + P_B1HI);   // [128][66]

    if (wid == 0) TC_ALLOC(sb + P_PTR, 256);
    if (t == 0) MB_INIT(sb + P_MBAR, 1);
    if (PASS == 1) {
        sB[t] = b1[t];
    } else {
        float m   = g_ssum[t] * invM;
        float var = g_ssq[t] * invM - m * m;
        float sc  = g1[t] * rsqrtf(var + 1e-5f);
        sSc[t] = sc;
        sSh[t] = fmaf(b1[t] - m, sc, be1[t]);   // fold b1 into shift
        if (t < 128) sB[t] = b2[t];
    }
    __syncthreads();
    uint32_t tmem;
    asm volatile("ld.shared.b32 %0, [%1];" : "=r"(tmem) : "r"(sb + P_PTR));

    const uint64_t dA1hi = make_desc(sb + P_A1HI);
    const uint64_t dA1lo = make_desc(sb + P_A1LO);
    const uint64_t dB1hi = make_desc(sb + P_B1HI);
    const uint64_t dB1lo = make_desc(sb + P_B1LO);

    float4 apf[8];
    int pc = 0;   // mbarrier phase counter

    // -------- phase 1: y = hin @ W1 (2 k-chunks, single-buffered) --------
#define PREF_A1(CH)                                                             \
    {                                                                           \
        int kb_ = (CH) * 64;                                                    \
        _Pragma("unroll")                                                       \
        for (int it = 0; it < 4; it++) {                                        \
            int idx = t + it * 256;                                             \
            int r_ = idx >> 3, kg_ = idx & 7;                                   \
            int grow_ = bm + r_;                                                \
            if (grow_ < M) {                                                    \
                const float* ap = A + (size_t)grow_ * 128 + kb_ + kg_ * 8;      \
                apf[it * 2]     = *(const float4*)ap;                           \
                apf[it * 2 + 1] = *(const float4*)(ap + 4);                     \
            } else {                                                            \
                apf[it * 2] = apf[it * 2 + 1] = make_float4(0.f, 0.f, 0.f, 0.f); \
            }                                                                   \
        }                                                                       \
    }
#define STORE_A1()                                                              \
    {                                                                           \
        _Pragma("unroll")                                                       \
        for (int it = 0; it < 4; it++) {                                        \
            int idx = t + it * 256;                                             \
            int r_ = idx >> 3, kg_ = idx & 7;                                   \
            uint32_t so_ = SW128((uint32_t)(r_ * 128 + kg_ * 16));              \
            float f[8];                                                         \
            *(float4*)(f)     = apf[it * 2];                                    \
            *(float4*)(f + 4) = apf[it * 2 + 1];                                \
            uint32_t h[4], lo[4];                                               \
            _Pragma("unroll")                                                   \
            for (int j = 0; j < 4; j++) {                                       \
                h[j] = pack_bf16x2(f[2 * j], f[2 * j + 1]);                     \
                __nv_bfloat162 hb = *reinterpret_cast<__nv_bfloat162*>(&h[j]);  \
                float2 hr = __bfloat1622float2(hb);                             \
                lo[j] = pack_bf16x2(f[2 * j] - hr.x, f[2 * j + 1] - hr.y);      \
            }                                                                   \
            *(uint4*)(smem + P_A1HI + so_) = make_uint4(h[0], h[1], h[2], h[3]); \
            *(uint4*)(smem + P_A1LO + so_) = make_uint4(lo[0], lo[1], lo[2], lo[3]); \
        }                                                                       \
    }
#define CPASYNC_B1(CH)                                                          \
    {                                                                           \
        int kb_ = (CH) * 64;                                                    \
        _Pragma("unroll")                                                       \
        for (int it = 0; it < 8; it++) {                                        \
            int idx = t + it * 256;                                             \
            int r_ = idx >> 3, kg_ = idx & 7;                                   \
            uint32_t so_ = SW128((uint32_t)(r_ * 128 + kg_ * 16));              \
            size_t bo_ = (size_t)r_ * 128 + kb_ + kg_ * 8;                      \
            CP_ASYNC16(sb + P_B1HI + so_, B1hi + bo_);                          \
            CP_ASYNC16(sb + P_B1LO + so_, B1lo + bo_);                          \
        }                                                                       \
        CP_COMMIT();                                                            \
    }
#define MMA1_CHUNK(CH)                                                          \
    if (wid == 0 && elect_one()) {                                              \
        _Pragma("unroll")                                                       \
        for (int T = 0; T < 2; T++) {                                           \
            uint64_t bh = dB1hi + T * 1024;                                     \
            uint64_t bl = dB1lo + T * 1024;                                     \
            uint32_t dt = tmem + T * 128;                                       \
            _Pragma("unroll")                                                   \
            for (int s = 0; s < 4; s++)                                         \
                mma_bf16_ss(dt, dA1hi + s * 2, bh + s * 2, TG_IDESC,            \
                            ((CH) == 0 && s == 0) ? 0u : 1u);                   \
            _Pragma("unroll")                                                   \
            for (int s = 0; s < 4; s++)                                         \
                mma_bf16_ss(dt, dA1hi + s * 2, bl + s * 2, TG_IDESC, 1u);       \
            _Pragma("unroll")                                                   \
            for (int s = 0; s < 4; s++)                                         \
                mma_bf16_ss(dt, dA1lo + s * 2, bh + s * 2, TG_IDESC, 1u);       \
        }                                                                       \
        TC_COMMIT(sb + P_MBAR);                                                 \
    }

    PREF_A1(0);
    CPASYNC_B1(0);
    STORE_A1();
    CP_WAIT0();
    FENCE_ASYNC();
    __syncthreads();
    MMA1_CHUNK(0);
    PREF_A1(1);
    MB_WAIT(sb + P_MBAR, pc & 1); pc++;
    CPASYNC_B1(1);
    STORE_A1();
    CP_WAIT0();
    FENCE_ASYNC();
    __syncthreads();
    MMA1_CHUNK(1);
    MB_WAIT(sb + P_MBAR, pc & 1); pc++;
    TC_FENCE_AFTER();

#undef PREF_A1
#undef STORE_A1
#undef CPASYNC_B1
#undef MMA1_CHUNK

    if (PASS == 1) {
        // -------- y stats only (4 rounds of 64 cols) --------
        for (int pr = 0; pr < 4; pr++) {
            if (wid < 4) {
                int r = wid * 32 + lid;
                int grow = bm + r;
                uint32_t r0[32], r1[32];
                LDTM32(r0, tmem + pr * 64);
                LDTM32(r1, tmem + pr * 64 + 32);
                TC_WAIT_LD();
                float v0[32], v1[32];
#pragma unroll
                for (int i = 0; i < 32; i++) {
                    v0[i] = (grow < M) ? __uint_as_float(r0[i]) + sB[pr * 64 + i]      : 0.f;
                    v1[i] = (grow < M) ? __uint_as_float(r1[i]) + sB[pr * 64 + 32 + i] : 0.f;
                }
#pragma unroll
                for (int i = 0; i < 32; i++) {
                    statbuf[r * 66 + i]      = v0[i];
                    statbuf[r * 66 + 32 + i] = v1[i];
                }
            }
            __syncthreads();
            {
                int c = t & 63, h = t >> 6;
                float s = 0.f, q = 0.f;
#pragma unroll 8
                for (int rr = 0; rr < 32; rr++) {
                    float v = statbuf[(h * 32 + rr) * 66 + c];
                    s += v;
                    q = fmaf(v, v, q);
                }
                psum[h * 64 + c] = s;
                psq[h * 64 + c]  = q;
            }
            __syncthreads();
            if (t < 64) {
                ssl[pr * 64 + t] = psum[t] + psum[64 + t] + psum[128 + t] + psum[192 + t];
                sql[pr * 64 + t] = psq[t]  + psq[64 + t]  + psq[128 + t]  + psq[192 + t];
            }
            __syncthreads();
        }
        if (wid < 4) TC_FENCE_BEFORE();
        __syncthreads();
        atomicAdd(&g_ssum[t], ssl[t]);
        atomicAdd(&g_ssq[t],  sql[t]);
    } else {
        // -------- phase 2: h2 = bnrelu(y) @ W2 + b2 --------
        const uint64_t dB2hi = make_desc(sb + P_A1HI);
        const uint64_t dB2lo = make_desc(sb + P_A1LO);

#define CPASYNC_B2_HALF(CH)                                                     \
    {   /* warps 4-7 only: 128 threads, 8 iters per precision */                \
        int kb_ = (CH) * 64;                                                    \
        _Pragma("unroll")                                                       \
        for (int it = 0; it < 8; it++) {                                        \
            int idx = (t - 128) + it * 128;                                     \
            int r_ = idx >> 3, kg_ = idx & 7;                                   \
            uint32_t so_ = SW128((uint32_t)(r_ * 128 + kg_ * 16));              \
            size_t bo_ = (size_t)r_ * 256 + kb_ + kg_ * 8;                      \
            CP_ASYNC16(sb + P_A1HI + so_, B2hi + bo_);                          \
            CP_ASYNC16(sb + P_A1LO + so_, B2lo + bo_);                          \
        }                                                                       \
        CP_COMMIT();                                                            \
        CP_WAIT0();                                                             \
    }
#define CPASYNC_B2_ALL(CH)                                                      \
    {   /* all 256 threads, 4 iters per precision */                            \
        int kb_ = (CH) * 64;                                                    \
        _Pragma("unroll")                                                       \
        for (int it = 0; it < 4; it++) {                                        \
            int idx = t + it * 256;                                             \
            int r_ = idx >> 3, kg_ = idx & 7;                                   \
            uint32_t so_ = SW128((uint32_t)(r_ * 128 + kg_ * 16));              \
            size_t bo_ = (size_t)r_ * 256 + kb_ + kg_ * 8;                      \
            CP_ASYNC16(sb + P_A1HI + so_, B2hi + bo_);                          \
            CP_ASYNC16(sb + P_A1LO + so_, B2lo + bo_);                          \
        }                                                                       \
        CP_COMMIT();                                                            \
        CP_WAIT0();                                                             \
    }
#define MMA2(SLOT, EN0)                                                         \
    if (wid == 0 && elect_one()) {                                              \
        uint64_t ah = make_desc(sb + P_B1HI + (SLOT) * 16384);                  \
        uint64_t al = make_desc(sb + P_B1LO + (SLOT) * 16384);                  \
        _Pragma("unroll")                                                       \
        for (int s = 0; s < 4; s++)                                             \
            mma_bf16_ss(tmem, ah + s * 2, dB2hi + s * 2, TG_IDESC,              \
                        ((EN0) && s == 0) ? 0u : 1u);                           \
        _Pragma("unroll")                                                       \
        for (int s = 0; s < 4; s++)                                             \
            mma_bf16_ss(tmem, ah + s * 2, dB2lo + s * 2, TG_IDESC, 1u);         \
        _Pragma("unroll")                                                       \
        for (int s = 0; s < 4; s++)                                             \
            mma_bf16_ss(tmem, al + s * 2, dB2hi + s * 2, TG_IDESC, 1u);         \
        TC_COMMIT(sb + P_MBAR);                                                 \
    }

#pragma unroll
        for (int half = 0; half < 2; half++) {
            // epilogue: y cols [half*128, half*128+128) -> A2 slots 0,1
            // warps 4-7 concurrently stage B2 chunk 2*half
            if (wid < 4) {
                int r = wid * 32 + lid;
#pragma unroll
                for (int p2 = 0; p2 < 2; p2++) {
                    int b0 = half * 4 + p2 * 2;     // 32-col block indices b0, b0+1
                    uint32_t r0[32], r1[32];
                    LDTM32(r0, tmem + b0 * 32);
                    LDTM32(r1, tmem + (b0 + 1) * 32);
                    TC_WAIT_LD();
                    float v[64];
#pragma unroll
                    for (int i = 0; i < 32; i++) {
                        int c0 = b0 * 32 + i, c1 = (b0 + 1) * 32 + i;
                        v[i]      = fmaxf(fmaf(__uint_as_float(r0[i]), sSc[c0], sSh[c0]), 0.f);
                        v[32 + i] = fmaxf(fmaf(__uint_as_float(r1[i]), sSc[c1], sSh[c1]), 0.f);
                    }
#pragma unroll
                    for (int bb = 0; bb < 2; bb++) {
                        int blk = b0 + bb;           // absolute 32-col block
                        int slot = (blk >> 1) & 1;
                        const float* vv = v + bb * 32;
#pragma unroll
                        for (int q = 0; q < 4; q++) {
                            uint32_t h[4], lo[4];
#pragma unroll
                            for (int p = 0; p < 4; p++) {
                                float a0 = vv[q * 8 + p * 2], a1 = vv[q * 8 + p * 2 + 1];
                                h[p] = pack_bf16x2(a0, a1);
                                __nv_bfloat162 hb = *reinterpret_cast<__nv_bfloat162*>(&h[p]);
                                float2 hr = __bfloat1622float2(hb);
                                lo[p] = pack_bf16x2(a0 - hr.x, a1 - hr.y);
                            }
                            uint32_t so = SW128((uint32_t)(r * 128 + (blk & 1) * 64 + q * 16));
                            *(uint4*)(smem + P_B1HI + slot * 16384 + so) = make_uint4(h[0], h[1], h[2], h[3]);
                            *(uint4*)(smem + P_B1LO + slot * 16384 + so) = make_uint4(lo[0], lo[1], lo[2], lo[3]);
                        }
                    }
                }
                TC_FENCE_BEFORE();
            } else {
                CPASYNC_B2_HALF(2 * half);
            }
            FENCE_ASYNC();
            __syncthreads();
            // round A: A2 slot0 x B2 chunk(2*half)
            MMA2(0, half == 0);
            MB_WAIT(sb + P_MBAR, pc & 1); pc++;
            // stage B2 chunk(2*half+1) (B2 buffer free now)
            CPASYNC_B2_ALL(2 * half + 1);
            FENCE_ASYNC();
            __syncthreads();
            // round B: A2 slot1 x B2 chunk(2*half+1)
            MMA2(1, false);
            MB_WAIT(sb + P_MBAR, pc & 1); pc++;
            TC_FENCE_AFTER();
        }

#undef CPASYNC_B2_HALF
#undef CPASYNC_B2_ALL
#undef MMA2

        // -------- final epilogue: h2 (tmem cols 0..127) --------
        for (int pr = 0; pr < 2; pr++) {
            if (wid < 4) {
                int r = wid * 32 + lid;
                int grow = bm + r;
                uint32_t r0[32], r1[32];
                LDTM32(r0, tmem + pr * 64);
                LDTM32(r1, tmem + pr * 64 + 32);
                TC_WAIT_LD();
                float v0[32], v1[32];
#pragma unroll
                for (int i = 0; i < 32; i++) {
                    v0[i] = __uint_as_float(r0[i]) + sB[pr * 64 + i];
                    v1[i] = __uint_as_float(r1[i]) + sB[pr * 64 + 32 + i];
                }
                if (grow < M) {
                    float* cp = C + (size_t)grow * 128 + pr * 64;
#pragma unroll
                    for (int q = 0; q < 8; q++) {
                        *(float4*)(cp + q * 4)      = *(float4*)(v0 + q * 4);
                        *(float4*)(cp + 32 + q * 4) = *(float4*)(v1 + q * 4);
                    }
                } else {
#pragma unroll
                    for (int i = 0; i < 32; i++) { v0[i] = 0.f; v1[i] = 0.f; }
                }
#pragma unroll
                for (int i = 0; i < 32; i++) {
                    statbuf[r * 66 + i]      = v0[i];
                    statbuf[r * 66 + 32 + i] = v1[i];
                }
            }
            __syncthreads();
            {
                int c = t & 63, h = t >> 6;
                float s = 0.f, q = 0.f;
#pragma unroll 8
                for (int rr = 0; rr < 32; rr++) {
                    float vv = statbuf[(h * 32 + rr) * 66 + c];
                    s += vv;
                    q = fmaf(vv, vv, q);
                }
                psum[h * 64 + c] = s;
                psq[h * 64 + c]  = q;
            }
            __syncthreads();
            if (t < 64) {
                ssl[pr * 64 + t] = psum[t] + psum[64 + t] + psum[128 + t] + psum[192 + t];
                sql[pr * 64 + t] = psq[t]  + psq[64 + t]  + psq[128 + t]  + psq[192 + t];
            }
            __syncthreads();
        }
        if (wid < 4) TC_FENCE_BEFORE();
        __syncthreads();
        if (t < 128) {
            atomicAdd(&g_ssum2[t], ssl[t]);
            atomicAdd(&g_ssq2[t],  sql[t]);
        }
    }

    __syncthreads();
    if (t == 0) MB_INVAL(sb + P_MBAR);
    if (wid == 0) TC_DEALLOC(tmem, 256);
}

// outer BN finalize: scale/shift for h2; zero both stats sets for next layer
__global__ void finalize_k(const float* __restrict__ gamma, const float* __restrict__ beta,
                           float invM) {
    int t = threadIdx.x;  // 256
    if (t < 128) {
        float m   = g_ssum2[t] * invM;
        float var = g_ssq2[t] * invM - m * m;
        float sc  = gamma[t] * rsqrtf(var + 1e-5f);
        g_scale[t] = sc;
        g_shift[t] = beta[t] - m * sc;
        g_ssum2[t] = 0.f;
        g_ssq2[t]  = 0.f;
    }
    g_ssum[t] = 0.f;
    g_ssq[t]  = 0.f;
}

// ---------------- readout pooling ----------------
__global__ void pool_k(const void* __restrict__ batch, int n) {
    long long t = (long long)blockIdx.x * blockDim.x + threadIdx.x;
    long long i = t >> 5;
    if (i >= n) return;
    int lane = (int)(t & 31);
    long long g;
    if (g_i64flag) g = ((const long long*)batch)[i];
    else           g = (long long)((const int*)batch)[i];
    int c = lane * 4;
    float4 v = ((const float4*)g_h2)[i * 32 + lane];
    float r0 = fmaxf(fmaf(v.x, g_scale[c + 0], g_shift[c + 0]), 0.f);
    float r1 = fmaxf(fmaf(v.y, g_scale[c + 1], g_shift[c + 1]), 0.f);
    float r2 = fmaxf(fmaf(v.z, g_scale[c + 2], g_shift[c + 2]), 0.f);
    float r3 = fmaxf(fmaf(v.w, g_scale[c + 3], g_shift[c + 3]), 0.f);
    float* ps = g_ps + g * 128 + c;
    asm volatile("red.global.add.v4.f32 [%0], {%1, %2, %3, %4};"
                 :: "l"(ps), "f"(r0), "f"(r1), "f"(r2), "f"(r3) : "memory");
    unsigned int* mx = (unsigned int*)(g_pmx + g * 128 + c);
    atomicMax(mx + 0, __float_as_uint(r0));
    atomicMax(mx + 1, __float_as_uint(r1));
    atomicMax(mx + 2, __float_as_uint(r2));
    atomicMax(mx + 3, __float_as_uint(r3));
    if (lane == 0) atomicAdd(&g_cnt[g], 1.0f);
}

// ---------------- classifier ----------------
__global__ void cgemm1_k(const float* __restrict__ cW1, const float* __restrict__ cb1) {
    int g = blockIdx.x;
    int j = threadIdx.x;  // 128
    __shared__ float z[384];
    float cnt = fmaxf(g_cnt[g], 1.0f);
    float sv = g_ps[g * 128 + j];
    z[j]       = sv;
    z[128 + j] = sv / cnt;
    z[256 + j] = g_pmx[g * 128 + j];
    __syncthreads();
    float acc = cb1[j];
#pragma unroll 8
    for (int k = 0; k < 384; k++)
        acc = fmaf(z[k], cW1[k * 128 + j], acc);
    g_z1[g * 128 + j] = acc;
}

__global__ void cstats_k(const float* __restrict__ cg, const float* __restrict__ cbeta) {
    int j = threadIdx.x;  // 128
    float s = 0.f, q = 0.f;
    for (int g = 0; g < GCNT; g++) {
        float v = g_z1[g * 128 + j];
        s += v; q += v * v;
    }
    float m   = s * (1.0f / GCNT);
    float var = q * (1.0f / GCNT) - m * m;
    float sc  = cg[j] * rsqrtf(var + 1e-5f);
    g_scale[j] = sc;
    g_shift[j] = cbeta[j] - m * sc;
}

__global__ void chead_k(const float* __restrict__ cW2, const float* __restrict__ cb2,
                        const float* __restrict__ cW3, const float* __restrict__ cb3,
                        float* __restrict__ out) {
    int g = blockIdx.x;
    int j = threadIdx.x;  // 64
    __shared__ float a[128];
    __shared__ float z2[64];
    for (int k = j; k < 128; k += 64)
        a[k] = fmaxf(fmaf(g_z1[g * 128 + k], g_scale[k], g_shift[k]), 0.f);
    __syncthreads();
    float acc = cb2[j];
#pragma unroll 8
    for (int k = 0; k < 128; k++)
        acc = fmaf(a[k], cW2[k * 64 + j], acc);
    z2[j] = fmaxf(acc, 0.f);
    __syncthreads();
    if (j < 2) {
        float o = cb3[j];
#pragma unroll 8
        for (int k = 0; k < 64; k++)
            o = fmaf(z2[k], cW3[k * 2 + j], o);
        out[g * 2 + j] = o;
    }
}

// ---------------- launcher ----------------
extern "C" void kernel_launch(void* const* d_in, const int* in_sizes, int n_in,
                              void* d_out, int out_size) {
    const float* x     = (const float*)d_in[0];
    const void*  ei    = d_in[1];
    const void*  batch = d_in[2];
    int base = (in_sizes[3] == 1) ? 4 : 3;
    const float* W1    = (const float*)d_in[base + 0];
    const float* b1    = (const float*)d_in[base + 1];
    const float* g1    = (const float*)d_in[base + 2];
    const float* be1   = (const float*)d_in[base + 3];
    const float* W2    = (const float*)d_in[base + 4];
    const float* b2    = (const float*)d_in[base + 5];
    const float* gbn   = (const float*)d_in[base + 6];
    const float* bbn   = (const float*)d_in[base + 7];
    const float* eps   = (const float*)d_in[base + 8];
    const float* cW1   = (const float*)d_in[base + 9];
    const float* cb1   = (const float*)d_in[base + 10];
    const float* cg    = (const float*)d_in[base + 11];
    const float* cbeta = (const float*)d_in[base + 12];
    const float* cW2   = (const float*)d_in[base + 13];
    const float* cb2   = (const float*)d_in[base + 14];
    const float* cW3   = (const float*)d_in[base + 15];
    const float* cb3   = (const float*)d_in[base + 16];

    int n = in_sizes[0] / 128;
    long long E = (long long)in_sizes[1] / 2;
    int n32 = n * 32;
    int nb = (n32 + 255) / 256;
    int gx = (n + 127) / 128;
    long long nwarp = (E + 3) / 4;
    int sblk = (int)((nwarp * 32 + 255) / 256);
    float invM = 1.0f / (float)n;

    static int smem_set = 0;
    if (!smem_set) {
        cudaFuncSetAttribute(pass_k<1>, cudaFuncAttributeMaxDynamicSharedMemorySize, P_SMEM);
        cudaFuncSetAttribute(pass_k<2>, cudaFuncAttributeMaxDynamicSharedMemorySize, P_SMEM);
        smem_set = 1;
    }

    float *p_hin, *p_h2;
    __nv_bfloat16 *p_b1hi, *p_b1lo, *p_b2hi, *p_b2lo;
    cudaGetSymbolAddress((void**)&p_hin, g_hin);
    cudaGetSymbolAddress((void**)&p_h2,  g_h2);
    cudaGetSymbolAddress((void**)&p_b1hi, g_b1hi);
    cudaGetSymbolAddress((void**)&p_b1lo, g_b1lo);
    cudaGetSymbolAddress((void**)&p_b2hi, g_b2hi);
    cudaGetSymbolAddress((void**)&p_b2lo, g_b2lo);

    detect_k<<<1, 1>>>((const unsigned int*)ei);
    wconv_k<<<(NLAYER * 256 * 128 + 255) / 256, 256>>>(W1, W2);
    prep0_k<<<nb, 256>>>((const float4*)x, eps, n32);

    for (int l = 0; l < 4; l++) {
        if (l > 0) {
            prep_k<<<nb, 256>>>(eps, l, n32);
            scatter_k<true><<<sblk, 256>>>(ei, p_h2, E);
        } else {
            scatter_k<false><<<sblk, 256>>>(ei, x, E);
        }
        pass_k<1><<<gx, 256, P_SMEM>>>(
            p_hin, p_b1hi + (size_t)l * 32768, p_b1lo + (size_t)l * 32768,
            p_b2hi + (size_t)l * 32768, p_b2lo + (size_t)l * 32768,
            b1 + l * 256, b2 + l * 128, g1 + l * 256, be1 + l * 256, invM,
            nullptr, n);
        pass_k<2><<<gx, 256, P_SMEM>>>(
            p_hin, p_b1hi + (size_t)l * 32768, p_b1lo + (size_t)l * 32768,
            p_b2hi + (size_t)l * 32768, p_b2lo + (size_t)l * 32768,
            b1 + l * 256, b2 + l * 128, g1 + l * 256, be1 + l * 256, invM,
            p_h2, n);
        finalize_k<<<1, 256>>>(gbn + l * 128, bbn + l * 128, invM);
    }

    pool_k<<<nb, 256>>>(batch, n);
    cgemm1_k<<<GCNT, 128>>>(cW1, cb1);
    cstats_k<<<1, 128>>>(cg, cbeta);
    chead_k<<<GCNT, 64>>>(cW2, cb2, cW3, cb3, (float*)d_out);
}

// round 10
// speedup vs baseline: 1.1890x; 1.0229x over previous
#include <cuda_runtime.h>
#include <cuda_bf16.h>
#include <cstdint>
#include <cstddef>

// Problem constants (fixed shapes)
#define NMAX 100000
#define EMAX 500000
#define GCNT 512
#define NLAYER 4

// tcgen05 only exists in the arch-specific (sm_103a) device pass.
#if defined(__CUDA_ARCH__) && defined(__CUDA_ARCH_FEAT_SM103_ALL)
#define HAS_TC 1
#else
#define HAS_TC 0
#endif

// ---------------- device scratch ----------------
__device__ float g_hin[NMAX * 128];
__device__ float g_h2 [NMAX * 128];
__device__ float g_ssum [256];
__device__ float g_ssq  [256];
__device__ float g_ssum2[128];
__device__ float g_ssq2 [128];
__device__ float g_scale[256];
__device__ float g_shift[256];
__device__ float g_ps [GCNT * 128];
__device__ float g_pmx[GCNT * 128];
__device__ float g_cnt[GCNT];
__device__ float g_z1 [GCNT * 128];
__device__ int   g_i64flag;

// CSR (built once per launch; edges fixed across layers)
__device__ int g_deg [NMAX];
__device__ int g_off [NMAX];
__device__ int g_cur [NMAX];
__device__ int g_csr [EMAX];
__device__ int g_bsum[128];
__device__ int g_bscn[128];

// pre-split weights, B layout: [layer][n(out)][k(in)] bf16, K-major rows
__device__ __nv_bfloat16 g_b1hi[NLAYER * 256 * 128];
__device__ __nv_bfloat16 g_b1lo[NLAYER * 256 * 128];
__device__ __nv_bfloat16 g_b2hi[NLAYER * 128 * 256];
__device__ __nv_bfloat16 g_b2lo[NLAYER * 128 * 256];

// ---------------- PTX helpers ----------------
__device__ __forceinline__ uint32_t smem_u32(const void* p) {
    uint32_t a;
    asm("{ .reg .u64 t; cvta.to.shared.u64 t, %1; cvt.u32.u64 %0, t; }" : "=r"(a) : "l"(p));
    return a;
}
__device__ __forceinline__ uint32_t elect_one() {
    uint32_t p;
    asm volatile("{ .reg .pred p; elect.sync _|p, 0xFFFFFFFF; selp.b32 %0, 1, 0, p; }" : "=r"(p));
    return p;
}
#define SW128(o) ((o) ^ (((o) >> 3) & 0x70))
static __device__ __forceinline__ uint64_t make_desc(uint32_t addr) {
    return ((uint64_t)2 << 61) | ((uint64_t)1 << 46) | ((uint64_t)64 << 32) |
           ((uint64_t)1 << 16) | ((uint64_t)(addr >> 4) & 0x3FFF);
}

#if HAS_TC
__device__ __forceinline__ void mma_bf16_ss(uint32_t d, uint64_t a, uint64_t b,
                                            uint32_t idesc, uint32_t en) {
    asm volatile(
        "{\n\t.reg .pred p;\n\tsetp.ne.u32 p, %4, 0;\n\t"
        "tcgen05.mma.cta_group::1.kind::f16 [%0], %1, %2, %3, {%5, %5, %5, %5}, p;\n\t}"
        :: "r"(d), "l"(a), "l"(b), "r"(idesc), "r"(en), "r"(0u) : "memory");
}
#define TC_ALLOC(sm, n)  asm volatile("tcgen05.alloc.cta_group::1.sync.aligned.shared::cta.b32 [%0], %1;" :: "r"(sm), "r"((uint32_t)(n)) : "memory")
#define TC_DEALLOC(t, n) asm volatile("tcgen05.dealloc.cta_group::1.sync.aligned.b32 %0, %1;" :: "r"(t), "r"((uint32_t)(n)))
#define TC_COMMIT(mb)    asm volatile("tcgen05.commit.cta_group::1.mbarrier::arrive::one.shared::cluster.b64 [%0];" :: "r"(mb) : "memory")
#define TC_FENCE_AFTER() asm volatile("tcgen05.fence::after_thread_sync;" ::: "memory")
#define TC_FENCE_BEFORE() asm volatile("tcgen05.fence::before_thread_sync;" ::: "memory")
#define TC_WAIT_LD()     asm volatile("tcgen05.wait::ld.sync.aligned;" ::: "memory")
#define LDTM32(r, a)                                                            \
    asm volatile("tcgen05.ld.sync.aligned.32x32b.x32.b32 "                      \
        "{%0,%1,%2,%3,%4,%5,%6,%7,%8,%9,%10,%11,%12,%13,%14,%15,"               \
        "%16,%17,%18,%19,%20,%21,%22,%23,%24,%25,%26,%27,%28,%29,%30,%31}, [%32];" \
        : "=r"((r)[0]),"=r"((r)[1]),"=r"((r)[2]),"=r"((r)[3]),                  \
          "=r"((r)[4]),"=r"((r)[5]),"=r"((r)[6]),"=r"((r)[7]),                  \
          "=r"((r)[8]),"=r"((r)[9]),"=r"((r)[10]),"=r"((r)[11]),                \
          "=r"((r)[12]),"=r"((r)[13]),"=r"((r)[14]),"=r"((r)[15]),              \
          "=r"((r)[16]),"=r"((r)[17]),"=r"((r)[18]),"=r"((r)[19]),              \
          "=r"((r)[20]),"=r"((r)[21]),"=r"((r)[22]),"=r"((r)[23]),              \
          "=r"((r)[24]),"=r"((r)[25]),"=r"((r)[26]),"=r"((r)[27]),              \
          "=r"((r)[28]),"=r"((r)[29]),"=r"((r)[30]),"=r"((r)[31])               \
        : "r"(a))
#define MB_WAIT(mb, par) do {                                                   \
    uint32_t _m = (mb), _p = (par), _d;                                         \
    asm volatile("{ .reg .pred p; mbarrier.try_wait.parity.acquire.cta.shared::cta.b64 p, [%1], %2; selp.b32 %0, 1, 0, p; }" \
                 : "=r"(_d) : "r"(_m), "r"(_p) : "memory");                     \
    if (!_d) {                                                                  \
        asm volatile("{ .reg .pred P1; W%=: mbarrier.try_wait.parity.acquire.cta.shared::cta.b64 P1, [%0], %1, 0x989680; @P1 bra.uni D%=; bra.uni W%=; D%=: }" \
                     :: "r"(_m), "r"(_p) : "memory");                           \
    }                                                                           \
} while (0)
#else
__device__ __forceinline__ void mma_bf16_ss(uint32_t, uint64_t, uint64_t, uint32_t, uint32_t) {}
#define TC_ALLOC(sm, n)   ((void)0)
#define TC_DEALLOC(t, n)  ((void)0)
#define TC_COMMIT(mb)     ((void)0)
#define TC_FENCE_AFTER()  ((void)0)
#define TC_FENCE_BEFORE() ((void)0)
#define TC_WAIT_LD()      ((void)0)
#define LDTM32(r, a)      do { _Pragma("unroll") for (int _i = 0; _i < 32; _i++) (r)[_i] = 0u; } while (0)
#define MB_WAIT(mb, par)  ((void)0)
#endif

#define MB_INIT(mb, c)   asm volatile("mbarrier.init.shared.b64 [%0], %1;" :: "r"(mb), "r"((uint32_t)(c)) : "memory")
#define MB_INVAL(mb)     asm volatile("mbarrier.inval.shared.b64 [%0];" :: "r"(mb) : "memory")
#define FENCE_ASYNC()    asm volatile("fence.proxy.async.shared::cta;" ::: "memory")
#define CP_ASYNC16(dst, src) asm volatile("cp.async.ca.shared.global [%0], [%1], 16;" :: "r"(dst), "l"(src) : "memory")
#define CP_COMMIT()      asm volatile("cp.async.commit_group;" ::: "memory")
#define CP_WAIT0()       asm volatile("cp.async.wait_group 0;" ::: "memory")

// ---------------- dtype detection ----------------
__global__ void detect_k(const unsigned int* __restrict__ e) {
    unsigned acc = 0;
    for (int i = 1; i < 128; i += 2) acc |= e[i];
    g_i64flag = (acc == 0u) ? 1 : 0;
}

// ---------------- weight split fp32 -> bf16 hi/lo ----------------
__global__ void wconv_k(const float* __restrict__ W1, const float* __restrict__ W2) {
    int i = blockIdx.x * 256 + threadIdx.x;
    const int tot = NLAYER * 256 * 128;
    if (i >= tot) return;
    int l = i / (256 * 128), rem = i % (256 * 128);
    {   // W1: [l][k(128)][n(256)] -> B1 [l][n][k]
        int n = rem / 128, k = rem % 128;
        float w = W1[l * 32768 + k * 256 + n];
        __nv_bfloat16 h = __float2bfloat16(w);
        g_b1hi[i] = h;
        g_b1lo[i] = __float2bfloat16(w - __bfloat162float(h));
    }
    {   // W2: [l][k(256)][n(128)] -> B2 [l][n][k]
        int n = rem / 256, k = rem % 256;
        float w = W2[l * 32768 + k * 128 + n];
        __nv_bfloat16 h = __float2bfloat16(w);
        g_b2hi[i] = h;
        g_b2lo[i] = __float2bfloat16(w - __bfloat162float(h));
    }
}

// ---------------- zero stats/pool/deg (grid-stride; covers n) ----------------
__global__ void zero_k(int n) {
    int tot = (n > GCNT * 128) ? n : GCNT * 128;
    for (int i = blockIdx.x * blockDim.x + threadIdx.x; i < tot;
         i += gridDim.x * blockDim.x) {
        if (i < 256) { g_ssum[i] = 0.f; g_ssq[i] = 0.f; }
        if (i < 128) { g_ssum2[i] = 0.f; g_ssq2[i] = 0.f; }
        if (i < GCNT * 128) { g_ps[i] = 0.f; g_pmx[i] = 0.f; }
        if (i < GCNT) g_cnt[i] = 0.f;
        if (i < n) g_deg[i] = 0;
    }
}

// ---------------- CSR build ----------------
__global__ void count_k(const void* __restrict__ ei, long long E) {
    long long e = (long long)blockIdx.x * blockDim.x + threadIdx.x;
    if (e >= E) return;
    int d;
    if (g_i64flag) d = (int)((const long long*)ei)[E + e];
    else           d = ((const int*)ei)[E + e];
    atomicAdd(&g_deg[d], 1);
}

// block sums over 1024-elem tiles
__global__ void scanA_k(int n) {
    __shared__ int sred[256];
    int blk = blockIdx.x, t = threadIdx.x;
    int base = blk * 1024 + t * 4;
    int s = 0;
#pragma unroll
    for (int j = 0; j < 4; j++) {
        int idx = base + j;
        if (idx < n) s += g_deg[idx];
    }
    sred[t] = s;
    __syncthreads();
    for (int o = 128; o > 0; o >>= 1) {
        if (t < o) sred[t] += sred[t + o];
        __syncthreads();
    }
    if (t == 0) g_bsum[blk] = sred[0];
}

__global__ void scanB_k(int nblk) {
    if (threadIdx.x == 0) {
        int run = 0;
        for (int i = 0; i < nblk; i++) { g_bscn[i] = run; run += g_bsum[i]; }
    }
}

// local exclusive scan + block offset -> g_off, g_cur
__global__ void scanC_k(int n) {
    __shared__ int sth[256];
    int blk = blockIdx.x, t = threadIdx.x;
    int base = blk * 1024 + t * 4;
    int v[4];
    int s = 0;
#pragma unroll
    for (int j = 0; j < 4; j++) {
        int idx = base + j;
        v[j] = (idx < n) ? g_deg[idx] : 0;
        s += v[j];
    }
    sth[t] = s;
    __syncthreads();
    for (int o = 1; o < 256; o <<= 1) {
        int add = (t >= o) ? sth[t - o] : 0;
        __syncthreads();
        sth[t] += add;
        __syncthreads();
    }
    int tpre = (t > 0 ? sth[t - 1] : 0) + g_bscn[blk];
#pragma unroll
    for (int j = 0; j < 4; j++) {
        int idx = base + j;
        if (idx < n) { g_off[idx] = tpre; g_cur[idx] = tpre; }
        tpre += v[j];
    }
}

__global__ void fill_k(const void* __restrict__ ei, long long E) {
    long long e = (long long)blockIdx.x * blockDim.x + threadIdx.x;
    if (e >= E) return;
    int s, d;
    if (g_i64flag) {
        const long long* p = (const long long*)ei;
        s = (int)p[e]; d = (int)p[E + e];
    } else {
        const int* p = (const int*)ei;
        s = p[e]; d = p[E + e];
    }
    int pos = atomicAdd(&g_cur[d], 1);
    if (pos < EMAX) g_csr[pos] = s;
}

// ---------------- CSR aggregation: hin[i] = (1+eps)*f(SRC[i]) + sum f(SRC[nbr]) ----
// warp per node; f = BN-relu (BN=true) or identity (l=0).
template<bool BN>
__global__ void __launch_bounds__(256) agg_k(
    const float* __restrict__ SRC, const float* __restrict__ epsp, int l, int n) {
    int node = (int)(((long long)blockIdx.x * blockDim.x + threadIdx.x) >> 5);
    int lane = threadIdx.x & 31;
    if (node >= n) return;
    float e = 1.0f + epsp[l];

    float sc0, sc1, sc2, sc3, sh0, sh1, sh2, sh3;
    if (BN) {
        int c = lane * 4;
        sc0 = g_scale[c]; sc1 = g_scale[c + 1]; sc2 = g_scale[c + 2]; sc3 = g_scale[c + 3];
        sh0 = g_shift[c]; sh1 = g_shift[c + 1]; sh2 = g_shift[c + 2]; sh3 = g_shift[c + 3];
    }
#define FBN(v)                                                                   \
    if (BN) {                                                                    \
        v.x = fmaxf(fmaf(v.x, sc0, sh0), 0.f);                                   \
        v.y = fmaxf(fmaf(v.y, sc1, sh1), 0.f);                                   \
        v.z = fmaxf(fmaf(v.z, sc2, sh2), 0.f);                                   \
        v.w = fmaxf(fmaf(v.w, sc3, sh3), 0.f);                                   \
    }

    int beg = g_off[node];
    int deg = g_deg[node];

    float4 self = ((const float4*)SRC)[(size_t)node * 32 + lane];
    FBN(self);
    float4 a0 = make_float4(self.x * e, self.y * e, self.z * e, self.w * e);
    float4 a1 = make_float4(0.f, 0.f, 0.f, 0.f);
    float4 a2 = make_float4(0.f, 0.f, 0.f, 0.f);
    float4 a3 = make_float4(0.f, 0.f, 0.f, 0.f);

    int i = 0;
    for (; i + 4 <= deg; i += 4) {
        int s0 = g_csr[beg + i];
        int s1 = g_csr[beg + i + 1];
        int s2 = g_csr[beg + i + 2];
        int s3 = g_csr[beg + i + 3];
        float4 v0 = ((const float4*)SRC)[(size_t)s0 * 32 + lane];
        float4 v1 = ((const float4*)SRC)[(size_t)s1 * 32 + lane];
        float4 v2 = ((const float4*)SRC)[(size_t)s2 * 32 + lane];
        float4 v3 = ((const float4*)SRC)[(size_t)s3 * 32 + lane];
        FBN(v0); FBN(v1); FBN(v2); FBN(v3);
        a0.x += v0.x; a0.y += v0.y; a0.z += v0.z; a0.w += v0.w;
        a1.x += v1.x; a1.y += v1.y; a1.z += v1.z; a1.w += v1.w;
        a2.x += v2.x; a2.y += v2.y; a2.z += v2.z; a2.w += v2.w;
        a3.x += v3.x; a3.y += v3.y; a3.z += v3.z; a3.w += v3.w;
    }
    for (; i < deg; i++) {
        int s0 = g_csr[beg + i];
        float4 v0 = ((const float4*)SRC)[(size_t)s0 * 32 + lane];
        FBN(v0);
        a1.x += v0.x; a1.y += v0.y; a1.z += v0.z; a1.w += v0.w;
    }
#undef FBN
    float4 r;
    r.x = (a0.x + a1.x) + (a2.x + a3.x);
    r.y = (a0.y + a1.y) + (a2.y + a3.y);
    r.z = (a0.z + a1.z) + (a2.z + a3.z);
    r.w = (a0.w + a1.w) + (a2.w + a3.w);
    ((float4*)g_hin)[(size_t)node * 32 + lane] = r;
}

// ================== fused layer kernel (unchanged from R8) ==================
#define P_PTR   0
#define P_MBAR  16
#define P_SC    32
#define P_SH    1056
#define P_SB    2080
#define P_SSL   3104
#define P_SQL   4128
#define P_PSUM  5152
#define P_PSQ   6176
#define P_A1HI  8192
#define P_A1LO  24576
#define P_B1HI  40960
#define P_B1LO  73728
#define P_SMEM  106496
#define TG_IDESC 0x8200490u

__device__ __forceinline__ uint32_t pack_bf16x2(float a, float b) {
    __nv_bfloat162 h = __float22bfloat162_rn(make_float2(a, b));
    return *reinterpret_cast<uint32_t*>(&h);
}

template<int PASS>
__global__ void __launch_bounds__(256, 2) pass_k(
    const float* __restrict__ A,
    const __nv_bfloat16* __restrict__ B1hi, const __nv_bfloat16* __restrict__ B1lo,
    const __nv_bfloat16* __restrict__ B2hi, const __nv_bfloat16* __restrict__ B2lo,
    const float* __restrict__ b1, const float* __restrict__ b2,
    const float* __restrict__ g1, const float* __restrict__ be1, float invM,
    float* __restrict__ C, int M)
{
    extern __shared__ char smem[];
    const uint32_t sb = smem_u32(smem);
    const int t = threadIdx.x, wid = t >> 5, lid = t & 31;
    const int bm = blockIdx.x * 128;
    float* sSc = reinterpret_cast<float*>(smem + P_SC);
    float* sSh = reinterpret_cast<float*>(smem + P_SH);
    float* sB  = reinterpret_cast<float*>(smem + P_SB);
    float* ssl = reinterpret_cast<float*>(smem + P_SSL);
    float* sql = reinterpret_cast<float*>(smem + P_SQL);
    float* psum = reinterpret_cast<float*>(smem + P_PSUM);
    float* psq  = reinterpret_cast<float*>(smem + P_PSQ);
    float* statbuf = reinterpret_cast<float*>(smem + P_B1HI);

    if (wid == 0) TC_ALLOC(sb + P_PTR, 256);
    if (t == 0) MB_INIT(sb + P_MBAR, 1);
    if (PASS == 1) {
        sB[t] = b1[t];
    } else {
        float m   = g_ssum[t] * invM;
        float var = g_ssq[t] * invM - m * m;
        float sc  = g1[t] * rsqrtf(var + 1e-5f);
        sSc[t] = sc;
        sSh[t] = fmaf(b1[t] - m, sc, be1[t]);
        if (t < 128) sB[t] = b2[t];
    }
    __syncthreads();
    uint32_t tmem;
    asm volatile("ld.shared.b32 %0, [%1];" : "=r"(tmem) : "r"(sb + P_PTR));

    const uint64_t dA1hi = make_desc(sb + P_A1HI);
    const uint64_t dA1lo = make_desc(sb + P_A1LO);
    const uint64_t dB1hi = make_desc(sb + P_B1HI);
    const uint64_t dB1lo = make_desc(sb + P_B1LO);

    float4 apf[8];
    int pc = 0;

#define PREF_A1(CH)                                                             \
    {                                                                           \
        int kb_ = (CH) * 64;                                                    \
        _Pragma("unroll")                                                       \
        for (int it = 0; it < 4; it++) {                                        \
            int idx = t + it * 256;                                             \
            int r_ = idx >> 3, kg_ = idx & 7;                                   \
            int grow_ = bm + r_;                                                \
            if (grow_ < M) {                                                    \
                const float* ap = A + (size_t)grow_ * 128 + kb_ + kg_ * 8;      \
                apf[it * 2]     = *(const float4*)ap;                           \
                apf[it * 2 + 1] = *(const float4*)(ap + 4);                     \
            } else {                                                            \
                apf[it * 2] = apf[it * 2 + 1] = make_float4(0.f, 0.f, 0.f, 0.f); \
            }                                                                   \
        }                                                                       \
    }
#define STORE_A1()                                                              \
    {                                                                           \
        _Pragma("unroll")                                                       \
        for (int it = 0; it < 4; it++) {                                        \
            int idx = t + it * 256;                                             \
            int r_ = idx >> 3, kg_ = idx & 7;                                   \
            uint32_t so_ = SW128((uint32_t)(r_ * 128 + kg_ * 16));              \
            float f[8];                                                         \
            *(float4*)(f)     = apf[it * 2];                                    \
            *(float4*)(f + 4) = apf[it * 2 + 1];                                \
            uint32_t h[4], lo[4];                                               \
            _Pragma("unroll")                                                   \
            for (int j = 0; j < 4; j++) {                                       \
                h[j] = pack_bf16x2(f[2 * j], f[2 * j + 1]);                     \
                __nv_bfloat162 hb = *reinterpret_cast<__nv_bfloat162*>(&h[j]);  \
                float2 hr = __bfloat1622float2(hb);                             \
                lo[j] = pack_bf16x2(f[2 * j] - hr.x, f[2 * j + 1] - hr.y);      \
            }                                                                   \
            *(uint4*)(smem + P_A1HI + so_) = make_uint4(h[0], h[1], h[2], h[3]); \
            *(uint4*)(smem + P_A1LO + so_) = make_uint4(lo[0], lo[1], lo[2], lo[3]); \
        }                                                                       \
    }
#define CPASYNC_B1(CH)                                                          \
    {                                                                           \
        int kb_ = (CH) * 64;                                                    \
        _Pragma("unroll")                                                       \
        for (int it = 0; it < 8; it++) {                                        \
            int idx = t + it * 256;                                             \
            int r_ = idx >> 3, kg_ = idx & 7;                                   \
            uint32_t so_ = SW128((uint32_t)(r_ * 128 + kg_ * 16));              \
            size_t bo_ = (size_t)r_ * 128 + kb_ + kg_ * 8;                      \
            CP_ASYNC16(sb + P_B1HI + so_, B1hi + bo_);                          \
            CP_ASYNC16(sb + P_B1LO + so_, B1lo + bo_);                          \
        }                                                                       \
        CP_COMMIT();                                                            \
    }
#define MMA1_CHUNK(CH)                                                          \
    if (wid == 0 && elect_one()) {                                              \
        _Pragma("unroll")                                                       \
        for (int T = 0; T < 2; T++) {                                           \
            uint64_t bh = dB1hi + T * 1024;                                     \
            uint64_t bl = dB1lo + T * 1024;                                     \
            uint32_t dt = tmem + T * 128;                                       \
            _Pragma("unroll")                                                   \
            for (int s = 0; s < 4; s++)                                         \
                mma_bf16_ss(dt, dA1hi + s * 2, bh + s * 2, TG_IDESC,            \
                            ((CH) == 0 && s == 0) ? 0u : 1u);                   \
            _Pragma("unroll")                                                   \
            for (int s = 0; s < 4; s++)                                         \
                mma_bf16_ss(dt, dA1hi + s * 2, bl + s * 2, TG_IDESC, 1u);       \
            _Pragma("unroll")                                                   \
            for (int s = 0; s < 4; s++)                                         \
                mma_bf16_ss(dt, dA1lo + s * 2, bh + s * 2, TG_IDESC, 1u);       \
        }                                                                       \
        TC_COMMIT(sb + P_MBAR);                                                 \
    }

    PREF_A1(0);
    CPASYNC_B1(0);
    STORE_A1();
    CP_WAIT0();
    FENCE_ASYNC();
    __syncthreads();
    MMA1_CHUNK(0);
    PREF_A1(1);
    MB_WAIT(sb + P_MBAR, pc & 1); pc++;
    CPASYNC_B1(1);
    STORE_A1();
    CP_WAIT0();
    FENCE_ASYNC();
    __syncthreads();
    MMA1_CHUNK(1);
    MB_WAIT(sb + P_MBAR, pc & 1); pc++;
    TC_FENCE_AFTER();

#undef PREF_A1
#undef STORE_A1
#undef CPASYNC_B1
#undef MMA1_CHUNK

    if (PASS == 1) {
        for (int pr = 0; pr < 4; pr++) {
            if (wid < 4) {
                int r = wid * 32 + lid;
                int grow = bm + r;
                uint32_t r0[32], r1[32];
                LDTM32(r0, tmem + pr * 64);
                LDTM32(r1, tmem + pr * 64 + 32);
                TC_WAIT_LD();
                float v0[32], v1[32];
#pragma unroll
                for (int i = 0; i < 32; i++) {
                    v0[i] = (grow < M) ? __uint_as_float(r0[i]) + sB[pr * 64 + i]      : 0.f;
                    v1[i] = (grow < M) ? __uint_as_float(r1[i]) + sB[pr * 64 + 32 + i] : 0.f;
                }
#pragma unroll
                for (int i = 0; i < 32; i++) {
                    statbuf[r * 66 + i]      = v0[i];
                    statbuf[r * 66 + 32 + i] = v1[i];
                }
            }
            __syncthreads();
            {
                int c = t & 63, h = t >> 6;
                float s = 0.f, q = 0.f;
#pragma unroll 8
                for (int rr = 0; rr < 32; rr++) {
                    float v = statbuf[(h * 32 + rr) * 66 + c];
                    s += v;
                    q = fmaf(v, v, q);
                }
                psum[h * 64 + c] = s;
                psq[h * 64 + c]  = q;
            }
            __syncthreads();
            if (t < 64) {
                ssl[pr * 64 + t] = psum[t] + psum[64 + t] + psum[128 + t] + psum[192 + t];
                sql[pr * 64 + t] = psq[t]  + psq[64 + t]  + psq[128 + t]  + psq[192 + t];
            }
            __syncthreads();
        }
        if (wid < 4) TC_FENCE_BEFORE();
        __syncthreads();
        atomicAdd(&g_ssum[t], ssl[t]);
        atomicAdd(&g_ssq[t],  sql[t]);
    } else {
        const uint64_t dB2hi = make_desc(sb + P_A1HI);
        const uint64_t dB2lo = make_desc(sb + P_A1LO);

#define CPASYNC_B2_HALF(CH)                                                     \
    {                                                                           \
        int kb_ = (CH) * 64;                                                    \
        _Pragma("unroll")                                                       \
        for (int it = 0; it < 8; it++) {                                        \
            int idx = (t - 128) + it * 128;                                     \
            int r_ = idx >> 3, kg_ = idx & 7;                                   \
            uint32_t so_ = SW128((uint32_t)(r_ * 128 + kg_ * 16));              \
            size_t bo_ = (size_t)r_ * 256 + kb_ + kg_ * 8;                      \
            CP_ASYNC16(sb + P_A1HI + so_, B2hi + bo_);                          \
            CP_ASYNC16(sb + P_A1LO + so_, B2lo + bo_);                          \
        }                                                                       \
        CP_COMMIT();                                                            \
        CP_WAIT0();                                                             \
    }
#define CPASYNC_B2_ALL(CH)                                                      \
    {                                                                           \
        int kb_ = (CH) * 64;                                                    \
        _Pragma("unroll")                                                       \
        for (int it = 0; it < 4; it++) {                                        \
            int idx = t + it * 256;                                             \
            int r_ = idx >> 3, kg_ = idx & 7;                                   \
            uint32_t so_ = SW128((uint32_t)(r_ * 128 + kg_ * 16));              \
            size_t bo_ = (size_t)r_ * 256 + kb_ + kg_ * 8;                      \
            CP_ASYNC16(sb + P_A1HI + so_, B2hi + bo_);                          \
            CP_ASYNC16(sb + P_A1LO + so_, B2lo + bo_);                          \
        }                                                                       \
        CP_COMMIT();                                                            \
        CP_WAIT0();                                                             \
    }
#define MMA2(SLOT, EN0)                                                         \
    if (wid == 0 && elect_one()) {                                              \
        uint64_t ah = make_desc(sb + P_B1HI + (SLOT) * 16384);                  \
        uint64_t al = make_desc(sb + P_B1LO + (SLOT) * 16384);                  \
        _Pragma("unroll")                                                       \
        for (int s = 0; s < 4; s++)                                             \
            mma_bf16_ss(tmem, ah + s * 2, dB2hi + s * 2, TG_IDESC,              \
                        ((EN0) && s == 0) ? 0u : 1u);                           \
        _Pragma("unroll")                                                       \
        for (int s = 0; s < 4; s++)                                             \
            mma_bf16_ss(tmem, ah + s * 2, dB2lo + s * 2, TG_IDESC, 1u);         \
        _Pragma("unroll")                                                       \
        for (int s = 0; s < 4; s++)                                             \
            mma_bf16_ss(tmem, al + s * 2, dB2hi + s * 2, TG_IDESC, 1u);         \
        TC_COMMIT(sb + P_MBAR);                                                 \
    }

#pragma unroll
        for (int half = 0; half < 2; half++) {
            if (wid < 4) {
                int r = wid * 32 + lid;
#pragma unroll
                for (int p2 = 0; p2 < 2; p2++) {
                    int b0 = half * 4 + p2 * 2;
                    uint32_t r0[32], r1[32];
                    LDTM32(r0, tmem + b0 * 32);
                    LDTM32(r1, tmem + (b0 + 1) * 32);
                    TC_WAIT_LD();
                    float v[64];
#pragma unroll
                    for (int i = 0; i < 32; i++) {
                        int c0 = b0 * 32 + i, c1 = (b0 + 1) * 32 + i;
                        v[i]      = fmaxf(fmaf(__uint_as_float(r0[i]), sSc[c0], sSh[c0]), 0.f);
                        v[32 + i] = fmaxf(fmaf(__uint_as_float(r1[i]), sSc[c1], sSh[c1]), 0.f);
                    }
#pragma unroll
                    for (int bb = 0; bb < 2; bb++) {
                        int blk = b0 + bb;
                        int slot = (blk >> 1) & 1;
                        const float* vv = v + bb * 32;
#pragma unroll
                        for (int q = 0; q < 4; q++) {
                            uint32_t h[4], lo[4];
#pragma unroll
                            for (int p = 0; p < 4; p++) {
                                float a0 = vv[q * 8 + p * 2], a1 = vv[q * 8 + p * 2 + 1];
                                h[p] = pack_bf16x2(a0, a1);
                                __nv_bfloat162 hb = *reinterpret_cast<__nv_bfloat162*>(&h[p]);
                                float2 hr = __bfloat1622float2(hb);
                                lo[p] = pack_bf16x2(a0 - hr.x, a1 - hr.y);
                            }
                            uint32_t so = SW128((uint32_t)(r * 128 + (blk & 1) * 64 + q * 16));
                            *(uint4*)(smem + P_B1HI + slot * 16384 + so) = make_uint4(h[0], h[1], h[2], h[3]);
                            *(uint4*)(smem + P_B1LO + slot * 16384 + so) = make_uint4(lo[0], lo[1], lo[2], lo[3]);
                        }
                    }
                }
                TC_FENCE_BEFORE();
            } else {
                CPASYNC_B2_HALF(2 * half);
            }
            FENCE_ASYNC();
            __syncthreads();
            MMA2(0, half == 0);
            MB_WAIT(sb + P_MBAR, pc & 1); pc++;
            CPASYNC_B2_ALL(2 * half + 1);
            FENCE_ASYNC();
            __syncthreads();
            MMA2(1, false);
            MB_WAIT(sb + P_MBAR, pc & 1); pc++;
            TC_FENCE_AFTER();
        }

#undef CPASYNC_B2_HALF
#undef CPASYNC_B2_ALL
#undef MMA2

        for (int pr = 0; pr < 2; pr++) {
            if (wid < 4) {
                int r = wid * 32 + lid;
                int grow = bm + r;
                uint32_t r0[32], r1[32];
                LDTM32(r0, tmem + pr * 64);
                LDTM32(r1, tmem + pr * 64 + 32);
                TC_WAIT_LD();
                float v0[32], v1[32];
#pragma unroll
                for (int i = 0; i < 32; i++) {
                    v0[i] = __uint_as_float(r0[i]) + sB[pr * 64 + i];
                    v1[i] = __uint_as_float(r1[i]) + sB[pr * 64 + 32 + i];
                }
                if (grow < M) {
                    float* cp = C + (size_t)grow * 128 + pr * 64;
#pragma unroll
                    for (int q = 0; q < 8; q++) {
                        *(float4*)(cp + q * 4)      = *(float4*)(v0 + q * 4);
                        *(float4*)(cp + 32 + q * 4) = *(float4*)(v1 + q * 4);
                    }
                } else {
#pragma unroll
                    for (int i = 0; i < 32; i++) { v0[i] = 0.f; v1[i] = 0.f; }
                }
#pragma unroll
                for (int i = 0; i < 32; i++) {
                    statbuf[r * 66 + i]      = v0[i];
                    statbuf[r * 66 + 32 + i] = v1[i];
                }
            }
            __syncthreads();
            {
                int c = t & 63, h = t >> 6;
                float s = 0.f, q = 0.f;
#pragma unroll 8
                for (int rr = 0; rr < 32; rr++) {
                    float vv = statbuf[(h * 32 + rr) * 66 + c];
                    s += vv;
                    q = fmaf(vv, vv, q);
                }
                psum[h * 64 + c] = s;
                psq[h * 64 + c]  = q;
            }
            __syncthreads();
            if (t < 64) {
                ssl[pr * 64 + t] = psum[t] + psum[64 + t] + psum[128 + t] + psum[192 + t];
                sql[pr * 64 + t] = psq[t]  + psq[64 + t]  + psq[128 + t]  + psq[192 + t];
            }
            __syncthreads();
        }
        if (wid < 4) TC_FENCE_BEFORE();
        __syncthreads();
        if (t < 128) {
            atomicAdd(&g_ssum2[t], ssl[t]);
            atomicAdd(&g_ssq2[t],  sql[t]);
        }
    }

    __syncthreads();
    if (t == 0) MB_INVAL(sb + P_MBAR);
    if (wid == 0) TC_DEALLOC(tmem, 256);
}

// outer BN finalize
__global__ void finalize_k(const float* __restrict__ gamma, const float* __restrict__ beta,
                           float invM) {
    int t = threadIdx.x;
    if (t < 128) {
        float m   = g_ssum2[t] * invM;
        float var = g_ssq2[t] * invM - m * m;
        float sc  = gamma[t] * rsqrtf(var + 1e-5f);
        g_scale[t] = sc;
        g_shift[t] = beta[t] - m * sc;
        g_ssum2[t] = 0.f;
        g_ssq2[t]  = 0.f;
    }
    g_ssum[t] = 0.f;
    g_ssq[t]  = 0.f;
}

// ---------------- readout pooling ----------------
__global__ void pool_k(const void* __restrict__ batch, int n) {
    long long t = (long long)blockIdx.x * blockDim.x + threadIdx.x;
    long long i = t >> 5;
    if (i >= n) return;
    int lane = (int)(t & 31);
    long long g;
    if (g_i64flag) g = ((const long long*)batch)[i];
    else           g = (long long)((const int*)batch)[i];
    int c = lane * 4;
    float4 v = ((const float4*)g_h2)[i * 32 + lane];
    float r0 = fmaxf(fmaf(v.x, g_scale[c + 0], g_shift[c + 0]), 0.f);
    float r1 = fmaxf(fmaf(v.y, g_scale[c + 1], g_shift[c + 1]), 0.f);
    float r2 = fmaxf(fmaf(v.z, g_scale[c + 2], g_shift[c + 2]), 0.f);
    float r3 = fmaxf(fmaf(v.w, g_scale[c + 3], g_shift[c + 3]), 0.f);
    float* ps = g_ps + g * 128 + c;
    asm volatile("red.global.add.v4.f32 [%0], {%1, %2, %3, %4};"
                 :: "l"(ps), "f"(r0), "f"(r1), "f"(r2), "f"(r3) : "memory");
    unsigned int* mx = (unsigned int*)(g_pmx + g * 128 + c);
    atomicMax(mx + 0, __float_as_uint(r0));
    atomicMax(mx + 1, __float_as_uint(r1));
    atomicMax(mx + 2, __float_as_uint(r2));
    atomicMax(mx + 3, __float_as_uint(r3));
    if (lane == 0) atomicAdd(&g_cnt[g], 1.0f);
}

// ---------------- classifier ----------------
__global__ void cgemm1_k(const float* __restrict__ cW1, const float* __restrict__ cb1) {
    int g = blockIdx.x;
    int j = threadIdx.x;
    __shared__ float z[384];
    float cnt = fmaxf(g_cnt[g], 1.0f);
    float sv = g_ps[g * 128 + j];
    z[j]       = sv;
    z[128 + j] = sv / cnt;
    z[256 + j] = g_pmx[g * 128 + j];
    __syncthreads();
    float acc = cb1[j];
#pragma unroll 8
    for (int k = 0; k < 384; k++)
        acc = fmaf(z[k], cW1[k * 128 + j], acc);
    g_z1[g * 128 + j] = acc;
}

__global__ void cstats_k(const float* __restrict__ cg, const float* __restrict__ cbeta) {
    int j = threadIdx.x;
    float s = 0.f, q = 0.f;
    for (int g = 0; g < GCNT; g++) {
        float v = g_z1[g * 128 + j];
        s += v; q += v * v;
    }
    float m   = s * (1.0f / GCNT);
    float var = q * (1.0f / GCNT) - m * m;
    float sc  = cg[j] * rsqrtf(var + 1e-5f);
    g_scale[j] = sc;
    g_shift[j] = cbeta[j] - m * sc;
}

__global__ void chead_k(const float* __restrict__ cW2, const float* __restrict__ cb2,
                        const float* __restrict__ cW3, const float* __restrict__ cb3,
                        float* __restrict__ out) {
    int g = blockIdx.x;
    int j = threadIdx.x;
    __shared__ float a[128];
    __shared__ float z2[64];
    for (int k = j; k < 128; k += 64)
        a[k] = fmaxf(fmaf(g_z1[g * 128 + k], g_scale[k], g_shift[k]), 0.f);
    __syncthreads();
    float acc = cb2[j];
#pragma unroll 8
    for (int k = 0; k < 128; k++)
        acc = fmaf(a[k], cW2[k * 64 + j], acc);
    z2[j] = fmaxf(acc, 0.f);
    __syncthreads();
    if (j < 2) {
        float o = cb3[j];
#pragma unroll 8
        for (int k = 0; k < 64; k++)
            o = fmaf(z2[k], cW3[k * 2 + j], o);
        out[g * 2 + j] = o;
    }
}

// ---------------- launcher ----------------
extern "C" void kernel_launch(void* const* d_in, const int* in_sizes, int n_in,
                              void* d_out, int out_size) {
    const float* x     = (const float*)d_in[0];
    const void*  ei    = d_in[1];
    const void*  batch = d_in[2];
    int base = (in_sizes[3] == 1) ? 4 : 3;
    const float* W1    = (const float*)d_in[base + 0];
    const float* b1    = (const float*)d_in[base + 1];
    const float* g1    = (const float*)d_in[base + 2];
    const float* be1   = (const float*)d_in[base + 3];
    const float* W2    = (const float*)d_in[base + 4];
    const float* b2    = (const float*)d_in[base + 5];
    const float* gbn   = (const float*)d_in[base + 6];
    const float* bbn   = (const float*)d_in[base + 7];
    const float* eps   = (const float*)d_in[base + 8];
    const float* cW1   = (const float*)d_in[base + 9];
    const float* cb1   = (const float*)d_in[base + 10];
    const float* cg    = (const float*)d_in[base + 11];
    const float* cbeta = (const float*)d_in[base + 12];
    const float* cW2   = (const float*)d_in[base + 13];
    const float* cb2   = (const float*)d_in[base + 14];
    const float* cW3   = (const float*)d_in[base + 15];
    const float* cb3   = (const float*)d_in[base + 16];

    int n = in_sizes[0] / 128;
    long long E = (long long)in_sizes[1] / 2;
    int n32 = n * 32;
    int nb = (n32 + 255) / 256;
    int gx = (n + 127) / 128;
    int eblk = (int)((E + 255) / 256);
    int nscan = (n + 1023) / 1024;
    int ablk = (n * 32 + 255) / 256;
    float invM = 1.0f / (float)n;

    static int smem_set = 0;
    if (!smem_set) {
        cudaFuncSetAttribute(pass_k<1>, cudaFuncAttributeMaxDynamicSharedMemorySize, P_SMEM);
        cudaFuncSetAttribute(pass_k<2>, cudaFuncAttributeMaxDynamicSharedMemorySize, P_SMEM);
        smem_set = 1;
    }

    float *p_hin, *p_h2;
    __nv_bfloat16 *p_b1hi, *p_b1lo, *p_b2hi, *p_b2lo;
    cudaGetSymbolAddress((void**)&p_hin, g_hin);
    cudaGetSymbolAddress((void**)&p_h2,  g_h2);
    cudaGetSymbolAddress((void**)&p_b1hi, g_b1hi);
    cudaGetSymbolAddress((void**)&p_b1lo, g_b1lo);
    cudaGetSymbolAddress((void**)&p_b2hi, g_b2hi);
    cudaGetSymbolAddress((void**)&p_b2lo, g_b2lo);

    detect_k<<<1, 1>>>((const unsigned int*)ei);
    wconv_k<<<(NLAYER * 256 * 128 + 255) / 256, 256>>>(W1, W2);
    zero_k<<<512, 256>>>(n);

    // CSR build (once; edges shared by all layers)
    count_k<<<eblk, 256>>>(ei, E);
    scanA_k<<<nscan, 256>>>(n);
    scanB_k<<<1, 32>>>(nscan);
    scanC_k<<<nscan, 256>>>(n);
    fill_k<<<eblk, 256>>>(ei, E);

    for (int l = 0; l < 4; l++) {
        if (l == 0) agg_k<false><<<ablk, 256>>>(x, eps, l, n);
        else        agg_k<true><<<ablk, 256>>>(p_h2, eps, l, n);

        pass_k<1><<<gx, 256, P_SMEM>>>(
            p_hin, p_b1hi + (size_t)l * 32768, p_b1lo + (size_t)l * 32768,
            p_b2hi + (size_t)l * 32768, p_b2lo + (size_t)l * 32768,
            b1 + l * 256, b2 + l * 128, g1 + l * 256, be1 + l * 256, invM,
            nullptr, n);
        pass_k<2><<<gx, 256, P_SMEM>>>(
            p_hin, p_b1hi + (size_t)l * 32768, p_b1lo + (size_t)l * 32768,
            p_b2hi + (size_t)l * 32768, p_b2lo + (size_t)l * 32768,
            b1 + l * 256, b2 + l * 128, g1 + l * 256, be1 + l * 256, invM,
            p_h2, n);
        finalize_k<<<1, 256>>>(gbn + l * 128, bbn + l * 128, invM);
    }

    pool_k<<<nb, 256>>>(batch, n);
    cgemm1_k<<<GCNT, 128>>>(cW1, cb1);
    cstats_k<<<1, 128>>>(cg, cbeta);
    chead_k<<<GCNT, 64>>>(cW2, cb2, cW3, cb3, (float*)d_out);
}

// round 11
// speedup vs baseline: 1.2479x; 1.0495x over previous
#include <cuda_runtime.h>
#include <cuda_bf16.h>
#include <cstdint>
#include <cstddef>

// Problem constants (fixed shapes)
#define NMAX 100000
#define EMAX 500000
#define GCNT 512
#define NLAYER 4
#define NTILE ((NMAX + 127) / 128)   // 782

// tcgen05 only exists in the arch-specific (sm_103a) device pass.
#if defined(__CUDA_ARCH__) && defined(__CUDA_ARCH_FEAT_SM103_ALL)
#define HAS_TC 1
#else
#define HAS_TC 0
#endif

// ---------------- device scratch ----------------
__device__ float g_h2 [NMAX * 128];
// aggregated layer input, pre-split bf16 hi/lo, pre-swizzled smem image:
// [tile][chunk(2)][16KB image]  where image[SW128(row*128 + kg*16)]
__device__ uint8_t g_ahi[(size_t)NTILE * 32768];
__device__ uint8_t g_alo[(size_t)NTILE * 32768];
__device__ float g_ssum [256];
__device__ float g_ssq  [256];
__device__ float g_ssum2[128];
__device__ float g_ssq2 [128];
__device__ float g_scale[256];
__device__ float g_shift[256];
__device__ float g_ps [GCNT * 128];
__device__ float g_pmx[GCNT * 128];
__device__ float g_cnt[GCNT];
__device__ float g_z1 [GCNT * 128];
__device__ int   g_i64flag;

// CSR (built once per launch; edges fixed across layers)
__device__ int g_deg [NMAX];
__device__ int g_off [NMAX];
__device__ int g_cur [NMAX];
__device__ int g_csr [EMAX];
__device__ int g_bsum[128];
__device__ int g_bscn[128];

// pre-split weights, B layout: [layer][n(out)][k(in)] bf16, K-major rows
__device__ __nv_bfloat16 g_b1hi[NLAYER * 256 * 128];
__device__ __nv_bfloat16 g_b1lo[NLAYER * 256 * 128];
__device__ __nv_bfloat16 g_b2hi[NLAYER * 128 * 256];
__device__ __nv_bfloat16 g_b2lo[NLAYER * 128 * 256];

// ---------------- PTX helpers ----------------
__device__ __forceinline__ uint32_t smem_u32(const void* p) {
    uint32_t a;
    asm("{ .reg .u64 t; cvta.to.shared.u64 t, %1; cvt.u32.u64 %0, t; }" : "=r"(a) : "l"(p));
    return a;
}
__device__ __forceinline__ uint32_t elect_one() {
    uint32_t p;
    asm volatile("{ .reg .pred p; elect.sync _|p, 0xFFFFFFFF; selp.b32 %0, 1, 0, p; }" : "=r"(p));
    return p;
}
#define SW128(o) ((o) ^ (((o) >> 3) & 0x70))
static __device__ __forceinline__ uint64_t make_desc(uint32_t addr) {
    return ((uint64_t)2 << 61) | ((uint64_t)1 << 46) | ((uint64_t)64 << 32) |
           ((uint64_t)1 << 16) | ((uint64_t)(addr >> 4) & 0x3FFF);
}

#if HAS_TC
__device__ __forceinline__ void mma_bf16_ss(uint32_t d, uint64_t a, uint64_t b,
                                            uint32_t idesc, uint32_t en) {
    asm volatile(
        "{\n\t.reg .pred p;\n\tsetp.ne.u32 p, %4, 0;\n\t"
        "tcgen05.mma.cta_group::1.kind::f16 [%0], %1, %2, %3, {%5, %5, %5, %5}, p;\n\t}"
        :: "r"(d), "l"(a), "l"(b), "r"(idesc), "r"(en), "r"(0u) : "memory");
}
#define TC_ALLOC(sm, n)  asm volatile("tcgen05.alloc.cta_group::1.sync.aligned.shared::cta.b32 [%0], %1;" :: "r"(sm), "r"((uint32_t)(n)) : "memory")
#define TC_DEALLOC(t, n) asm volatile("tcgen05.dealloc.cta_group::1.sync.aligned.b32 %0, %1;" :: "r"(t), "r"((uint32_t)(n)))
#define TC_COMMIT(mb)    asm volatile("tcgen05.commit.cta_group::1.mbarrier::arrive::one.shared::cluster.b64 [%0];" :: "r"(mb) : "memory")
#define TC_FENCE_AFTER() asm volatile("tcgen05.fence::after_thread_sync;" ::: "memory")
#define TC_FENCE_BEFORE() asm volatile("tcgen05.fence::before_thread_sync;" ::: "memory")
#define TC_WAIT_LD()     asm volatile("tcgen05.wait::ld.sync.aligned;" ::: "memory")
#define LDTM32(r, a)                                                            \
    asm volatile("tcgen05.ld.sync.aligned.32x32b.x32.b32 "                      \
        "{%0,%1,%2,%3,%4,%5,%6,%7,%8,%9,%10,%11,%12,%13,%14,%15,"               \
        "%16,%17,%18,%19,%20,%21,%22,%23,%24,%25,%26,%27,%28,%29,%30,%31}, [%32];" \
        : "=r"((r)[0]),"=r"((r)[1]),"=r"((r)[2]),"=r"((r)[3]),                  \
          "=r"((r)[4]),"=r"((r)[5]),"=r"((r)[6]),"=r"((r)[7]),                  \
          "=r"((r)[8]),"=r"((r)[9]),"=r"((r)[10]),"=r"((r)[11]),                \
          "=r"((r)[12]),"=r"((r)[13]),"=r"((r)[14]),"=r"((r)[15]),              \
          "=r"((r)[16]),"=r"((r)[17]),"=r"((r)[18]),"=r"((r)[19]),              \
          "=r"((r)[20]),"=r"((r)[21]),"=r"((r)[22]),"=r"((r)[23]),              \
          "=r"((r)[24]),"=r"((r)[25]),"=r"((r)[26]),"=r"((r)[27]),              \
          "=r"((r)[28]),"=r"((r)[29]),"=r"((r)[30]),"=r"((r)[31])               \
        : "r"(a))
#define MB_WAIT(mb, par) do {                                                   \
    uint32_t _m = (mb), _p = (par), _d;                                         \
    asm volatile("{ .reg .pred p; mbarrier.try_wait.parity.acquire.cta.shared::cta.b64 p, [%1], %2; selp.b32 %0, 1, 0, p; }" \
                 : "=r"(_d) : "r"(_m), "r"(_p) : "memory");                     \
    if (!_d) {                                                                  \
        asm volatile("{ .reg .pred P1; W%=: mbarrier.try_wait.parity.acquire.cta.shared::cta.b64 P1, [%0], %1, 0x989680; @P1 bra.uni D%=; bra.uni W%=; D%=: }" \
                     :: "r"(_m), "r"(_p) : "memory");                           \
    }                                                                           \
} while (0)
#else
__device__ __forceinline__ void mma_bf16_ss(uint32_t, uint64_t, uint64_t, uint32_t, uint32_t) {}
#define TC_ALLOC(sm, n)   ((void)0)
#define TC_DEALLOC(t, n)  ((void)0)
#define TC_COMMIT(mb)     ((void)0)
#define TC_FENCE_AFTER()  ((void)0)
#define TC_FENCE_BEFORE() ((void)0)
#define TC_WAIT_LD()      ((void)0)
#define LDTM32(r, a)      do { _Pragma("unroll") for (int _i = 0; _i < 32; _i++) (r)[_i] = 0u; } while (0)
#define MB_WAIT(mb, par)  ((void)0)
#endif

#define MB_INIT(mb, c)   asm volatile("mbarrier.init.shared.b64 [%0], %1;" :: "r"(mb), "r"((uint32_t)(c)) : "memory")
#define MB_INVAL(mb)     asm volatile("mbarrier.inval.shared.b64 [%0];" :: "r"(mb) : "memory")
#define FENCE_ASYNC()    asm volatile("fence.proxy.async.shared::cta;" ::: "memory")
#define CP_ASYNC16(dst, src) asm volatile("cp.async.ca.shared.global [%0], [%1], 16;" :: "r"(dst), "l"(src) : "memory")
#define CP_COMMIT()      asm volatile("cp.async.commit_group;" ::: "memory")
#define CP_WAIT0()       asm volatile("cp.async.wait_group 0;" ::: "memory")

// ---------------- dtype detection ----------------
__global__ void detect_k(const unsigned int* __restrict__ e) {
    unsigned acc = 0;
    for (int i = 1; i < 128; i += 2) acc |= e[i];
    g_i64flag = (acc == 0u) ? 1 : 0;
}

// ---------------- weight split fp32 -> bf16 hi/lo ----------------
__global__ void wconv_k(const float* __restrict__ W1, const float* __restrict__ W2) {
    int i = blockIdx.x * 256 + threadIdx.x;
    const int tot = NLAYER * 256 * 128;
    if (i >= tot) return;
    int l = i / (256 * 128), rem = i % (256 * 128);
    {   // W1: [l][k(128)][n(256)] -> B1 [l][n][k]
        int n = rem / 128, k = rem % 128;
        float w = W1[l * 32768 + k * 256 + n];
        __nv_bfloat16 h = __float2bfloat16(w);
        g_b1hi[i] = h;
        g_b1lo[i] = __float2bfloat16(w - __bfloat162float(h));
    }
    {   // W2: [l][k(256)][n(128)] -> B2 [l][n][k]
        int n = rem / 256, k = rem % 256;
        float w = W2[l * 32768 + k * 128 + n];
        __nv_bfloat16 h = __float2bfloat16(w);
        g_b2hi[i] = h;
        g_b2lo[i] = __float2bfloat16(w - __bfloat162float(h));
    }
}

// ---------------- zero stats/pool/deg (grid-stride; covers n) ----------------
__global__ void zero_k(int n) {
    int tot = (n > GCNT * 128) ? n : GCNT * 128;
    for (int i = blockIdx.x * blockDim.x + threadIdx.x; i < tot;
         i += gridDim.x * blockDim.x) {
        if (i < 256) { g_ssum[i] = 0.f; g_ssq[i] = 0.f; }
        if (i < 128) { g_ssum2[i] = 0.f; g_ssq2[i] = 0.f; }
        if (i < GCNT * 128) { g_ps[i] = 0.f; g_pmx[i] = 0.f; }
        if (i < GCNT) g_cnt[i] = 0.f;
        if (i < n) g_deg[i] = 0;
    }
}

// ---------------- CSR build ----------------
__global__ void count_k(const void* __restrict__ ei, long long E) {
    long long e = (long long)blockIdx.x * blockDim.x + threadIdx.x;
    if (e >= E) return;
    int d;
    if (g_i64flag) d = (int)((const long long*)ei)[E + e];
    else           d = ((const int*)ei)[E + e];
    atomicAdd(&g_deg[d], 1);
}

__global__ void scanA_k(int n) {
    __shared__ int sred[256];
    int blk = blockIdx.x, t = threadIdx.x;
    int base = blk * 1024 + t * 4;
    int s = 0;
#pragma unroll
    for (int j = 0; j < 4; j++) {
        int idx = base + j;
        if (idx < n) s += g_deg[idx];
    }
    sred[t] = s;
    __syncthreads();
    for (int o = 128; o > 0; o >>= 1) {
        if (t < o) sred[t] += sred[t + o];
        __syncthreads();
    }
    if (t == 0) g_bsum[blk] = sred[0];
}

__global__ void scanB_k(int nblk) {
    if (threadIdx.x == 0) {
        int run = 0;
        for (int i = 0; i < nblk; i++) { g_bscn[i] = run; run += g_bsum[i]; }
    }
}

__global__ void scanC_k(int n) {
    __shared__ int sth[256];
    int blk = blockIdx.x, t = threadIdx.x;
    int base = blk * 1024 + t * 4;
    int v[4];
    int s = 0;
#pragma unroll
    for (int j = 0; j < 4; j++) {
        int idx = base + j;
        v[j] = (idx < n) ? g_deg[idx] : 0;
        s += v[j];
    }
    sth[t] = s;
    __syncthreads();
    for (int o = 1; o < 256; o <<= 1) {
        int add = (t >= o) ? sth[t - o] : 0;
        __syncthreads();
        sth[t] += add;
        __syncthreads();
    }
    int tpre = (t > 0 ? sth[t - 1] : 0) + g_bscn[blk];
#pragma unroll
    for (int j = 0; j < 4; j++) {
        int idx = base + j;
        if (idx < n) { g_off[idx] = tpre; g_cur[idx] = tpre; }
        tpre += v[j];
    }
}

__global__ void fill_k(const void* __restrict__ ei, long long E) {
    long long e = (long long)blockIdx.x * blockDim.x + threadIdx.x;
    if (e >= E) return;
    int s, d;
    if (g_i64flag) {
        const long long* p = (const long long*)ei;
        s = (int)p[e]; d = (int)p[E + e];
    } else {
        const int* p = (const int*)ei;
        s = p[e]; d = p[E + e];
    }
    int pos = atomicAdd(&g_cur[d], 1);
    if (pos < EMAX) g_csr[pos] = s;
}

__device__ __forceinline__ uint32_t pack_bf16x2(float a, float b) {
    __nv_bfloat162 h = __float22bfloat162_rn(make_float2(a, b));
    return *reinterpret_cast<uint32_t*>(&h);
}

// ---------------- CSR aggregation + bf16 split + swizzled store ----------------
// warp per node: r = (1+eps)*f(SRC[node]) + sum f(SRC[nbr]); f = bnrelu or id.
// Writes pre-split hi/lo A-tile image directly (g_ahi/g_alo).
template<bool BN>
__global__ void __launch_bounds__(256) agg_k(
    const float* __restrict__ SRC, const float* __restrict__ epsp, int l, int n) {
    int node = (int)(((long long)blockIdx.x * blockDim.x + threadIdx.x) >> 5);
    int lane = threadIdx.x & 31;
    if (node >= n) return;
    float e = 1.0f + epsp[l];

    float sc0, sc1, sc2, sc3, sh0, sh1, sh2, sh3;
    if (BN) {
        int c = lane * 4;
        sc0 = g_scale[c]; sc1 = g_scale[c + 1]; sc2 = g_scale[c + 2]; sc3 = g_scale[c + 3];
        sh0 = g_shift[c]; sh1 = g_shift[c + 1]; sh2 = g_shift[c + 2]; sh3 = g_shift[c + 3];
    }
#define FBN(v)                                                                   \
    if (BN) {                                                                    \
        v.x = fmaxf(fmaf(v.x, sc0, sh0), 0.f);                                   \
        v.y = fmaxf(fmaf(v.y, sc1, sh1), 0.f);                                   \
        v.z = fmaxf(fmaf(v.z, sc2, sh2), 0.f);                                   \
        v.w = fmaxf(fmaf(v.w, sc3, sh3), 0.f);                                   \
    }

    int beg = g_off[node];
    int deg = g_deg[node];

    float4 self = ((const float4*)SRC)[(size_t)node * 32 + lane];
    FBN(self);
    float4 a0 = make_float4(self.x * e, self.y * e, self.z * e, self.w * e);
    float4 a1 = make_float4(0.f, 0.f, 0.f, 0.f);
    float4 a2 = make_float4(0.f, 0.f, 0.f, 0.f);
    float4 a3 = make_float4(0.f, 0.f, 0.f, 0.f);

    int i = 0;
    for (; i + 4 <= deg; i += 4) {
        int s0 = g_csr[beg + i];
        int s1 = g_csr[beg + i + 1];
        int s2 = g_csr[beg + i + 2];
        int s3 = g_csr[beg + i + 3];
        float4 v0 = ((const float4*)SRC)[(size_t)s0 * 32 + lane];
        float4 v1 = ((const float4*)SRC)[(size_t)s1 * 32 + lane];
        float4 v2 = ((const float4*)SRC)[(size_t)s2 * 32 + lane];
        float4 v3 = ((const float4*)SRC)[(size_t)s3 * 32 + lane];
        FBN(v0); FBN(v1); FBN(v2); FBN(v3);
        a0.x += v0.x; a0.y += v0.y; a0.z += v0.z; a0.w += v0.w;
        a1.x += v1.x; a1.y += v1.y; a1.z += v1.z; a1.w += v1.w;
        a2.x += v2.x; a2.y += v2.y; a2.z += v2.z; a2.w += v2.w;
        a3.x += v3.x; a3.y += v3.y; a3.z += v3.z; a3.w += v3.w;
    }
    if (i < deg) {
        int rem = deg - i;                       // 1..3
        int s0 = g_csr[beg + i];
        int s1 = g_csr[beg + ((rem > 1) ? i + 1 : i)];
        int s2 = g_csr[beg + ((rem > 2) ? i + 2 : i)];
        float4 v0 = ((const float4*)SRC)[(size_t)s0 * 32 + lane];
        float4 v1 = ((const float4*)SRC)[(size_t)s1 * 32 + lane];
        float4 v2 = ((const float4*)SRC)[(size_t)s2 * 32 + lane];
        FBN(v0); FBN(v1); FBN(v2);
        a1.x += v0.x; a1.y += v0.y; a1.z += v0.z; a1.w += v0.w;
        if (rem > 1) { a2.x += v1.x; a2.y += v1.y; a2.z += v1.z; a2.w += v1.w; }
        if (rem > 2) { a3.x += v2.x; a3.y += v2.y; a3.z += v2.z; a3.w += v2.w; }
    }
#undef FBN
    float4 r;
    r.x = (a0.x + a1.x) + (a2.x + a3.x);
    r.y = (a0.y + a1.y) + (a2.y + a3.y);
    r.z = (a0.z + a1.z) + (a2.z + a3.z);
    r.w = (a0.w + a1.w) + (a2.w + a3.w);

    // bf16 hi/lo split + swizzled store into the smem-image buffers
    uint32_t h0 = pack_bf16x2(r.x, r.y);
    uint32_t h1 = pack_bf16x2(r.z, r.w);
    __nv_bfloat162 hb0 = *reinterpret_cast<__nv_bfloat162*>(&h0);
    __nv_bfloat162 hb1 = *reinterpret_cast<__nv_bfloat162*>(&h1);
    float2 hr0 = __bfloat1622float2(hb0);
    float2 hr1 = __bfloat1622float2(hb1);
    uint32_t l0 = pack_bf16x2(r.x - hr0.x, r.y - hr0.y);
    uint32_t l1 = pack_bf16x2(r.z - hr1.x, r.w - hr1.y);

    int T = node >> 7, rr = node & 127;
    int c8 = lane >> 4;              // chunk (k<64 / k>=64)
    int g8 = (lane >> 1) & 7;        // 16B group within row
    int half = lane & 1;             // low/high 8B of group
    size_t base = ((size_t)T * 2 + c8) * 16384
                + SW128((uint32_t)(rr * 128 + g8 * 16)) + half * 8;
    *(uint2*)(g_ahi + base) = make_uint2(h0, h1);
    *(uint2*)(g_alo + base) = make_uint2(l0, l1);
}

// ================== fused layer kernel ==================
// PASS 1: y = A@W1 + b1 in TMEM; stats -> g_ssum/g_ssq. y NOT stored.
// PASS 2: recompute y, BN+ReLU in-register, GEMM2 -> h2 + stats (g_ssum2).
// A comes pre-split/pre-swizzled from g_ahi/g_alo (pure cp.async staging).
#define P_PTR   0
#define P_MBAR  16
#define P_SC    32
#define P_SH    1056
#define P_SB    2080
#define P_SSL   3104
#define P_SQL   4128
#define P_PSUM  5152
#define P_PSQ   6176
#define P_A1HI  8192
#define P_A1LO  24576
#define P_B1HI  40960
#define P_B1LO  73728
#define P_SMEM  106496
#define TG_IDESC 0x8200490u

template<int PASS>
__global__ void __launch_bounds__(256, 2) pass_k(
    const uint8_t* __restrict__ Ahi, const uint8_t* __restrict__ Alo,
    const __nv_bfloat16* __restrict__ B1hi, const __nv_bfloat16* __restrict__ B1lo,
    const __nv_bfloat16* __restrict__ B2hi, const __nv_bfloat16* __restrict__ B2lo,
    const float* __restrict__ b1, const float* __restrict__ b2,
    const float* __restrict__ g1, const float* __restrict__ be1, float invM,
    float* __restrict__ C, int M)
{
    extern __shared__ char smem[];
    const uint32_t sb = smem_u32(smem);
    const int t = threadIdx.x, wid = t >> 5, lid = t & 31;
    const int bm = blockIdx.x * 128;
    float* sSc = reinterpret_cast<float*>(smem + P_SC);
    float* sSh = reinterpret_cast<float*>(smem + P_SH);
    float* sB  = reinterpret_cast<float*>(smem + P_SB);
    float* ssl = reinterpret_cast<float*>(smem + P_SSL);
    float* sql = reinterpret_cast<float*>(smem + P_SQL);
    float* psum = reinterpret_cast<float*>(smem + P_PSUM);
    float* psq  = reinterpret_cast<float*>(smem + P_PSQ);
    float* statbuf = reinterpret_cast<float*>(smem + P_B1HI);

    if (wid == 0) TC_ALLOC(sb + P_PTR, 256);
    if (t == 0) MB_INIT(sb + P_MBAR, 1);
    if (PASS == 1) {
        sB[t] = b1[t];
    } else {
        float m   = g_ssum[t] * invM;
        float var = g_ssq[t] * invM - m * m;
        float sc  = g1[t] * rsqrtf(var + 1e-5f);
        sSc[t] = sc;
        sSh[t] = fmaf(b1[t] - m, sc, be1[t]);
        if (t < 128) sB[t] = b2[t];
    }
    __syncthreads();
    uint32_t tmem;
    asm volatile("ld.shared.b32 %0, [%1];" : "=r"(tmem) : "r"(sb + P_PTR));

    const uint64_t dA1hi = make_desc(sb + P_A1HI);
    const uint64_t dA1lo = make_desc(sb + P_A1LO);
    const uint64_t dB1hi = make_desc(sb + P_B1HI);
    const uint64_t dB1lo = make_desc(sb + P_B1LO);

    int pc = 0;

    // -------- phase 1: y = A @ W1 (2 k-chunks) --------
#define CPASYNC_A1(CH)                                                          \
    {                                                                           \
        size_t abase = ((size_t)blockIdx.x * 2 + (CH)) * 16384;                 \
        _Pragma("unroll")                                                       \
        for (int it = 0; it < 4; it++) {                                        \
            uint32_t o = (uint32_t)(t + it * 256) * 16;                         \
            CP_ASYNC16(sb + P_A1HI + o, Ahi + abase + o);                       \
            CP_ASYNC16(sb + P_A1LO + o, Alo + abase + o);                       \
        }                                                                       \
    }
#define CPASYNC_B1(CH)                                                          \
    {                                                                           \
        int kb_ = (CH) * 64;                                                    \
        _Pragma("unroll")                                                       \
        for (int it = 0; it < 8; it++) {                                        \
            int idx = t + it * 256;                                             \
            int r_ = idx >> 3, kg_ = idx & 7;                                   \
            uint32_t so_ = SW128((uint32_t)(r_ * 128 + kg_ * 16));              \
            size_t bo_ = (size_t)r_ * 128 + kb_ + kg_ * 8;                      \
            CP_ASYNC16(sb + P_B1HI + so_, B1hi + bo_);                          \
            CP_ASYNC16(sb + P_B1LO + so_, B1lo + bo_);                          \
        }                                                                       \
        CP_COMMIT();                                                            \
    }
#define MMA1_CHUNK(CH)                                                          \
    if (wid == 0 && elect_one()) {                                              \
        _Pragma("unroll")                                                       \
        for (int T = 0; T < 2; T++) {                                           \
            uint64_t bh = dB1hi + T * 1024;                                     \
            uint64_t bl = dB1lo + T * 1024;                                     \
            uint32_t dt = tmem + T * 128;                                       \
            _Pragma("unroll")                                                   \
            for (int s = 0; s < 4; s++)                                         \
                mma_bf16_ss(dt, dA1hi + s * 2, bh + s * 2, TG_IDESC,            \
                            ((CH) == 0 && s == 0) ? 0u : 1u);                   \
            _Pragma("unroll")                                                   \
            for (int s = 0; s < 4; s++)                                         \
                mma_bf16_ss(dt, dA1hi + s * 2, bl + s * 2, TG_IDESC, 1u);       \
            _Pragma("unroll")                                                   \
            for (int s = 0; s < 4; s++)                                         \
                mma_bf16_ss(dt, dA1lo + s * 2, bh + s * 2, TG_IDESC, 1u);       \
        }                                                                       \
        TC_COMMIT(sb + P_MBAR);                                                 \
    }

    CPASYNC_A1(0);
    CPASYNC_B1(0);
    CP_WAIT0();
    FENCE_ASYNC();
    __syncthreads();
    MMA1_CHUNK(0);
    MB_WAIT(sb + P_MBAR, pc & 1); pc++;
    CPASYNC_A1(1);
    CPASYNC_B1(1);
    CP_WAIT0();
    FENCE_ASYNC();
    __syncthreads();
    MMA1_CHUNK(1);
    MB_WAIT(sb + P_MBAR, pc & 1); pc++;
    TC_FENCE_AFTER();

#undef CPASYNC_A1
#undef CPASYNC_B1
#undef MMA1_CHUNK

    if (PASS == 1) {
        // -------- y stats only --------
        for (int pr = 0; pr < 4; pr++) {
            if (wid < 4) {
                int r = wid * 32 + lid;
                int grow = bm + r;
                uint32_t r0[32], r1[32];
                LDTM32(r0, tmem + pr * 64);
                LDTM32(r1, tmem + pr * 64 + 32);
                TC_WAIT_LD();
                float v0[32], v1[32];
#pragma unroll
                for (int i = 0; i < 32; i++) {
                    v0[i] = (grow < M) ? __uint_as_float(r0[i]) + sB[pr * 64 + i]      : 0.f;
                    v1[i] = (grow < M) ? __uint_as_float(r1[i]) + sB[pr * 64 + 32 + i] : 0.f;
                }
#pragma unroll
                for (int i = 0; i < 32; i++) {
                    statbuf[r * 66 + i]      = v0[i];
                    statbuf[r * 66 + 32 + i] = v1[i];
                }
            }
            __syncthreads();
            {
                int c = t & 63, h = t >> 6;
                float s = 0.f, q = 0.f;
#pragma unroll 8
                for (int rr = 0; rr < 32; rr++) {
                    float v = statbuf[(h * 32 + rr) * 66 + c];
                    s += v;
                    q = fmaf(v, v, q);
                }
                psum[h * 64 + c] = s;
                psq[h * 64 + c]  = q;
            }
            __syncthreads();
            if (t < 64) {
                ssl[pr * 64 + t] = psum[t] + psum[64 + t] + psum[128 + t] + psum[192 + t];
                sql[pr * 64 + t] = psq[t]  + psq[64 + t]  + psq[128 + t]  + psq[192 + t];
            }
            __syncthreads();
        }
        if (wid < 4) TC_FENCE_BEFORE();
        __syncthreads();
        atomicAdd(&g_ssum[t], ssl[t]);
        atomicAdd(&g_ssq[t],  sql[t]);
    } else {
        // -------- phase 2: h2 = bnrelu(y) @ W2 + b2 --------
        const uint64_t dB2hi = make_desc(sb + P_A1HI);
        const uint64_t dB2lo = make_desc(sb + P_A1LO);

#define CPASYNC_B2_HALF(CH)                                                     \
    {                                                                           \
        int kb_ = (CH) * 64;                                                    \
        _Pragma("unroll")                                                       \
        for (int it = 0; it < 8; it++) {                                        \
            int idx = (t - 128) + it * 128;                                     \
            int r_ = idx >> 3, kg_ = idx & 7;                                   \
            uint32_t so_ = SW128((uint32_t)(r_ * 128 + kg_ * 16));              \
            size_t bo_ = (size_t)r_ * 256 + kb_ + kg_ * 8;                      \
            CP_ASYNC16(sb + P_A1HI + so_, B2hi + bo_);                          \
            CP_ASYNC16(sb + P_A1LO + so_, B2lo + bo_);                          \
        }                                                                       \
        CP_COMMIT();                                                            \
        CP_WAIT0();                                                             \
    }
#define CPASYNC_B2_ALL(CH)                                                      \
    {                                                                           \
        int kb_ = (CH) * 64;                                                    \
        _Pragma("unroll")                                                       \
        for (int it = 0; it < 4; it++) {                                        \
            int idx = t + it * 256;                                             \
            int r_ = idx >> 3, kg_ = idx & 7;                                   \
            uint32_t so_ = SW128((uint32_t)(r_ * 128 + kg_ * 16));              \
            size_t bo_ = (size_t)r_ * 256 + kb_ + kg_ * 8;                      \
            CP_ASYNC16(sb + P_A1HI + so_, B2hi + bo_);                          \
            CP_ASYNC16(sb + P_A1LO + so_, B2lo + bo_);                          \
        }                                                                       \
        CP_COMMIT();                                                            \
        CP_WAIT0();                                                             \
    }
#define MMA2(SLOT, EN0)                                                         \
    if (wid == 0 && elect_one()) {                                              \
        uint64_t ah = make_desc(sb + P_B1HI + (SLOT) * 16384);                  \
        uint64_t al = make_desc(sb + P_B1LO + (SLOT) * 16384);                  \
        _Pragma("unroll")                                                       \
        for (int s = 0; s < 4; s++)                                             \
            mma_bf16_ss(tmem, ah + s * 2, dB2hi + s * 2, TG_IDESC,              \
                        ((EN0) && s == 0) ? 0u : 1u);                           \
        _Pragma("unroll")                                                       \
        for (int s = 0; s < 4; s++)                                             \
            mma_bf16_ss(tmem, ah + s * 2, dB2lo + s * 2, TG_IDESC, 1u);         \
        _Pragma("unroll")                                                       \
        for (int s = 0; s < 4; s++)                                             \
            mma_bf16_ss(tmem, al + s * 2, dB2hi + s * 2, TG_IDESC, 1u);         \
        TC_COMMIT(sb + P_MBAR);                                                 \
    }

#pragma unroll
        for (int half = 0; half < 2; half++) {
            if (wid < 4) {
                int r = wid * 32 + lid;
#pragma unroll
                for (int p2 = 0; p2 < 2; p2++) {
                    int b0 = half * 4 + p2 * 2;
                    uint32_t r0[32], r1[32];
                    LDTM32(r0, tmem + b0 * 32);
                    LDTM32(r1, tmem + (b0 + 1) * 32);
                    TC_WAIT_LD();
                    float v[64];
#pragma unroll
                    for (int i = 0; i < 32; i++) {
                        int c0 = b0 * 32 + i, c1 = (b0 + 1) * 32 + i;
                        v[i]      = fmaxf(fmaf(__uint_as_float(r0[i]), sSc[c0], sSh[c0]), 0.f);
                        v[32 + i] = fmaxf(fmaf(__uint_as_float(r1[i]), sSc[c1], sSh[c1]), 0.f);
                    }
#pragma unroll
                    for (int bb = 0; bb < 2; bb++) {
                        int blk = b0 + bb;
                        int slot = (blk >> 1) & 1;
                        const float* vv = v + bb * 32;
#pragma unroll
                        for (int q = 0; q < 4; q++) {
                            uint32_t h[4], lo[4];
#pragma unroll
                            for (int p = 0; p < 4; p++) {
                                float a0 = vv[q * 8 + p * 2], a1 = vv[q * 8 + p * 2 + 1];
                                h[p] = pack_bf16x2(a0, a1);
                                __nv_bfloat162 hb = *reinterpret_cast<__nv_bfloat162*>(&h[p]);
                                float2 hr = __bfloat1622float2(hb);
                                lo[p] = pack_bf16x2(a0 - hr.x, a1 - hr.y);
                            }
                            uint32_t so = SW128((uint32_t)(r * 128 + (blk & 1) * 64 + q * 16));
                            *(uint4*)(smem + P_B1HI + slot * 16384 + so) = make_uint4(h[0], h[1], h[2], h[3]);
                            *(uint4*)(smem + P_B1LO + slot * 16384 + so) = make_uint4(lo[0], lo[1], lo[2], lo[3]);
                        }
                    }
                }
                TC_FENCE_BEFORE();
            } else {
                CPASYNC_B2_HALF(2 * half);
            }
            FENCE_ASYNC();
            __syncthreads();
            MMA2(0, half == 0);
            MB_WAIT(sb + P_MBAR, pc & 1); pc++;
            CPASYNC_B2_ALL(2 * half + 1);
            FENCE_ASYNC();
            __syncthreads();
            MMA2(1, false);
            MB_WAIT(sb + P_MBAR, pc & 1); pc++;
            TC_FENCE_AFTER();
        }

#undef CPASYNC_B2_HALF
#undef CPASYNC_B2_ALL
#undef MMA2

        // -------- final epilogue: h2 --------
        for (int pr = 0; pr < 2; pr++) {
            if (wid < 4) {
                int r = wid * 32 + lid;
                int grow = bm + r;
                uint32_t r0[32], r1[32];
                LDTM32(r0, tmem + pr * 64);
                LDTM32(r1, tmem + pr * 64 + 32);
                TC_WAIT_LD();
                float v0[32], v1[32];
#pragma unroll
                for (int i = 0; i < 32; i++) {
                    v0[i] = __uint_as_float(r0[i]) + sB[pr * 64 + i];
                    v1[i] = __uint_as_float(r1[i]) + sB[pr * 64 + 32 + i];
                }
                if (grow < M) {
                    float* cp = C + (size_t)grow * 128 + pr * 64;
#pragma unroll
                    for (int q = 0; q < 8; q++) {
                        *(float4*)(cp + q * 4)      = *(float4*)(v0 + q * 4);
                        *(float4*)(cp + 32 + q * 4) = *(float4*)(v1 + q * 4);
                    }
                } else {
#pragma unroll
                    for (int i = 0; i < 32; i++) { v0[i] = 0.f; v1[i] = 0.f; }
                }
#pragma unroll
                for (int i = 0; i < 32; i++) {
                    statbuf[r * 66 + i]      = v0[i];
                    statbuf[r * 66 + 32 + i] = v1[i];
                }
            }
            __syncthreads();
            {
                int c = t & 63, h = t >> 6;
                float s = 0.f, q = 0.f;
#pragma unroll 8
                for (int rr = 0; rr < 32; rr++) {
                    float vv = statbuf[(h * 32 + rr) * 66 + c];
                    s += vv;
                    q = fmaf(vv, vv, q);
                }
                psum[h * 64 + c] = s;
                psq[h * 64 + c]  = q;
            }
            __syncthreads();
            if (t < 64) {
                ssl[pr * 64 + t] = psum[t] + psum[64 + t] + psum[128 + t] + psum[192 + t];
                sql[pr * 64 + t] = psq[t]  + psq[64 + t]  + psq[128 + t]  + psq[192 + t];
            }
            __syncthreads();
        }
        if (wid < 4) TC_FENCE_BEFORE();
        __syncthreads();
        if (t < 128) {
            atomicAdd(&g_ssum2[t], ssl[t]);
            atomicAdd(&g_ssq2[t],  sql[t]);
        }
    }

    __syncthreads();
    if (t == 0) MB_INVAL(sb + P_MBAR);
    if (wid == 0) TC_DEALLOC(tmem, 256);
}

// outer BN finalize
__global__ void finalize_k(const float* __restrict__ gamma, const float* __restrict__ beta,
                           float invM) {
    int t = threadIdx.x;
    if (t < 128) {
        float m   = g_ssum2[t] * invM;
        float var = g_ssq2[t] * invM - m * m;
        float sc  = gamma[t] * rsqrtf(var + 1e-5f);
        g_scale[t] = sc;
        g_shift[t] = beta[t] - m * sc;
        g_ssum2[t] = 0.f;
        g_ssq2[t]  = 0.f;
    }
    g_ssum[t] = 0.f;
    g_ssq[t]  = 0.f;
}

// ---------------- readout pooling ----------------
__global__ void pool_k(const void* __restrict__ batch, int n) {
    long long t = (long long)blockIdx.x * blockDim.x + threadIdx.x;
    long long i = t >> 5;
    if (i >= n) return;
    int lane = (int)(t & 31);
    long long g;
    if (g_i64flag) g = ((const long long*)batch)[i];
    else           g = (long long)((const int*)batch)[i];
    int c = lane * 4;
    float4 v = ((const float4*)g_h2)[i * 32 + lane];
    float r0 = fmaxf(fmaf(v.x, g_scale[c + 0], g_shift[c + 0]), 0.f);
    float r1 = fmaxf(fmaf(v.y, g_scale[c + 1], g_shift[c + 1]), 0.f);
    float r2 = fmaxf(fmaf(v.z, g_scale[c + 2], g_shift[c + 2]), 0.f);
    float r3 = fmaxf(fmaf(v.w, g_scale[c + 3], g_shift[c + 3]), 0.f);
    float* ps = g_ps + g * 128 + c;
    asm volatile("red.global.add.v4.f32 [%0], {%1, %2, %3, %4};"
                 :: "l"(ps), "f"(r0), "f"(r1), "f"(r2), "f"(r3) : "memory");
    unsigned int* mx = (unsigned int*)(g_pmx + g * 128 + c);
    atomicMax(mx + 0, __float_as_uint(r0));
    atomicMax(mx + 1, __float_as_uint(r1));
    atomicMax(mx + 2, __float_as_uint(r2));
    atomicMax(mx + 3, __float_as_uint(r3));
    if (lane == 0) atomicAdd(&g_cnt[g], 1.0f);
}

// ---------------- classifier ----------------
__global__ void cgemm1_k(const float* __restrict__ cW1, const float* __restrict__ cb1) {
    int g = blockIdx.x;
    int j = threadIdx.x;
    __shared__ float z[384];
    float cnt = fmaxf(g_cnt[g], 1.0f);
    float sv = g_ps[g * 128 + j];
    z[j]       = sv;
    z[128 + j] = sv / cnt;
    z[256 + j] = g_pmx[g * 128 + j];
    __syncthreads();
    float acc = cb1[j];
#pragma unroll 8
    for (int k = 0; k < 384; k++)
        acc = fmaf(z[k], cW1[k * 128 + j], acc);
    g_z1[g * 128 + j] = acc;
}

__global__ void cstats_k(const float* __restrict__ cg, const float* __restrict__ cbeta) {
    int j = threadIdx.x;
    float s = 0.f, q = 0.f;
    for (int g = 0; g < GCNT; g++) {
        float v = g_z1[g * 128 + j];
        s += v; q += v * v;
    }
    float m   = s * (1.0f / GCNT);
    float var = q * (1.0f / GCNT) - m * m;
    float sc  = cg[j] * rsqrtf(var + 1e-5f);
    g_scale[j] = sc;
    g_shift[j] = cbeta[j] - m * sc;
}

__global__ void chead_k(const float* __restrict__ cW2, const float* __restrict__ cb2,
                        const float* __restrict__ cW3, const float* __restrict__ cb3,
                        float* __restrict__ out) {
    int g = blockIdx.x;
    int j = threadIdx.x;
    __shared__ float a[128];
    __shared__ float z2[64];
    for (int k = j; k < 128; k += 64)
        a[k] = fmaxf(fmaf(g_z1[g * 128 + k], g_scale[k], g_shift[k]), 0.f);
    __syncthreads();
    float acc = cb2[j];
#pragma unroll 8
    for (int k = 0; k < 128; k++)
        acc = fmaf(a[k], cW2[k * 64 + j], acc);
    z2[j] = fmaxf(acc, 0.f);
    __syncthreads();
    if (j < 2) {
        float o = cb3[j];
#pragma unroll 8
        for (int k = 0; k < 64; k++)
            o = fmaf(z2[k], cW3[k * 2 + j], o);
        out[g * 2 + j] = o;
    }
}

// ---------------- launcher ----------------
extern "C" void kernel_launch(void* const* d_in, const int* in_sizes, int n_in,
                              void* d_out, int out_size) {
    const float* x     = (const float*)d_in[0];
    const void*  ei    = d_in[1];
    const void*  batch = d_in[2];
    int base = (in_sizes[3] == 1) ? 4 : 3;
    const float* W1    = (const float*)d_in[base + 0];
    const float* b1    = (const float*)d_in[base + 1];
    const float* g1    = (const float*)d_in[base + 2];
    const float* be1   = (const float*)d_in[base + 3];
    const float* W2    = (const float*)d_in[base + 4];
    const float* b2    = (const float*)d_in[base + 5];
    const float* gbn   = (const float*)d_in[base + 6];
    const float* bbn   = (const float*)d_in[base + 7];
    const float* eps   = (const float*)d_in[base + 8];
    const float* cW1   = (const float*)d_in[base + 9];
    const float* cb1   = (const float*)d_in[base + 10];
    const float* cg    = (const float*)d_in[base + 11];
    const float* cbeta = (const float*)d_in[base + 12];
    const float* cW2   = (const float*)d_in[base + 13];
    const float* cb2   = (const float*)d_in[base + 14];
    const float* cW3   = (const float*)d_in[base + 15];
    const float* cb3   = (const float*)d_in[base + 16];

    int n = in_sizes[0] / 128;
    long long E = (long long)in_sizes[1] / 2;
    int n32 = n * 32;
    int nb = (n32 + 255) / 256;
    int gx = (n + 127) / 128;
    int eblk = (int)((E + 255) / 256);
    int nscan = (n + 1023) / 1024;
    int ablk = (n * 32 + 255) / 256;
    float invM = 1.0f / (float)n;

    static int smem_set = 0;
    if (!smem_set) {
        cudaFuncSetAttribute(pass_k<1>, cudaFuncAttributeMaxDynamicSharedMemorySize, P_SMEM);
        cudaFuncSetAttribute(pass_k<2>, cudaFuncAttributeMaxDynamicSharedMemorySize, P_SMEM);
        smem_set = 1;
    }

    float *p_h2;
    uint8_t *p_ahi, *p_alo;
    __nv_bfloat16 *p_b1hi, *p_b1lo, *p_b2hi, *p_b2lo;
    cudaGetSymbolAddress((void**)&p_h2,  g_h2);
    cudaGetSymbolAddress((void**)&p_ahi, g_ahi);
    cudaGetSymbolAddress((void**)&p_alo, g_alo);
    cudaGetSymbolAddress((void**)&p_b1hi, g_b1hi);
    cudaGetSymbolAddress((void**)&p_b1lo, g_b1lo);
    cudaGetSymbolAddress((void**)&p_b2hi, g_b2hi);
    cudaGetSymbolAddress((void**)&p_b2lo, g_b2lo);

    detect_k<<<1, 1>>>((const unsigned int*)ei);
    wconv_k<<<(NLAYER * 256 * 128 + 255) / 256, 256>>>(W1, W2);
    zero_k<<<512, 256>>>(n);

    // CSR build (once; edges shared by all layers)
    count_k<<<eblk, 256>>>(ei, E);
    scanA_k<<<nscan, 256>>>(n);
    scanB_k<<<1, 32>>>(nscan);
    scanC_k<<<nscan, 256>>>(n);
    fill_k<<<eblk, 256>>>(ei, E);

    for (int l = 0; l < 4; l++) {
        if (l == 0) agg_k<false><<<ablk, 256>>>(x, eps, l, n);
        else        agg_k<true><<<ablk, 256>>>(p_h2, eps, l, n);

        pass_k<1><<<gx, 256, P_SMEM>>>(
            p_ahi, p_alo,
            p_b1hi + (size_t)l * 32768, p_b1lo + (size_t)l * 32768,
            p_b2hi + (size_t)l * 32768, p_b2lo + (size_t)l * 32768,
            b1 + l * 256, b2 + l * 128, g1 + l * 256, be1 + l * 256, invM,
            nullptr, n);
        pass_k<2><<<gx, 256, P_SMEM>>>(
            p_ahi, p_alo,
            p_b1hi + (size_t)l * 32768, p_b1lo + (size_t)l * 32768,
            p_b2hi + (size_t)l * 32768, p_b2lo + (size_t)l * 32768,
            b1 + l * 256, b2 + l * 128, g1 + l * 256, be1 + l * 256, invM,
            p_h2, n);
        finalize_k<<<1, 256>>>(gbn + l * 128, bbn + l * 128, invM);
    }

    pool_k<<<nb, 256>>>(batch, n);
    cgemm1_k<<<GCNT, 128>>>(cW1, cb1);
    cstats_k<<<1, 128>>>(cg, cbeta);
    chead_k<<<GCNT, 64>>>(cW2, cb2, cW3, cb3, (float*)d_out);
}

// round 12
// speedup vs baseline: 1.2538x; 1.0047x over previous
#include <cuda_runtime.h>
#include <cuda_bf16.h>
#include <cstdint>
#include <cstddef>

// Problem constants (fixed shapes)
#define NMAX 100000
#define EMAX 500000
#define GCNT 512
#define NLAYER 4
#define NTILE ((NMAX + 127) / 128)   // 782

// tcgen05 only exists in the arch-specific (sm_103a) device pass.
#if defined(__CUDA_ARCH__) && defined(__CUDA_ARCH_FEAT_SM103_ALL)
#define HAS_TC 1
#else
#define HAS_TC 0
#endif

// ---------------- device scratch ----------------
__device__ float g_h2 [NMAX * 128];
// aggregated layer input, pre-split bf16 hi/lo, pre-swizzled smem image:
// [tile][chunk(2)][16KB image]  where image[SW128(row*128 + kg*16)]
__device__ uint8_t g_ahi[(size_t)NTILE * 32768];
__device__ uint8_t g_alo[(size_t)NTILE * 32768];
__device__ float g_ssum [256];
__device__ float g_ssq  [256];
__device__ float g_ssum2[128];
__device__ float g_ssq2 [128];
__device__ float g_scale[256];   // used by classifier only now
__device__ float g_shift[256];
__device__ float g_ps [GCNT * 128];
__device__ float g_pmx[GCNT * 128];
__device__ float g_cnt[GCNT];
__device__ float g_z1 [GCNT * 128];
__device__ int   g_i64flag;

// CSR (built once per launch; edges fixed across layers)
__device__ int g_deg [NMAX];
__device__ int g_off [NMAX];
__device__ int g_cur [NMAX];
__device__ int g_csr [EMAX];
__device__ int g_bsum[128];
__device__ int g_bscn[128];

// pre-split weights, B layout: [layer][n(out)][k(in)] bf16, K-major rows
__device__ __nv_bfloat16 g_b1hi[NLAYER * 256 * 128];
__device__ __nv_bfloat16 g_b1lo[NLAYER * 256 * 128];
__device__ __nv_bfloat16 g_b2hi[NLAYER * 128 * 256];
__device__ __nv_bfloat16 g_b2lo[NLAYER * 128 * 256];

// ---------------- PTX helpers ----------------
__device__ __forceinline__ uint32_t smem_u32(const void* p) {
    uint32_t a;
    asm("{ .reg .u64 t; cvta.to.shared.u64 t, %1; cvt.u32.u64 %0, t; }" : "=r"(a) : "l"(p));
    return a;
}
__device__ __forceinline__ uint32_t elect_one() {
    uint32_t p;
    asm volatile("{ .reg .pred p; elect.sync _|p, 0xFFFFFFFF; selp.b32 %0, 1, 0, p; }" : "=r"(p));
    return p;
}
#define SW128(o) ((o) ^ (((o) >> 3) & 0x70))
static __device__ __forceinline__ uint64_t make_desc(uint32_t addr) {
    return ((uint64_t)2 << 61) | ((uint64_t)1 << 46) | ((uint64_t)64 << 32) |
           ((uint64_t)1 << 16) | ((uint64_t)(addr >> 4) & 0x3FFF);
}

#if HAS_TC
__device__ __forceinline__ void mma_bf16_ss(uint32_t d, uint64_t a, uint64_t b,
                                            uint32_t idesc, uint32_t en) {
    asm volatile(
        "{\n\t.reg .pred p;\n\tsetp.ne.u32 p, %4, 0;\n\t"
        "tcgen05.mma.cta_group::1.kind::f16 [%0], %1, %2, %3, {%5, %5, %5, %5}, p;\n\t}"
        :: "r"(d), "l"(a), "l"(b), "r"(idesc), "r"(en), "r"(0u) : "memory");
}
#define TC_ALLOC(sm, n)  asm volatile("tcgen05.alloc.cta_group::1.sync.aligned.shared::cta.b32 [%0], %1;" :: "r"(sm), "r"((uint32_t)(n)) : "memory")
#define TC_DEALLOC(t, n) asm volatile("tcgen05.dealloc.cta_group::1.sync.aligned.b32 %0, %1;" :: "r"(t), "r"((uint32_t)(n)))
#define TC_COMMIT(mb)    asm volatile("tcgen05.commit.cta_group::1.mbarrier::arrive::one.shared::cluster.b64 [%0];" :: "r"(mb) : "memory")
#define TC_FENCE_AFTER() asm volatile("tcgen05.fence::after_thread_sync;" ::: "memory")
#define TC_FENCE_BEFORE() asm volatile("tcgen05.fence::before_thread_sync;" ::: "memory")
#define TC_WAIT_LD()     asm volatile("tcgen05.wait::ld.sync.aligned;" ::: "memory")
#define LDTM32(r, a)                                                            \
    asm volatile("tcgen05.ld.sync.aligned.32x32b.x32.b32 "                      \
        "{%0,%1,%2,%3,%4,%5,%6,%7,%8,%9,%10,%11,%12,%13,%14,%15,"               \
        "%16,%17,%18,%19,%20,%21,%22,%23,%24,%25,%26,%27,%28,%29,%30,%31}, [%32];" \
        : "=r"((r)[0]),"=r"((r)[1]),"=r"((r)[2]),"=r"((r)[3]),                  \
          "=r"((r)[4]),"=r"((r)[5]),"=r"((r)[6]),"=r"((r)[7]),                  \
          "=r"((r)[8]),"=r"((r)[9]),"=r"((r)[10]),"=r"((r)[11]),                \
          "=r"((r)[12]),"=r"((r)[13]),"=r"((r)[14]),"=r"((r)[15]),              \
          "=r"((r)[16]),"=r"((r)[17]),"=r"((r)[18]),"=r"((r)[19]),              \
          "=r"((r)[20]),"=r"((r)[21]),"=r"((r)[22]),"=r"((r)[23]),              \
          "=r"((r)[24]),"=r"((r)[25]),"=r"((r)[26]),"=r"((r)[27]),              \
          "=r"((r)[28]),"=r"((r)[29]),"=r"((r)[30]),"=r"((r)[31])               \
        : "r"(a))
#define MB_WAIT(mb, par) do {                                                   \
    uint32_t _m = (mb), _p = (par), _d;                                         \
    asm volatile("{ .reg .pred p; mbarrier.try_wait.parity.acquire.cta.shared::cta.b64 p, [%1], %2; selp.b32 %0, 1, 0, p; }" \
                 : "=r"(_d) : "r"(_m), "r"(_p) : "memory");                     \
    if (!_d) {                                                                  \
        asm volatile("{ .reg .pred P1; W%=: mbarrier.try_wait.parity.acquire.cta.shared::cta.b64 P1, [%0], %1, 0x989680; @P1 bra.uni D%=; bra.uni W%=; D%=: }" \
                     :: "r"(_m), "r"(_p) : "memory");                           \
    }                                                                           \
} while (0)
#else
__device__ __forceinline__ void mma_bf16_ss(uint32_t, uint64_t, uint64_t, uint32_t, uint32_t) {}
#define TC_ALLOC(sm, n)   ((void)0)
#define TC_DEALLOC(t, n)  ((void)0)
#define TC_COMMIT(mb)     ((void)0)
#define TC_FENCE_AFTER()  ((void)0)
#define TC_FENCE_BEFORE() ((void)0)
#define TC_WAIT_LD()      ((void)0)
#define LDTM32(r, a)      do { _Pragma("unroll") for (int _i = 0; _i < 32; _i++) (r)[_i] = 0u; } while (0)
#define MB_WAIT(mb, par)  ((void)0)
#endif

#define MB_INIT(mb, c)   asm volatile("mbarrier.init.shared.b64 [%0], %1;" :: "r"(mb), "r"((uint32_t)(c)) : "memory")
#define MB_INVAL(mb)     asm volatile("mbarrier.inval.shared.b64 [%0];" :: "r"(mb) : "memory")
#define FENCE_ASYNC()    asm volatile("fence.proxy.async.shared::cta;" ::: "memory")
#define CP_ASYNC16(dst, src) asm volatile("cp.async.ca.shared.global [%0], [%1], 16;" :: "r"(dst), "l"(src) : "memory")
#define CP_COMMIT()      asm volatile("cp.async.commit_group;" ::: "memory")
#define CP_WAIT0()       asm volatile("cp.async.wait_group 0;" ::: "memory")

// ---------------- dtype detection ----------------
__global__ void detect_k(const unsigned int* __restrict__ e) {
    unsigned acc = 0;
    for (int i = 1; i < 128; i += 2) acc |= e[i];
    g_i64flag = (acc == 0u) ? 1 : 0;
}

// ---------------- weight split fp32 -> bf16 hi/lo ----------------
__global__ void wconv_k(const float* __restrict__ W1, const float* __restrict__ W2) {
    int i = blockIdx.x * 256 + threadIdx.x;
    const int tot = NLAYER * 256 * 128;
    if (i >= tot) return;
    int l = i / (256 * 128), rem = i % (256 * 128);
    {
        int n = rem / 128, k = rem % 128;
        float w = W1[l * 32768 + k * 256 + n];
        __nv_bfloat16 h = __float2bfloat16(w);
        g_b1hi[i] = h;
        g_b1lo[i] = __float2bfloat16(w - __bfloat162float(h));
    }
    {
        int n = rem / 256, k = rem % 256;
        float w = W2[l * 32768 + k * 128 + n];
        __nv_bfloat16 h = __float2bfloat16(w);
        g_b2hi[i] = h;
        g_b2lo[i] = __float2bfloat16(w - __bfloat162float(h));
    }
}

// ---------------- zero (grid-stride; covers n) ----------------
__global__ void zero_k(int n) {
    int tot = (n > GCNT * 128) ? n : GCNT * 128;
    for (int i = blockIdx.x * blockDim.x + threadIdx.x; i < tot;
         i += gridDim.x * blockDim.x) {
        if (i < 256) { g_ssum[i] = 0.f; g_ssq[i] = 0.f; }
        if (i < 128) { g_ssum2[i] = 0.f; g_ssq2[i] = 0.f; }
        if (i < GCNT * 128) { g_ps[i] = 0.f; g_pmx[i] = 0.f; }
        if (i < GCNT) g_cnt[i] = 0.f;
        if (i < n) g_deg[i] = 0;
    }
}

// ---------------- CSR build ----------------
__global__ void count_k(const void* __restrict__ ei, long long E) {
    long long e = (long long)blockIdx.x * blockDim.x + threadIdx.x;
    if (e >= E) return;
    int d;
    if (g_i64flag) d = (int)((const long long*)ei)[E + e];
    else           d = ((const int*)ei)[E + e];
    atomicAdd(&g_deg[d], 1);
}

__global__ void scanA_k(int n) {
    __shared__ int sred[256];
    int blk = blockIdx.x, t = threadIdx.x;
    int base = blk * 1024 + t * 4;
    int s = 0;
#pragma unroll
    for (int j = 0; j < 4; j++) {
        int idx = base + j;
        if (idx < n) s += g_deg[idx];
    }
    sred[t] = s;
    __syncthreads();
    for (int o = 128; o > 0; o >>= 1) {
        if (t < o) sred[t] += sred[t + o];
        __syncthreads();
    }
    if (t == 0) g_bsum[blk] = sred[0];
}

__global__ void scanB_k(int nblk) {
    if (threadIdx.x == 0) {
        int run = 0;
        for (int i = 0; i < nblk; i++) { g_bscn[i] = run; run += g_bsum[i]; }
    }
}

__global__ void scanC_k(int n) {
    __shared__ int sth[256];
    int blk = blockIdx.x, t = threadIdx.x;
    int base = blk * 1024 + t * 4;
    int v[4];
    int s = 0;
#pragma unroll
    for (int j = 0; j < 4; j++) {
        int idx = base + j;
        v[j] = (idx < n) ? g_deg[idx] : 0;
        s += v[j];
    }
    sth[t] = s;
    __syncthreads();
    for (int o = 1; o < 256; o <<= 1) {
        int add = (t >= o) ? sth[t - o] : 0;
        __syncthreads();
        sth[t] += add;
        __syncthreads();
    }
    int tpre = (t > 0 ? sth[t - 1] : 0) + g_bscn[blk];
#pragma unroll
    for (int j = 0; j < 4; j++) {
        int idx = base + j;
        if (idx < n) { g_off[idx] = tpre; g_cur[idx] = tpre; }
        tpre += v[j];
    }
}

__global__ void fill_k(const void* __restrict__ ei, long long E) {
    long long e = (long long)blockIdx.x * blockDim.x + threadIdx.x;
    if (e >= E) return;
    int s, d;
    if (g_i64flag) {
        const long long* p = (const long long*)ei;
        s = (int)p[e]; d = (int)p[E + e];
    } else {
        const int* p = (const int*)ei;
        s = p[e]; d = p[E + e];
    }
    int pos = atomicAdd(&g_cur[d], 1);
    if (pos < EMAX) g_csr[pos] = s;
}

__device__ __forceinline__ uint32_t pack_bf16x2(float a, float b) {
    __nv_bfloat162 h = __float22bfloat162_rn(make_float2(a, b));
    return *reinterpret_cast<uint32_t*>(&h);
}

// ---------------- CSR aggregation + bf16 split + swizzled store ----------------
// warp per node: r = (1+eps)*f(SRC[node]) + sum f(SRC[nbr]); f = bnrelu or id.
// BN=true: compute outer-BN scale/shift in-warp from raw g_ssum2/g_ssq2;
//          block 0 also zeroes g_ssum/g_ssq for the upcoming pass1.
template<bool BN>
__global__ void __launch_bounds__(256) agg_k(
    const float* __restrict__ SRC, const float* __restrict__ epsp, int l, int n,
    const float* __restrict__ gamma, const float* __restrict__ beta, float invM) {
    if (BN && blockIdx.x == 0) {
        g_ssum[threadIdx.x] = 0.f;
        g_ssq[threadIdx.x]  = 0.f;
    }
    int node = (int)(((long long)blockIdx.x * blockDim.x + threadIdx.x) >> 5);
    int lane = threadIdx.x & 31;
    if (node >= n) return;
    float e = 1.0f + epsp[l];

    float sc0, sc1, sc2, sc3, sh0, sh1, sh2, sh3;
    if (BN) {
        int c = lane * 4;
#pragma unroll
        for (int j = 0; j < 4; j++) {
            float m   = g_ssum2[c + j] * invM;
            float var = g_ssq2[c + j] * invM - m * m;
            float sc  = gamma[c + j] * rsqrtf(var + 1e-5f);
            float sh  = beta[c + j] - m * sc;
            if (j == 0) { sc0 = sc; sh0 = sh; }
            else if (j == 1) { sc1 = sc; sh1 = sh; }
            else if (j == 2) { sc2 = sc; sh2 = sh; }
            else { sc3 = sc; sh3 = sh; }
        }
    }
#define FBN(v)                                                                   \
    if (BN) {                                                                    \
        v.x = fmaxf(fmaf(v.x, sc0, sh0), 0.f);                                   \
        v.y = fmaxf(fmaf(v.y, sc1, sh1), 0.f);                                   \
        v.z = fmaxf(fmaf(v.z, sc2, sh2), 0.f);                                   \
        v.w = fmaxf(fmaf(v.w, sc3, sh3), 0.f);                                   \
    }

    int beg = g_off[node];
    int deg = g_deg[node];

    float4 self = ((const float4*)SRC)[(size_t)node * 32 + lane];
    FBN(self);
    float4 a0 = make_float4(self.x * e, self.y * e, self.z * e, self.w * e);
    float4 a1 = make_float4(0.f, 0.f, 0.f, 0.f);
    float4 a2 = make_float4(0.f, 0.f, 0.f, 0.f);
    float4 a3 = make_float4(0.f, 0.f, 0.f, 0.f);

    int i = 0;
    for (; i + 4 <= deg; i += 4) {
        int s0 = g_csr[beg + i];
        int s1 = g_csr[beg + i + 1];
        int s2 = g_csr[beg + i + 2];
        int s3 = g_csr[beg + i + 3];
        float4 v0 = ((const float4*)SRC)[(size_t)s0 * 32 + lane];
        float4 v1 = ((const float4*)SRC)[(size_t)s1 * 32 + lane];
        float4 v2 = ((const float4*)SRC)[(size_t)s2 * 32 + lane];
        float4 v3 = ((const float4*)SRC)[(size_t)s3 * 32 + lane];
        FBN(v0); FBN(v1); FBN(v2); FBN(v3);
        a0.x += v0.x; a0.y += v0.y; a0.z += v0.z; a0.w += v0.w;
        a1.x += v1.x; a1.y += v1.y; a1.z += v1.z; a1.w += v1.w;
        a2.x += v2.x; a2.y += v2.y; a2.z += v2.z; a2.w += v2.w;
        a3.x += v3.x; a3.y += v3.y; a3.z += v3.z; a3.w += v3.w;
    }
    if (i < deg) {
        int rem = deg - i;
        int s0 = g_csr[beg + i];
        int s1 = g_csr[beg + ((rem > 1) ? i + 1 : i)];
        int s2 = g_csr[beg + ((rem > 2) ? i + 2 : i)];
        float4 v0 = ((const float4*)SRC)[(size_t)s0 * 32 + lane];
        float4 v1 = ((const float4*)SRC)[(size_t)s1 * 32 + lane];
        float4 v2 = ((const float4*)SRC)[(size_t)s2 * 32 + lane];
        FBN(v0); FBN(v1); FBN(v2);
        a1.x += v0.x; a1.y += v0.y; a1.z += v0.z; a1.w += v0.w;
        if (rem > 1) { a2.x += v1.x; a2.y += v1.y; a2.z += v1.z; a2.w += v1.w; }
        if (rem > 2) { a3.x += v2.x; a3.y += v2.y; a3.z += v2.z; a3.w += v2.w; }
    }
#undef FBN
    float4 r;
    r.x = (a0.x + a1.x) + (a2.x + a3.x);
    r.y = (a0.y + a1.y) + (a2.y + a3.y);
    r.z = (a0.z + a1.z) + (a2.z + a3.z);
    r.w = (a0.w + a1.w) + (a2.w + a3.w);

    uint32_t h0 = pack_bf16x2(r.x, r.y);
    uint32_t h1 = pack_bf16x2(r.z, r.w);
    __nv_bfloat162 hb0 = *reinterpret_cast<__nv_bfloat162*>(&h0);
    __nv_bfloat162 hb1 = *reinterpret_cast<__nv_bfloat162*>(&h1);
    float2 hr0 = __bfloat1622float2(hb0);
    float2 hr1 = __bfloat1622float2(hb1);
    uint32_t l0 = pack_bf16x2(r.x - hr0.x, r.y - hr0.y);
    uint32_t l1 = pack_bf16x2(r.z - hr1.x, r.w - hr1.y);

    int T = node >> 7, rr = node & 127;
    int c8 = lane >> 4;
    int g8 = (lane >> 1) & 7;
    int half = lane & 1;
    size_t base = ((size_t)T * 2 + c8) * 16384
                + SW128((uint32_t)(rr * 128 + g8 * 16)) + half * 8;
    *(uint2*)(g_ahi + base) = make_uint2(h0, h1);
    *(uint2*)(g_alo + base) = make_uint2(l0, l1);
}

// ================== persistent fused layer kernel ==================
// PASS 1: y = A@W1 + b1 in TMEM; stats -> g_ssum/g_ssq. y NOT stored.
//          Block 0 zeroes g_ssum2/g_ssq2 for the upcoming pass2.
// PASS 2: recompute y, BN+ReLU in-register, GEMM2 -> h2 + stats (g_ssum2).
// Persistent: each CTA loops over tiles with stride gridDim.x.
#define P_PTR   0
#define P_MBAR  16
#define P_SC    32
#define P_SH    1056
#define P_SB    2080
#define P_SSL   3104
#define P_SQL   4128
#define P_PSUM  5152
#define P_PSQ   6176
#define P_A1HI  8192
#define P_A1LO  24576
#define P_B1HI  40960
#define P_B1LO  73728
#define P_SMEM  106496
#define TG_IDESC 0x8200490u

template<int PASS>
__global__ void __launch_bounds__(256, 2) pass_k(
    const uint8_t* __restrict__ Ahi, const uint8_t* __restrict__ Alo,
    const __nv_bfloat16* __restrict__ B1hi, const __nv_bfloat16* __restrict__ B1lo,
    const __nv_bfloat16* __restrict__ B2hi, const __nv_bfloat16* __restrict__ B2lo,
    const float* __restrict__ b1, const float* __restrict__ b2,
    const float* __restrict__ g1, const float* __restrict__ be1, float invM,
    float* __restrict__ C, int M, int ntiles)
{
    extern __shared__ char smem[];
    const uint32_t sb = smem_u32(smem);
    const int t = threadIdx.x, wid = t >> 5, lid = t & 31;
    float* sSc = reinterpret_cast<float*>(smem + P_SC);
    float* sSh = reinterpret_cast<float*>(smem + P_SH);
    float* sB  = reinterpret_cast<float*>(smem + P_SB);
    float* ssl = reinterpret_cast<float*>(smem + P_SSL);
    float* sql = reinterpret_cast<float*>(smem + P_SQL);
    float* psum = reinterpret_cast<float*>(smem + P_PSUM);
    float* psq  = reinterpret_cast<float*>(smem + P_PSQ);
    float* statbuf = reinterpret_cast<float*>(smem + P_B1HI);

    if (PASS == 1 && blockIdx.x == 0 && t < 128) {
        g_ssum2[t] = 0.f;
        g_ssq2[t]  = 0.f;
    }
    if (wid == 0) TC_ALLOC(sb + P_PTR, 256);
    if (t == 0) MB_INIT(sb + P_MBAR, 1);
    if (PASS == 1) {
        sB[t] = b1[t];
    } else {
        float m   = g_ssum[t] * invM;
        float var = g_ssq[t] * invM - m * m;
        float sc  = g1[t] * rsqrtf(var + 1e-5f);
        sSc[t] = sc;
        sSh[t] = fmaf(b1[t] - m, sc, be1[t]);
        if (t < 128) sB[t] = b2[t];
    }
    __syncthreads();
    uint32_t tmem;
    asm volatile("ld.shared.b32 %0, [%1];" : "=r"(tmem) : "r"(sb + P_PTR));

    const uint64_t dA1hi = make_desc(sb + P_A1HI);
    const uint64_t dA1lo = make_desc(sb + P_A1LO);
    const uint64_t dB1hi = make_desc(sb + P_B1HI);
    const uint64_t dB1lo = make_desc(sb + P_B1LO);

    int pc = 0;

#define CPASYNC_A1(TILE, CH)                                                    \
    {                                                                           \
        size_t abase = ((size_t)(TILE) * 2 + (CH)) * 16384;                     \
        _Pragma("unroll")                                                       \
        for (int it = 0; it < 4; it++) {                                        \
            uint32_t o = (uint32_t)(t + it * 256) * 16;                         \
            CP_ASYNC16(sb + P_A1HI + o, Ahi + abase + o);                       \
            CP_ASYNC16(sb + P_A1LO + o, Alo + abase + o);                       \
        }                                                                       \
    }
#define CPASYNC_B1(CH)                                                          \
    {                                                                           \
        int kb_ = (CH) * 64;                                                    \
        _Pragma("unroll")                                                       \
        for (int it = 0; it < 8; it++) {                                        \
            int idx = t + it * 256;                                             \
            int r_ = idx >> 3, kg_ = idx & 7;                                   \
            uint32_t so_ = SW128((uint32_t)(r_ * 128 + kg_ * 16));              \
            size_t bo_ = (size_t)r_ * 128 + kb_ + kg_ * 8;                      \
            CP_ASYNC16(sb + P_B1HI + so_, B1hi + bo_);                          \
            CP_ASYNC16(sb + P_B1LO + so_, B1lo + bo_);                          \
        }                                                                       \
        CP_COMMIT();                                                            \
    }
#define MMA1_CHUNK(CH)                                                          \
    if (wid == 0 && elect_one()) {                                              \
        _Pragma("unroll")                                                       \
        for (int T = 0; T < 2; T++) {                                           \
            uint64_t bh = dB1hi + T * 1024;                                     \
            uint64_t bl = dB1lo + T * 1024;                                     \
            uint32_t dt = tmem + T * 128;                                       \
            _Pragma("unroll")                                                   \
            for (int s = 0; s < 4; s++)                                         \
                mma_bf16_ss(dt, dA1hi + s * 2, bh + s * 2, TG_IDESC,            \
                            ((CH) == 0 && s == 0) ? 0u : 1u);                   \
            _Pragma("unroll")                                                   \
            for (int s = 0; s < 4; s++)                                         \
                mma_bf16_ss(dt, dA1hi + s * 2, bl + s * 2, TG_IDESC, 1u);       \
            _Pragma("unroll")                                                   \
            for (int s = 0; s < 4; s++)                                         \
                mma_bf16_ss(dt, dA1lo + s * 2, bh + s * 2, TG_IDESC, 1u);       \
        }                                                                       \
        TC_COMMIT(sb + P_MBAR);                                                 \
    }

    for (int tile = blockIdx.x; tile < ntiles; tile += gridDim.x) {
        const int bm = tile * 128;

        // -------- phase 1: y = A @ W1 (2 k-chunks) --------
        CPASYNC_A1(tile, 0);
        CPASYNC_B1(0);
        CP_WAIT0();
        FENCE_ASYNC();
        __syncthreads();
        MMA1_CHUNK(0);
        MB_WAIT(sb + P_MBAR, pc & 1); pc++;
        CPASYNC_A1(tile, 1);
        CPASYNC_B1(1);
        CP_WAIT0();
        FENCE_ASYNC();
        __syncthreads();
        MMA1_CHUNK(1);
        MB_WAIT(sb + P_MBAR, pc & 1); pc++;
        TC_FENCE_AFTER();

        if (PASS == 1) {
            // -------- y stats only --------
            for (int pr = 0; pr < 4; pr++) {
                if (wid < 4) {
                    int r = wid * 32 + lid;
                    int grow = bm + r;
                    uint32_t r0[32], r1[32];
                    LDTM32(r0, tmem + pr * 64);
                    LDTM32(r1, tmem + pr * 64 + 32);
                    TC_WAIT_LD();
                    float v0[32], v1[32];
#pragma unroll
                    for (int i = 0; i < 32; i++) {
                        v0[i] = (grow < M) ? __uint_as_float(r0[i]) + sB[pr * 64 + i]      : 0.f;
                        v1[i] = (grow < M) ? __uint_as_float(r1[i]) + sB[pr * 64 + 32 + i] : 0.f;
                    }
#pragma unroll
                    for (int i = 0; i < 32; i++) {
                        statbuf[r * 66 + i]      = v0[i];
                        statbuf[r * 66 + 32 + i] = v1[i];
                    }
                }
                __syncthreads();
                {
                    int c = t & 63, h = t >> 6;
                    float s = 0.f, q = 0.f;
#pragma unroll 8
                    for (int rr = 0; rr < 32; rr++) {
                        float v = statbuf[(h * 32 + rr) * 66 + c];
                        s += v;
                        q = fmaf(v, v, q);
                    }
                    psum[h * 64 + c] = s;
                    psq[h * 64 + c]  = q;
                }
                __syncthreads();
                if (t < 64) {
                    ssl[pr * 64 + t] = psum[t] + psum[64 + t] + psum[128 + t] + psum[192 + t];
                    sql[pr * 64 + t] = psq[t]  + psq[64 + t]  + psq[128 + t]  + psq[192 + t];
                }
                __syncthreads();
            }
            if (wid < 4) TC_FENCE_BEFORE();
            __syncthreads();
            atomicAdd(&g_ssum[t], ssl[t]);
            atomicAdd(&g_ssq[t],  sql[t]);
            __syncthreads();
        } else {
            // -------- phase 2: h2 = bnrelu(y) @ W2 + b2 --------
            const uint64_t dB2hi = make_desc(sb + P_A1HI);
            const uint64_t dB2lo = make_desc(sb + P_A1LO);

#define CPASYNC_B2_HALF(CH)                                                     \
    {                                                                           \
        int kb_ = (CH) * 64;                                                    \
        _Pragma("unroll")                                                       \
        for (int it = 0; it < 8; it++) {                                        \
            int idx = (t - 128) + it * 128;                                     \
            int r_ = idx >> 3, kg_ = idx & 7;                                   \
            uint32_t so_ = SW128((uint32_t)(r_ * 128 + kg_ * 16));              \
            size_t bo_ = (size_t)r_ * 256 + kb_ + kg_ * 8;                      \
            CP_ASYNC16(sb + P_A1HI + so_, B2hi + bo_);                          \
            CP_ASYNC16(sb + P_A1LO + so_, B2lo + bo_);                          \
        }                                                                       \
        CP_COMMIT();                                                            \
        CP_WAIT0();                                                             \
    }
#define CPASYNC_B2_ALL(CH)                                                      \
    {                                                                           \
        int kb_ = (CH) * 64;                                                    \
        _Pragma("unroll")                                                       \
        for (int it = 0; it < 4; it++) {                                        \
            int idx = t + it * 256;                                             \
            int r_ = idx >> 3, kg_ = idx & 7;                                   \
            uint32_t so_ = SW128((uint32_t)(r_ * 128 + kg_ * 16));              \
            size_t bo_ = (size_t)r_ * 256 + kb_ + kg_ * 8;                      \
            CP_ASYNC16(sb + P_A1HI + so_, B2hi + bo_);                          \
            CP_ASYNC16(sb + P_A1LO + so_, B2lo + bo_);                          \
        }                                                                       \
        CP_COMMIT();                                                            \
        CP_WAIT0();                                                             \
    }
#define MMA2(SLOT, EN0)                                                         \
    if (wid == 0 && elect_one()) {                                              \
        uint64_t ah = make_desc(sb + P_B1HI + (SLOT) * 16384);                  \
        uint64_t al = make_desc(sb + P_B1LO + (SLOT) * 16384);                  \
        _Pragma("unroll")                                                       \
        for (int s = 0; s < 4; s++)                                             \
            mma_bf16_ss(tmem, ah + s * 2, dB2hi + s * 2, TG_IDESC,              \
                        ((EN0) && s == 0) ? 0u : 1u);                           \
        _Pragma("unroll")                                                       \
        for (int s = 0; s < 4; s++)                                             \
            mma_bf16_ss(tmem, ah + s * 2, dB2lo + s * 2, TG_IDESC, 1u);         \
        _Pragma("unroll")                                                       \
        for (int s = 0; s < 4; s++)                                             \
            mma_bf16_ss(tmem, al + s * 2, dB2hi + s * 2, TG_IDESC, 1u);         \
        TC_COMMIT(sb + P_MBAR);                                                 \
    }

#pragma unroll
            for (int half = 0; half < 2; half++) {
                if (wid < 4) {
                    int r = wid * 32 + lid;
#pragma unroll
                    for (int p2 = 0; p2 < 2; p2++) {
                        int b0 = half * 4 + p2 * 2;
                        uint32_t r0[32], r1[32];
                        LDTM32(r0, tmem + b0 * 32);
                        LDTM32(r1, tmem + (b0 + 1) * 32);
                        TC_WAIT_LD();
                        float v[64];
#pragma unroll
                        for (int i = 0; i < 32; i++) {
                            int c0 = b0 * 32 + i, c1 = (b0 + 1) * 32 + i;
                            v[i]      = fmaxf(fmaf(__uint_as_float(r0[i]), sSc[c0], sSh[c0]), 0.f);
                            v[32 + i] = fmaxf(fmaf(__uint_as_float(r1[i]), sSc[c1], sSh[c1]), 0.f);
                        }
#pragma unroll
                        for (int bb = 0; bb < 2; bb++) {
                            int blk = b0 + bb;
                            int slot = (blk >> 1) & 1;
                            const float* vv = v + bb * 32;
#pragma unroll
                            for (int q = 0; q < 4; q++) {
                                uint32_t h[4], lo[4];
#pragma unroll
                                for (int p = 0; p < 4; p++) {
                                    float a0 = vv[q * 8 + p * 2], a1 = vv[q * 8 + p * 2 + 1];
                                    h[p] = pack_bf16x2(a0, a1);
                                    __nv_bfloat162 hb = *reinterpret_cast<__nv_bfloat162*>(&h[p]);
                                    float2 hr = __bfloat1622float2(hb);
                                    lo[p] = pack_bf16x2(a0 - hr.x, a1 - hr.y);
                                }
                                uint32_t so = SW128((uint32_t)(r * 128 + (blk & 1) * 64 + q * 16));
                                *(uint4*)(smem + P_B1HI + slot * 16384 + so) = make_uint4(h[0], h[1], h[2], h[3]);
                                *(uint4*)(smem + P_B1LO + slot * 16384 + so) = make_uint4(lo[0], lo[1], lo[2], lo[3]);
                            }
                        }
                    }
                    TC_FENCE_BEFORE();
                } else {
                    CPASYNC_B2_HALF(2 * half);
                }
                FENCE_ASYNC();
                __syncthreads();
                MMA2(0, half == 0);
                MB_WAIT(sb + P_MBAR, pc & 1); pc++;
                CPASYNC_B2_ALL(2 * half + 1);
                FENCE_ASYNC();
                __syncthreads();
                MMA2(1, false);
                MB_WAIT(sb + P_MBAR, pc & 1); pc++;
                TC_FENCE_AFTER();
            }

#undef CPASYNC_B2_HALF
#undef CPASYNC_B2_ALL
#undef MMA2

            // -------- final epilogue: h2 --------
            for (int pr = 0; pr < 2; pr++) {
                if (wid < 4) {
                    int r = wid * 32 + lid;
                    int grow = bm + r;
                    uint32_t r0[32], r1[32];
                    LDTM32(r0, tmem + pr * 64);
                    LDTM32(r1, tmem + pr * 64 + 32);
                    TC_WAIT_LD();
                    float v0[32], v1[32];
#pragma unroll
                    for (int i = 0; i < 32; i++) {
                        v0[i] = __uint_as_float(r0[i]) + sB[pr * 64 + i];
                        v1[i] = __uint_as_float(r1[i]) + sB[pr * 64 + 32 + i];
                    }
                    if (grow < M) {
                        float* cp = C + (size_t)grow * 128 + pr * 64;
#pragma unroll
                        for (int q = 0; q < 8; q++) {
                            *(float4*)(cp + q * 4)      = *(float4*)(v0 + q * 4);
                            *(float4*)(cp + 32 + q * 4) = *(float4*)(v1 + q * 4);
                        }
                    } else {
#pragma unroll
                        for (int i = 0; i < 32; i++) { v0[i] = 0.f; v1[i] = 0.f; }
                    }
#pragma unroll
                    for (int i = 0; i < 32; i++) {
                        statbuf[r * 66 + i]      = v0[i];
                        statbuf[r * 66 + 32 + i] = v1[i];
                    }
                }
                __syncthreads();
                {
                    int c = t & 63, h = t >> 6;
                    float s = 0.f, q = 0.f;
#pragma unroll 8
                    for (int rr = 0; rr < 32; rr++) {
                        float vv = statbuf[(h * 32 + rr) * 66 + c];
                        s += vv;
                        q = fmaf(vv, vv, q);
                    }
                    psum[h * 64 + c] = s;
                    psq[h * 64 + c]  = q;
                }
                __syncthreads();
                if (t < 64) {
                    ssl[pr * 64 + t] = psum[t] + psum[64 + t] + psum[128 + t] + psum[192 + t];
                    sql[pr * 64 + t] = psq[t]  + psq[64 + t]  + psq[128 + t]  + psq[192 + t];
                }
                __syncthreads();
            }
            if (wid < 4) TC_FENCE_BEFORE();
            __syncthreads();
            if (t < 128) {
                atomicAdd(&g_ssum2[t], ssl[t]);
                atomicAdd(&g_ssq2[t],  sql[t]);
            }
            __syncthreads();
        }
    }

#undef CPASYNC_A1
#undef CPASYNC_B1
#undef MMA1_CHUNK

    if (t == 0) MB_INVAL(sb + P_MBAR);
    if (wid == 0) TC_DEALLOC(tmem, 256);
}

// ---------------- readout pooling (computes outer BN inline) ----------------
__global__ void pool_k(const void* __restrict__ batch, int n,
                       const float* __restrict__ gamma, const float* __restrict__ beta,
                       float invM) {
    long long t = (long long)blockIdx.x * blockDim.x + threadIdx.x;
    long long i = t >> 5;
    if (i >= n) return;
    int lane = (int)(t & 31);
    long long g;
    if (g_i64flag) g = ((const long long*)batch)[i];
    else           g = (long long)((const int*)batch)[i];
    int c = lane * 4;
    float sc[4], sh[4];
#pragma unroll
    for (int j = 0; j < 4; j++) {
        float m   = g_ssum2[c + j] * invM;
        float var = g_ssq2[c + j] * invM - m * m;
        sc[j] = gamma[c + j] * rsqrtf(var + 1e-5f);
        sh[j] = beta[c + j] - m * sc[j];
    }
    float4 v = ((const float4*)g_h2)[i * 32 + lane];
    float r0 = fmaxf(fmaf(v.x, sc[0], sh[0]), 0.f);
    float r1 = fmaxf(fmaf(v.y, sc[1], sh[1]), 0.f);
    float r2 = fmaxf(fmaf(v.z, sc[2], sh[2]), 0.f);
    float r3 = fmaxf(fmaf(v.w, sc[3], sh[3]), 0.f);
    float* ps = g_ps + g * 128 + c;
    asm volatile("red.global.add.v4.f32 [%0], {%1, %2, %3, %4};"
                 :: "l"(ps), "f"(r0), "f"(r1), "f"(r2), "f"(r3) : "memory");
    unsigned int* mx = (unsigned int*)(g_pmx + g * 128 + c);
    atomicMax(mx + 0, __float_as_uint(r0));
    atomicMax(mx + 1, __float_as_uint(r1));
    atomicMax(mx + 2, __float_as_uint(r2));
    atomicMax(mx + 3, __float_as_uint(r3));
    if (lane == 0) atomicAdd(&g_cnt[g], 1.0f);
}

// ---------------- classifier ----------------
__global__ void cgemm1_k(const float* __restrict__ cW1, const float* __restrict__ cb1) {
    int g = blockIdx.x;
    int j = threadIdx.x;
    __shared__ float z[384];
    float cnt = fmaxf(g_cnt[g], 1.0f);
    float sv = g_ps[g * 128 + j];
    z[j]       = sv;
    z[128 + j] = sv / cnt;
    z[256 + j] = g_pmx[g * 128 + j];
    __syncthreads();
    float acc = cb1[j];
#pragma unroll 8
    for (int k = 0; k < 384; k++)
        acc = fmaf(z[k], cW1[k * 128 + j], acc);
    g_z1[g * 128 + j] = acc;
}

__global__ void cstats_k(const float* __restrict__ cg, const float* __restrict__ cbeta) {
    int j = threadIdx.x;
    float s = 0.f, q = 0.f;
    for (int g = 0; g < GCNT; g++) {
        float v = g_z1[g * 128 + j];
        s += v; q += v * v;
    }
    float m   = s * (1.0f / GCNT);
    float var = q * (1.0f / GCNT) - m * m;
    float sc  = cg[j] * rsqrtf(var + 1e-5f);
    g_scale[j] = sc;
    g_shift[j] = cbeta[j] - m * sc;
}

__global__ void chead_k(const float* __restrict__ cW2, const float* __restrict__ cb2,
                        const float* __restrict__ cW3, const float* __restrict__ cb3,
                        float* __restrict__ out) {
    int g = blockIdx.x;
    int j = threadIdx.x;
    __shared__ float a[128];
    __shared__ float z2[64];
    for (int k = j; k < 128; k += 64)
        a[k] = fmaxf(fmaf(g_z1[g * 128 + k], g_scale[k], g_shift[k]), 0.f);
    __syncthreads();
    float acc = cb2[j];
#pragma unroll 8
    for (int k = 0; k < 128; k++)
        acc = fmaf(a[k], cW2[k * 64 + j], acc);
    z2[j] = fmaxf(acc, 0.f);
    __syncthreads();
    if (j < 2) {
        float o = cb3[j];
#pragma unroll 8
        for (int k = 0; k < 64; k++)
            o = fmaf(z2[k], cW3[k * 2 + j], o);
        out[g * 2 + j] = o;
    }
}

// ---------------- launcher ----------------
extern "C" void kernel_launch(void* const* d_in, const int* in_sizes, int n_in,
                              void* d_out, int out_size) {
    const float* x     = (const float*)d_in[0];
    const void*  ei    = d_in[1];
    const void*  batch = d_in[2];
    int base = (in_sizes[3] == 1) ? 4 : 3;
    const float* W1    = (const float*)d_in[base + 0];
    const float* b1    = (const float*)d_in[base + 1];
    const float* g1    = (const float*)d_in[base + 2];
    const float* be1   = (const float*)d_in[base + 3];
    const float* W2    = (const float*)d_in[base + 4];
    const float* b2    = (const float*)d_in[base + 5];
    const float* gbn   = (const float*)d_in[base + 6];
    const float* bbn   = (const float*)d_in[base + 7];
    const float* eps   = (const float*)d_in[base + 8];
    const float* cW1   = (const float*)d_in[base + 9];
    const float* cb1   = (const float*)d_in[base + 10];
    const float* cg    = (const float*)d_in[base + 11];
    const float* cbeta = (const float*)d_in[base + 12];
    const float* cW2   = (const float*)d_in[base + 13];
    const float* cb2   = (const float*)d_in[base + 14];
    const float* cW3   = (const float*)d_in[base + 15];
    const float* cb3   = (const float*)d_in[base + 16];

    int n = in_sizes[0] / 128;
    long long E = (long long)in_sizes[1] / 2;
    int n32 = n * 32;
    int nb = (n32 + 255) / 256;
    int gx = (n + 127) / 128;
    int pgrid = (gx < 296) ? gx : 296;
    int eblk = (int)((E + 255) / 256);
    int nscan = (n + 1023) / 1024;
    int ablk = (n * 32 + 255) / 256;
    float invM = 1.0f / (float)n;

    static int smem_set = 0;
    if (!smem_set) {
        cudaFuncSetAttribute(pass_k<1>, cudaFuncAttributeMaxDynamicSharedMemorySize, P_SMEM);
        cudaFuncSetAttribute(pass_k<2>, cudaFuncAttributeMaxDynamicSharedMemorySize, P_SMEM);
        smem_set = 1;
    }

    float *p_h2;
    uint8_t *p_ahi, *p_alo;
    __nv_bfloat16 *p_b1hi, *p_b1lo, *p_b2hi, *p_b2lo;
    cudaGetSymbolAddress((void**)&p_h2,  g_h2);
    cudaGetSymbolAddress((void**)&p_ahi, g_ahi);
    cudaGetSymbolAddress((void**)&p_alo, g_alo);
    cudaGetSymbolAddress((void**)&p_b1hi, g_b1hi);
    cudaGetSymbolAddress((void**)&p_b1lo, g_b1lo);
    cudaGetSymbolAddress((void**)&p_b2hi, g_b2hi);
    cudaGetSymbolAddress((void**)&p_b2lo, g_b2lo);

    detect_k<<<1, 1>>>((const unsigned int*)ei);
    wconv_k<<<(NLAYER * 256 * 128 + 255) / 256, 256>>>(W1, W2);
    zero_k<<<512, 256>>>(n);

    // CSR build (once; edges shared by all layers)
    count_k<<<eblk, 256>>>(ei, E);
    scanA_k<<<nscan, 256>>>(n);
    scanB_k<<<1, 32>>>(nscan);
    scanC_k<<<nscan, 256>>>(n);
    fill_k<<<eblk, 256>>>(ei, E);

    for (int l = 0; l < 4; l++) {
        if (l == 0)
            agg_k<false><<<ablk, 256>>>(x, eps, l, n, nullptr, nullptr, invM);
        else
            agg_k<true><<<ablk, 256>>>(p_h2, eps, l, n,
                                       gbn + (l - 1) * 128, bbn + (l - 1) * 128, invM);

        pass_k<1><<<pgrid, 256, P_SMEM>>>(
            p_ahi, p_alo,
            p_b1hi + (size_t)l * 32768, p_b1lo + (size_t)l * 32768,
            p_b2hi + (size_t)l * 32768, p_b2lo + (size_t)l * 32768,
            b1 + l * 256, b2 + l * 128, g1 + l * 256, be1 + l * 256, invM,
            nullptr, n, gx);
        pass_k<2><<<pgrid, 256, P_SMEM>>>(
            p_ahi, p_alo,
            p_b1hi + (size_t)l * 32768, p_b1lo + (size_t)l * 32768,
            p_b2hi + (size_t)l * 32768, p_b2lo + (size_t)l * 32768,
            b1 + l * 256, b2 + l * 128, g1 + l * 256, be1 + l * 256, invM,
            p_h2, n, gx);
    }

    pool_k<<<nb, 256>>>(batch, n, gbn + 3 * 128, bbn + 3 * 128, invM);
    cgemm1_k<<<GCNT, 128>>>(cW1, cb1);
    cstats_k<<<1, 128>>>(cg, cbeta);
    chead_k<<<GCNT, 64>>>(cW2, cb2, cW3, cb3, (float*)d_out);
}

// round 13
// speedup vs baseline: 1.3014x; 1.0380x over previous
#include <cuda_runtime.h>
#include <cuda_bf16.h>
#include <cstdint>
#include <cstddef>

// Problem constants (fixed shapes)
#define NMAX 100000
#define EMAX 500000
#define GCNT 512
#define NLAYER 4
#define NTILE ((NMAX + 127) / 128)   // 782

// tcgen05 only exists in the arch-specific (sm_103a) device pass.
#if defined(__CUDA_ARCH__) && defined(__CUDA_ARCH_FEAT_SM103_ALL)
#define HAS_TC 1
#else
#define HAS_TC 0
#endif

// ---------------- device scratch ----------------
__device__ float g_h2 [NMAX * 128];
// aggregated layer input, pre-split bf16 hi/lo, pre-swizzled smem image:
// [tile][chunk(2)][16KB image]  where image[SW128(row*128 + kg*16)]
__device__ uint8_t g_ahi[(size_t)NTILE * 32768];
__device__ uint8_t g_alo[(size_t)NTILE * 32768];
__device__ float g_ssum [256];
__device__ float g_ssq  [256];
__device__ float g_ssum2[128];
__device__ float g_ssq2 [128];
__device__ float g_scale[256];   // used by classifier only now
__device__ float g_shift[256];
__device__ float g_ps [GCNT * 128];
__device__ float g_pmx[GCNT * 128];
__device__ float g_cnt[GCNT];
__device__ float g_z1 [GCNT * 128];
__device__ int   g_i64flag;

// CSR (built once per launch; edges fixed across layers)
__device__ int g_deg [NMAX];
__device__ int g_off [NMAX];
__device__ int g_cur [NMAX];
__device__ int g_csr [EMAX];
__device__ int g_bsum[128];
__device__ int g_bscn[128];

// pre-split weights, B layout: [layer][n(out)][k(in)] bf16, K-major rows
__device__ __nv_bfloat16 g_b1hi[NLAYER * 256 * 128];
__device__ __nv_bfloat16 g_b1lo[NLAYER * 256 * 128];
__device__ __nv_bfloat16 g_b2hi[NLAYER * 128 * 256];
__device__ __nv_bfloat16 g_b2lo[NLAYER * 128 * 256];

// ---------------- PTX helpers ----------------
__device__ __forceinline__ uint32_t smem_u32(const void* p) {
    uint32_t a;
    asm("{ .reg .u64 t; cvta.to.shared.u64 t, %1; cvt.u32.u64 %0, t; }" : "=r"(a) : "l"(p));
    return a;
}
__device__ __forceinline__ uint32_t elect_one() {
    uint32_t p;
    asm volatile("{ .reg .pred p; elect.sync _|p, 0xFFFFFFFF; selp.b32 %0, 1, 0, p; }" : "=r"(p));
    return p;
}
#define SW128(o) ((o) ^ (((o) >> 3) & 0x70))
static __device__ __forceinline__ uint64_t make_desc(uint32_t addr) {
    return ((uint64_t)2 << 61) | ((uint64_t)1 << 46) | ((uint64_t)64 << 32) |
           ((uint64_t)1 << 16) | ((uint64_t)(addr >> 4) & 0x3FFF);
}

#if HAS_TC
__device__ __forceinline__ void mma_bf16_ss(uint32_t d, uint64_t a, uint64_t b,
                                            uint32_t idesc, uint32_t en) {
    asm volatile(
        "{\n\t.reg .pred p;\n\tsetp.ne.u32 p, %4, 0;\n\t"
        "tcgen05.mma.cta_group::1.kind::f16 [%0], %1, %2, %3, {%5, %5, %5, %5}, p;\n\t}"
        :: "r"(d), "l"(a), "l"(b), "r"(idesc), "r"(en), "r"(0u) : "memory");
}
#define TC_ALLOC(sm, n)  asm volatile("tcgen05.alloc.cta_group::1.sync.aligned.shared::cta.b32 [%0], %1;" :: "r"(sm), "r"((uint32_t)(n)) : "memory")
#define TC_DEALLOC(t, n) asm volatile("tcgen05.dealloc.cta_group::1.sync.aligned.b32 %0, %1;" :: "r"(t), "r"((uint32_t)(n)))
#define TC_COMMIT(mb)    asm volatile("tcgen05.commit.cta_group::1.mbarrier::arrive::one.shared::cluster.b64 [%0];" :: "r"(mb) : "memory")
#define TC_FENCE_AFTER() asm volatile("tcgen05.fence::after_thread_sync;" ::: "memory")
#define TC_FENCE_BEFORE() asm volatile("tcgen05.fence::before_thread_sync;" ::: "memory")
#define TC_WAIT_LD()     asm volatile("tcgen05.wait::ld.sync.aligned;" ::: "memory")
#define LDTM32(r, a)                                                            \
    asm volatile("tcgen05.ld.sync.aligned.32x32b.x32.b32 "                      \
        "{%0,%1,%2,%3,%4,%5,%6,%7,%8,%9,%10,%11,%12,%13,%14,%15,"               \
        "%16,%17,%18,%19,%20,%21,%22,%23,%24,%25,%26,%27,%28,%29,%30,%31}, [%32];" \
        : "=r"((r)[0]),"=r"((r)[1]),"=r"((r)[2]),"=r"((r)[3]),                  \
          "=r"((r)[4]),"=r"((r)[5]),"=r"((r)[6]),"=r"((r)[7]),                  \
          "=r"((r)[8]),"=r"((r)[9]),"=r"((r)[10]),"=r"((r)[11]),                \
          "=r"((r)[12]),"=r"((r)[13]),"=r"((r)[14]),"=r"((r)[15]),              \
          "=r"((r)[16]),"=r"((r)[17]),"=r"((r)[18]),"=r"((r)[19]),              \
          "=r"((r)[20]),"=r"((r)[21]),"=r"((r)[22]),"=r"((r)[23]),              \
          "=r"((r)[24]),"=r"((r)[25]),"=r"((r)[26]),"=r"((r)[27]),              \
          "=r"((r)[28]),"=r"((r)[29]),"=r"((r)[30]),"=r"((r)[31])               \
        : "r"(a))
#define MB_WAIT(mb, par) do {                                                   \
    uint32_t _m = (mb), _p = (par), _d;                                         \
    asm volatile("{ .reg .pred p; mbarrier.try_wait.parity.acquire.cta.shared::cta.b64 p, [%1], %2; selp.b32 %0, 1, 0, p; }" \
                 : "=r"(_d) : "r"(_m), "r"(_p) : "memory");                     \
    if (!_d) {                                                                  \
        asm volatile("{ .reg .pred P1; W%=: mbarrier.try_wait.parity.acquire.cta.shared::cta.b64 P1, [%0], %1, 0x989680; @P1 bra.uni D%=; bra.uni W%=; D%=: }" \
                     :: "r"(_m), "r"(_p) : "memory");                           \
    }                                                                           \
} while (0)
#else
__device__ __forceinline__ void mma_bf16_ss(uint32_t, uint64_t, uint64_t, uint32_t, uint32_t) {}
#define TC_ALLOC(sm, n)   ((void)0)
#define TC_DEALLOC(t, n)  ((void)0)
#define TC_COMMIT(mb)     ((void)0)
#define TC_FENCE_AFTER()  ((void)0)
#define TC_FENCE_BEFORE() ((void)0)
#define TC_WAIT_LD()      ((void)0)
#define LDTM32(r, a)      do { _Pragma("unroll") for (int _i = 0; _i < 32; _i++) (r)[_i] = 0u; } while (0)
#define MB_WAIT(mb, par)  ((void)0)
#endif

#define MB_INIT(mb, c)   asm volatile("mbarrier.init.shared.b64 [%0], %1;" :: "r"(mb), "r"((uint32_t)(c)) : "memory")
#define MB_INVAL(mb)     asm volatile("mbarrier.inval.shared.b64 [%0];" :: "r"(mb) : "memory")
#define FENCE_ASYNC()    asm volatile("fence.proxy.async.shared::cta;" ::: "memory")
#define CP_ASYNC16(dst, src) asm volatile("cp.async.ca.shared.global [%0], [%1], 16;" :: "r"(dst), "l"(src) : "memory")
#define CP_COMMIT()      asm volatile("cp.async.commit_group;" ::: "memory")
#define CP_WAIT0()       asm volatile("cp.async.wait_group 0;" ::: "memory")

// ---------------- dtype detection ----------------
__global__ void detect_k(const unsigned int* __restrict__ e) {
    unsigned acc = 0;
    for (int i = 1; i < 128; i += 2) acc |= e[i];
    g_i64flag = (acc == 0u) ? 1 : 0;
}

// ---------------- weight split fp32 -> bf16 hi/lo ----------------
__global__ void wconv_k(const float* __restrict__ W1, const float* __restrict__ W2) {
    int i = blockIdx.x * 256 + threadIdx.x;
    const int tot = NLAYER * 256 * 128;
    if (i >= tot) return;
    int l = i / (256 * 128), rem = i % (256 * 128);
    {
        int n = rem / 128, k = rem % 128;
        float w = W1[l * 32768 + k * 256 + n];
        __nv_bfloat16 h = __float2bfloat16(w);
        g_b1hi[i] = h;
        g_b1lo[i] = __float2bfloat16(w - __bfloat162float(h));
    }
    {
        int n = rem / 256, k = rem % 256;
        float w = W2[l * 32768 + k * 128 + n];
        __nv_bfloat16 h = __float2bfloat16(w);
        g_b2hi[i] = h;
        g_b2lo[i] = __float2bfloat16(w - __bfloat162float(h));
    }
}

// ---------------- zero (grid-stride; covers n + pad tile image) ----------------
__global__ void zero_k(int n, int gx) {
    int tot = (n > GCNT * 128) ? n : GCNT * 128;
    for (int i = blockIdx.x * blockDim.x + threadIdx.x; i < tot;
         i += gridDim.x * blockDim.x) {
        if (i < 256) { g_ssum[i] = 0.f; g_ssq[i] = 0.f; }
        if (i < 128) { g_ssum2[i] = 0.f; g_ssq2[i] = 0.f; }
        if (i < GCNT * 128) { g_ps[i] = 0.f; g_pmx[i] = 0.f; }
        if (i < GCNT) g_cnt[i] = 0.f;
        if (i < n) g_deg[i] = 0;
    }
    // zero the last tile's A-image (pad rows must contribute 0 to raw stats)
    size_t lt = (size_t)(gx - 1) * 32768;
    for (int i = blockIdx.x * blockDim.x + threadIdx.x; i < 32768 / 16;
         i += gridDim.x * blockDim.x) {
        ((uint4*)(g_ahi + lt))[i] = make_uint4(0, 0, 0, 0);
        ((uint4*)(g_alo + lt))[i] = make_uint4(0, 0, 0, 0);
    }
}

// ---------------- CSR build ----------------
__global__ void count_k(const void* __restrict__ ei, long long E) {
    long long e = (long long)blockIdx.x * blockDim.x + threadIdx.x;
    if (e >= E) return;
    int d;
    if (g_i64flag) d = (int)((const long long*)ei)[E + e];
    else           d = ((const int*)ei)[E + e];
    atomicAdd(&g_deg[d], 1);
}

__global__ void scanA_k(int n) {
    __shared__ int sred[256];
    int blk = blockIdx.x, t = threadIdx.x;
    int base = blk * 1024 + t * 4;
    int s = 0;
#pragma unroll
    for (int j = 0; j < 4; j++) {
        int idx = base + j;
        if (idx < n) s += g_deg[idx];
    }
    sred[t] = s;
    __syncthreads();
    for (int o = 128; o > 0; o >>= 1) {
        if (t < o) sred[t] += sred[t + o];
        __syncthreads();
    }
    if (t == 0) g_bsum[blk] = sred[0];
}

__global__ void scanB_k(int nblk) {
    if (threadIdx.x == 0) {
        int run = 0;
        for (int i = 0; i < nblk; i++) { g_bscn[i] = run; run += g_bsum[i]; }
    }
}

__global__ void scanC_k(int n) {
    __shared__ int sth[256];
    int blk = blockIdx.x, t = threadIdx.x;
    int base = blk * 1024 + t * 4;
    int v[4];
    int s = 0;
#pragma unroll
    for (int j = 0; j < 4; j++) {
        int idx = base + j;
        v[j] = (idx < n) ? g_deg[idx] : 0;
        s += v[j];
    }
    sth[t] = s;
    __syncthreads();
    for (int o = 1; o < 256; o <<= 1) {
        int add = (t >= o) ? sth[t - o] : 0;
        __syncthreads();
        sth[t] += add;
        __syncthreads();
    }
    int tpre = (t > 0 ? sth[t - 1] : 0) + g_bscn[blk];
#pragma unroll
    for (int j = 0; j < 4; j++) {
        int idx = base + j;
        if (idx < n) { g_off[idx] = tpre; g_cur[idx] = tpre; }
        tpre += v[j];
    }
}

__global__ void fill_k(const void* __restrict__ ei, long long E) {
    long long e = (long long)blockIdx.x * blockDim.x + threadIdx.x;
    if (e >= E) return;
    int s, d;
    if (g_i64flag) {
        const long long* p = (const long long*)ei;
        s = (int)p[e]; d = (int)p[E + e];
    } else {
        const int* p = (const int*)ei;
        s = p[e]; d = p[E + e];
    }
    int pos = atomicAdd(&g_cur[d], 1);
    if (pos < EMAX) g_csr[pos] = s;
}

__device__ __forceinline__ uint32_t pack_bf16x2(float a, float b) {
    __nv_bfloat162 h = __float22bfloat162_rn(make_float2(a, b));
    return *reinterpret_cast<uint32_t*>(&h);
}

// ---------------- CSR aggregation + bf16 split + swizzled store ----------------
template<bool BN>
__global__ void __launch_bounds__(256) agg_k(
    const float* __restrict__ SRC, const float* __restrict__ epsp, int l, int n,
    const float* __restrict__ gamma, const float* __restrict__ beta, float invM) {
    if (BN && blockIdx.x == 0) {
        g_ssum[threadIdx.x] = 0.f;
        g_ssq[threadIdx.x]  = 0.f;
    }
    int node = (int)(((long long)blockIdx.x * blockDim.x + threadIdx.x) >> 5);
    int lane = threadIdx.x & 31;
    if (node >= n) return;
    float e = 1.0f + epsp[l];

    float sc0, sc1, sc2, sc3, sh0, sh1, sh2, sh3;
    if (BN) {
        int c = lane * 4;
#pragma unroll
        for (int j = 0; j < 4; j++) {
            float m   = g_ssum2[c + j] * invM;
            float var = g_ssq2[c + j] * invM - m * m;
            float sc  = gamma[c + j] * rsqrtf(var + 1e-5f);
            float sh  = beta[c + j] - m * sc;
            if (j == 0) { sc0 = sc; sh0 = sh; }
            else if (j == 1) { sc1 = sc; sh1 = sh; }
            else if (j == 2) { sc2 = sc; sh2 = sh; }
            else { sc3 = sc; sh3 = sh; }
        }
    }
#define FBN(v)                                                                   \
    if (BN) {                                                                    \
        v.x = fmaxf(fmaf(v.x, sc0, sh0), 0.f);                                   \
        v.y = fmaxf(fmaf(v.y, sc1, sh1), 0.f);                                   \
        v.z = fmaxf(fmaf(v.z, sc2, sh2), 0.f);                                   \
        v.w = fmaxf(fmaf(v.w, sc3, sh3), 0.f);                                   \
    }

    int beg = g_off[node];
    int deg = g_deg[node];

    float4 self = ((const float4*)SRC)[(size_t)node * 32 + lane];
    FBN(self);
    float4 a0 = make_float4(self.x * e, self.y * e, self.z * e, self.w * e);
    float4 a1 = make_float4(0.f, 0.f, 0.f, 0.f);
    float4 a2 = make_float4(0.f, 0.f, 0.f, 0.f);
    float4 a3 = make_float4(0.f, 0.f, 0.f, 0.f);

    int i = 0;
    for (; i + 4 <= deg; i += 4) {
        int s0 = g_csr[beg + i];
        int s1 = g_csr[beg + i + 1];
        int s2 = g_csr[beg + i + 2];
        int s3 = g_csr[beg + i + 3];
        float4 v0 = ((const float4*)SRC)[(size_t)s0 * 32 + lane];
        float4 v1 = ((const float4*)SRC)[(size_t)s1 * 32 + lane];
        float4 v2 = ((const float4*)SRC)[(size_t)s2 * 32 + lane];
        float4 v3 = ((const float4*)SRC)[(size_t)s3 * 32 + lane];
        FBN(v0); FBN(v1); FBN(v2); FBN(v3);
        a0.x += v0.x; a0.y += v0.y; a0.z += v0.z; a0.w += v0.w;
        a1.x += v1.x; a1.y += v1.y; a1.z += v1.z; a1.w += v1.w;
        a2.x += v2.x; a2.y += v2.y; a2.z += v2.z; a2.w += v2.w;
        a3.x += v3.x; a3.y += v3.y; a3.z += v3.z; a3.w += v3.w;
    }
    if (i < deg) {
        int rem = deg - i;
        int s0 = g_csr[beg + i];
        int s1 = g_csr[beg + ((rem > 1) ? i + 1 : i)];
        int s2 = g_csr[beg + ((rem > 2) ? i + 2 : i)];
        float4 v0 = ((const float4*)SRC)[(size_t)s0 * 32 + lane];
        float4 v1 = ((const float4*)SRC)[(size_t)s1 * 32 + lane];
        float4 v2 = ((const float4*)SRC)[(size_t)s2 * 32 + lane];
        FBN(v0); FBN(v1); FBN(v2);
        a1.x += v0.x; a1.y += v0.y; a1.z += v0.z; a1.w += v0.w;
        if (rem > 1) { a2.x += v1.x; a2.y += v1.y; a2.z += v1.z; a2.w += v1.w; }
        if (rem > 2) { a3.x += v2.x; a3.y += v2.y; a3.z += v2.z; a3.w += v2.w; }
    }
#undef FBN
    float4 r;
    r.x = (a0.x + a1.x) + (a2.x + a3.x);
    r.y = (a0.y + a1.y) + (a2.y + a3.y);
    r.z = (a0.z + a1.z) + (a2.z + a3.z);
    r.w = (a0.w + a1.w) + (a2.w + a3.w);

    uint32_t h0 = pack_bf16x2(r.x, r.y);
    uint32_t h1 = pack_bf16x2(r.z, r.w);
    __nv_bfloat162 hb0 = *reinterpret_cast<__nv_bfloat162*>(&h0);
    __nv_bfloat162 hb1 = *reinterpret_cast<__nv_bfloat162*>(&h1);
    float2 hr0 = __bfloat1622float2(hb0);
    float2 hr1 = __bfloat1622float2(hb1);
    uint32_t l0 = pack_bf16x2(r.x - hr0.x, r.y - hr0.y);
    uint32_t l1 = pack_bf16x2(r.z - hr1.x, r.w - hr1.y);

    int T = node >> 7, rr = node & 127;
    int c8 = lane >> 4;
    int g8 = (lane >> 1) & 7;
    int half = lane & 1;
    size_t base = ((size_t)T * 2 + c8) * 16384
                + SW128((uint32_t)(rr * 128 + g8 * 16)) + half * 8;
    *(uint2*)(g_ahi + base) = make_uint2(h0, h1);
    *(uint2*)(g_alo + base) = make_uint2(l0, l1);
}

// ================== persistent fused layer kernel ==================
// PASS 1: raw y = A@W1 in TMEM; RAW stats (no bias, pad rows are zero) -> g_ssum/g_ssq.
//          Cross-tile A-ch0 prefetch overlaps the stats epilogue.
// PASS 2: recompute y, BN+ReLU in-register (bias folded into shift), GEMM2 -> h2 + stats.
#define P_PTR   0
#define P_MBAR  16
#define P_SC    32
#define P_SH    1056
#define P_SB    2080
#define P_SSL   3104
#define P_SQL   4128
#define P_PSUM  5152
#define P_PSQ   6176
#define P_A1HI  8192
#define P_A1LO  24576
#define P_B1HI  40960
#define P_B1LO  73728
#define P_SMEM  106496
#define TG_IDESC 0x8200490u

template<int PASS>
__global__ void __launch_bounds__(256, 2) pass_k(
    const uint8_t* __restrict__ Ahi, const uint8_t* __restrict__ Alo,
    const __nv_bfloat16* __restrict__ B1hi, const __nv_bfloat16* __restrict__ B1lo,
    const __nv_bfloat16* __restrict__ B2hi, const __nv_bfloat16* __restrict__ B2lo,
    const float* __restrict__ b1, const float* __restrict__ b2,
    const float* __restrict__ g1, const float* __restrict__ be1, float invM,
    float* __restrict__ C, int M, int ntiles)
{
    extern __shared__ char smem[];
    const uint32_t sb = smem_u32(smem);
    const int t = threadIdx.x, wid = t >> 5, lid = t & 31;
    float* sSc = reinterpret_cast<float*>(smem + P_SC);
    float* sSh = reinterpret_cast<float*>(smem + P_SH);
    float* sB  = reinterpret_cast<float*>(smem + P_SB);
    float* ssl = reinterpret_cast<float*>(smem + P_SSL);
    float* sql = reinterpret_cast<float*>(smem + P_SQL);
    float* psum = reinterpret_cast<float*>(smem + P_PSUM);
    float* psq  = reinterpret_cast<float*>(smem + P_PSQ);
    float* statbuf = reinterpret_cast<float*>(smem + P_B1HI);

    if (PASS == 1 && blockIdx.x == 0 && t < 128) {
        g_ssum2[t] = 0.f;
        g_ssq2[t]  = 0.f;
    }
    if (wid == 0) TC_ALLOC(sb + P_PTR, 256);
    if (t == 0) MB_INIT(sb + P_MBAR, 1);
    if (PASS == 2) {
        // raw stats: mean_raw = ssum*invM ; y = raw + b1 -> fold into shift
        float mraw = g_ssum[t] * invM;
        float var  = g_ssq[t] * invM - mraw * mraw;
        float sc   = g1[t] * rsqrtf(var + 1e-5f);
        sSc[t] = sc;
        sSh[t] = fmaf(-mraw, sc, be1[t]);
        if (t < 128) sB[t] = b2[t];
    }
    __syncthreads();
    uint32_t tmem;
    asm volatile("ld.shared.b32 %0, [%1];" : "=r"(tmem) : "r"(sb + P_PTR));

    const uint64_t dA1hi = make_desc(sb + P_A1HI);
    const uint64_t dA1lo = make_desc(sb + P_A1LO);
    const uint64_t dB1hi = make_desc(sb + P_B1HI);
    const uint64_t dB1lo = make_desc(sb + P_B1LO);

    int pc = 0;

#define CPASYNC_A1(TILE, CH)                                                    \
    {                                                                           \
        size_t abase = ((size_t)(TILE) * 2 + (CH)) * 16384;                     \
        _Pragma("unroll")                                                       \
        for (int it = 0; it < 4; it++) {                                        \
            uint32_t o = (uint32_t)(t + it * 256) * 16;                         \
            CP_ASYNC16(sb + P_A1HI + o, Ahi + abase + o);                       \
            CP_ASYNC16(sb + P_A1LO + o, Alo + abase + o);                       \
        }                                                                       \
    }
#define CPASYNC_B1(CH)                                                          \
    {                                                                           \
        int kb_ = (CH) * 64;                                                    \
        _Pragma("unroll")                                                       \
        for (int it = 0; it < 8; it++) {                                        \
            int idx = t + it * 256;                                             \
            int r_ = idx >> 3, kg_ = idx & 7;                                   \
            uint32_t so_ = SW128((uint32_t)(r_ * 128 + kg_ * 16));              \
            size_t bo_ = (size_t)r_ * 128 + kb_ + kg_ * 8;                      \
            CP_ASYNC16(sb + P_B1HI + so_, B1hi + bo_);                          \
            CP_ASYNC16(sb + P_B1LO + so_, B1lo + bo_);                          \
        }                                                                       \
        CP_COMMIT();                                                            \
    }
#define MMA1_CHUNK(CH)                                                          \
    if (wid == 0 && elect_one()) {                                              \
        _Pragma("unroll")                                                       \
        for (int T = 0; T < 2; T++) {                                           \
            uint64_t bh = dB1hi + T * 1024;                                     \
            uint64_t bl = dB1lo + T * 1024;                                     \
            uint32_t dt = tmem + T * 128;                                       \
            _Pragma("unroll")                                                   \
            for (int s = 0; s < 4; s++)                                         \
                mma_bf16_ss(dt, dA1hi + s * 2, bh + s * 2, TG_IDESC,            \
                            ((CH) == 0 && s == 0) ? 0u : 1u);                   \
            _Pragma("unroll")                                                   \
            for (int s = 0; s < 4; s++)                                         \
                mma_bf16_ss(dt, dA1hi + s * 2, bl + s * 2, TG_IDESC, 1u);       \
            _Pragma("unroll")                                                   \
            for (int s = 0; s < 4; s++)                                         \
                mma_bf16_ss(dt, dA1lo + s * 2, bh + s * 2, TG_IDESC, 1u);       \
        }                                                                       \
        TC_COMMIT(sb + P_MBAR);                                                 \
    }

    // PASS1: prefetch first tile's A-ch0 before the loop
    if (PASS == 1 && blockIdx.x < ntiles) {
        CPASYNC_A1(blockIdx.x, 0);
        CP_COMMIT();
    }

    for (int tile = blockIdx.x; tile < ntiles; tile += gridDim.x) {
        const int bm = tile * 128;

        // -------- phase 1: y = A @ W1 (2 k-chunks) --------
        if (PASS == 2) CPASYNC_A1(tile, 0);   // PASS1: already prefetched
        CPASYNC_B1(0);
        CP_WAIT0();
        FENCE_ASYNC();
        __syncthreads();
        MMA1_CHUNK(0);
        MB_WAIT(sb + P_MBAR, pc & 1); pc++;
        CPASYNC_A1(tile, 1);
        CPASYNC_B1(1);
        CP_WAIT0();
        FENCE_ASYNC();
        __syncthreads();
        MMA1_CHUNK(1);
        MB_WAIT(sb + P_MBAR, pc & 1); pc++;
        TC_FENCE_AFTER();

        if (PASS == 1) {
            // prefetch next tile's A-ch0 (A smem free; overlaps epilogue)
            int nxt = tile + gridDim.x;
            if (nxt < ntiles) {
                __syncthreads();   // all MMA-consumers past; safe to overwrite A
                CPASYNC_A1(nxt, 0);
                CP_COMMIT();
            }
            // -------- RAW y stats (no bias, no mask: pad rows are zero) --------
            for (int pr = 0; pr < 4; pr++) {
                if (wid < 4) {
                    int r = wid * 32 + lid;
                    uint32_t r0[32], r1[32];
                    LDTM32(r0, tmem + pr * 64);
                    LDTM32(r1, tmem + pr * 64 + 32);
                    TC_WAIT_LD();
#pragma unroll
                    for (int i = 0; i < 32; i++) {
                        statbuf[r * 66 + i]      = __uint_as_float(r0[i]);
                        statbuf[r * 66 + 32 + i] = __uint_as_float(r1[i]);
                    }
                }
                __syncthreads();
                {
                    int c = t & 63, h = t >> 6;
                    float s = 0.f, q = 0.f;
#pragma unroll 8
                    for (int rr = 0; rr < 32; rr++) {
                        float v = statbuf[(h * 32 + rr) * 66 + c];
                        s += v;
                        q = fmaf(v, v, q);
                    }
                    psum[h * 64 + c] = s;
                    psq[h * 64 + c]  = q;
                }
                __syncthreads();
                if (t < 64) {
                    ssl[pr * 64 + t] = psum[t] + psum[64 + t] + psum[128 + t] + psum[192 + t];
                    sql[pr * 64 + t] = psq[t]  + psq[64 + t]  + psq[128 + t]  + psq[192 + t];
                }
                __syncthreads();
            }
            if (wid < 4) TC_FENCE_BEFORE();
            __syncthreads();
            atomicAdd(&g_ssum[t], ssl[t]);
            atomicAdd(&g_ssq[t],  sql[t]);
            __syncthreads();
        } else {
            // -------- phase 2: h2 = bnrelu(y) @ W2 + b2 --------
            const uint64_t dB2hi = make_desc(sb + P_A1HI);
            const uint64_t dB2lo = make_desc(sb + P_A1LO);

#define CPASYNC_B2_HALF(CH)                                                     \
    {                                                                           \
        int kb_ = (CH) * 64;                                                    \
        _Pragma("unroll")                                                       \
        for (int it = 0; it < 8; it++) {                                        \
            int idx = (t - 128) + it * 128;                                     \
            int r_ = idx >> 3, kg_ = idx & 7;                                   \
            uint32_t so_ = SW128((uint32_t)(r_ * 128 + kg_ * 16));              \
            size_t bo_ = (size_t)r_ * 256 + kb_ + kg_ * 8;                      \
            CP_ASYNC16(sb + P_A1HI + so_, B2hi + bo_);                          \
            CP_ASYNC16(sb + P_A1LO + so_, B2lo + bo_);                          \
        }                                                                       \
        CP_COMMIT();                                                            \
        CP_WAIT0();                                                             \
    }
#define CPASYNC_B2_ALL(CH)                                                      \
    {                                                                           \
        int kb_ = (CH) * 64;                                                    \
        _Pragma("unroll")                                                       \
        for (int it = 0; it < 4; it++) {                                        \
            int idx = t + it * 256;                                             \
            int r_ = idx >> 3, kg_ = idx & 7;                                   \
            uint32_t so_ = SW128((uint32_t)(r_ * 128 + kg_ * 16));              \
            size_t bo_ = (size_t)r_ * 256 + kb_ + kg_ * 8;                      \
            CP_ASYNC16(sb + P_A1HI + so_, B2hi + bo_);                          \
            CP_ASYNC16(sb + P_A1LO + so_, B2lo + bo_);                          \
        }                                                                       \
        CP_COMMIT();                                                            \
        CP_WAIT0();                                                             \
    }
#define MMA2(SLOT, EN0)                                                         \
    if (wid == 0 && elect_one()) {                                              \
        uint64_t ah = make_desc(sb + P_B1HI + (SLOT) * 16384);                  \
        uint64_t al = make_desc(sb + P_B1LO + (SLOT) * 16384);                  \
        _Pragma("unroll")                                                       \
        for (int s = 0; s < 4; s++)                                             \
            mma_bf16_ss(tmem, ah + s * 2, dB2hi + s * 2, TG_IDESC,              \
                        ((EN0) && s == 0) ? 0u : 1u);                           \
        _Pragma("unroll")                                                       \
        for (int s = 0; s < 4; s++)                                             \
            mma_bf16_ss(tmem, ah + s * 2, dB2lo + s * 2, TG_IDESC, 1u);         \
        _Pragma("unroll")                                                       \
        for (int s = 0; s < 4; s++)                                             \
            mma_bf16_ss(tmem, al + s * 2, dB2hi + s * 2, TG_IDESC, 1u);         \
        TC_COMMIT(sb + P_MBAR);                                                 \
    }

#pragma unroll
            for (int half = 0; half < 2; half++) {
                if (wid < 4) {
                    int r = wid * 32 + lid;
#pragma unroll
                    for (int p2 = 0; p2 < 2; p2++) {
                        int b0 = half * 4 + p2 * 2;
                        uint32_t r0[32], r1[32];
                        LDTM32(r0, tmem + b0 * 32);
                        LDTM32(r1, tmem + (b0 + 1) * 32);
                        TC_WAIT_LD();
                        float v[64];
#pragma unroll
                        for (int i = 0; i < 32; i++) {
                            int c0 = b0 * 32 + i, c1 = (b0 + 1) * 32 + i;
                            v[i]      = fmaxf(fmaf(__uint_as_float(r0[i]), sSc[c0], sSh[c0]), 0.f);
                            v[32 + i] = fmaxf(fmaf(__uint_as_float(r1[i]), sSc[c1], sSh[c1]), 0.f);
                        }
#pragma unroll
                        for (int bb = 0; bb < 2; bb++) {
                            int blk = b0 + bb;
                            int slot = (blk >> 1) & 1;
                            const float* vv = v + bb * 32;
#pragma unroll
                            for (int q = 0; q < 4; q++) {
                                uint32_t h[4], lo[4];
#pragma unroll
                                for (int p = 0; p < 4; p++) {
                                    float a0 = vv[q * 8 + p * 2], a1 = vv[q * 8 + p * 2 + 1];
                                    h[p] = pack_bf16x2(a0, a1);
                                    __nv_bfloat162 hb = *reinterpret_cast<__nv_bfloat162*>(&h[p]);
                                    float2 hr = __bfloat1622float2(hb);
                                    lo[p] = pack_bf16x2(a0 - hr.x, a1 - hr.y);
                                }
                                uint32_t so = SW128((uint32_t)(r * 128 + (blk & 1) * 64 + q * 16));
                                *(uint4*)(smem + P_B1HI + slot * 16384 + so) = make_uint4(h[0], h[1], h[2], h[3]);
                                *(uint4*)(smem + P_B1LO + slot * 16384 + so) = make_uint4(lo[0], lo[1], lo[2], lo[3]);
                            }
                        }
                    }
                    TC_FENCE_BEFORE();
                } else {
                    CPASYNC_B2_HALF(2 * half);
                }
                FENCE_ASYNC();
                __syncthreads();
                MMA2(0, half == 0);
                MB_WAIT(sb + P_MBAR, pc & 1); pc++;
                CPASYNC_B2_ALL(2 * half + 1);
                FENCE_ASYNC();
                __syncthreads();
                MMA2(1, false);
                MB_WAIT(sb + P_MBAR, pc & 1); pc++;
                TC_FENCE_AFTER();
            }

#undef CPASYNC_B2_HALF
#undef CPASYNC_B2_ALL
#undef MMA2

            // -------- final epilogue: h2 --------
            for (int pr = 0; pr < 2; pr++) {
                if (wid < 4) {
                    int r = wid * 32 + lid;
                    int grow = bm + r;
                    uint32_t r0[32], r1[32];
                    LDTM32(r0, tmem + pr * 64);
                    LDTM32(r1, tmem + pr * 64 + 32);
                    TC_WAIT_LD();
                    float v0[32], v1[32];
#pragma unroll
                    for (int i = 0; i < 32; i++) {
                        v0[i] = __uint_as_float(r0[i]) + sB[pr * 64 + i];
                        v1[i] = __uint_as_float(r1[i]) + sB[pr * 64 + 32 + i];
                    }
                    if (grow < M) {
                        float* cp = C + (size_t)grow * 128 + pr * 64;
#pragma unroll
                        for (int q = 0; q < 8; q++) {
                            *(float4*)(cp + q * 4)      = *(float4*)(v0 + q * 4);
                            *(float4*)(cp + 32 + q * 4) = *(float4*)(v1 + q * 4);
                        }
                    } else {
#pragma unroll
                        for (int i = 0; i < 32; i++) { v0[i] = 0.f; v1[i] = 0.f; }
                    }
#pragma unroll
                    for (int i = 0; i < 32; i++) {
                        statbuf[r * 66 + i]      = v0[i];
                        statbuf[r * 66 + 32 + i] = v1[i];
                    }
                }
                __syncthreads();
                {
                    int c = t & 63, h = t >> 6;
                    float s = 0.f, q = 0.f;
#pragma unroll 8
                    for (int rr = 0; rr < 32; rr++) {
                        float vv = statbuf[(h * 32 + rr) * 66 + c];
                        s += vv;
                        q = fmaf(vv, vv, q);
                    }
                    psum[h * 64 + c] = s;
                    psq[h * 64 + c]  = q;
                }
                __syncthreads();
                if (t < 64) {
                    ssl[pr * 64 + t] = psum[t] + psum[64 + t] + psum[128 + t] + psum[192 + t];
                    sql[pr * 64 + t] = psq[t]  + psq[64 + t]  + psq[128 + t]  + psq[192 + t];
                }
                __syncthreads();
            }
            if (wid < 4) TC_FENCE_BEFORE();
            __syncthreads();
            if (t < 128) {
                atomicAdd(&g_ssum2[t], ssl[t]);
                atomicAdd(&g_ssq2[t],  sql[t]);
            }
            __syncthreads();
        }
    }

#undef CPASYNC_A1
#undef CPASYNC_B1
#undef MMA1_CHUNK

    CP_WAIT0();   // drain any dangling prefetch
    if (t == 0) MB_INVAL(sb + P_MBAR);
    if (wid == 0) TC_DEALLOC(tmem, 256);
}

// ---------------- readout pooling (computes outer BN inline) ----------------
__global__ void pool_k(const void* __restrict__ batch, int n,
                       const float* __restrict__ gamma, const float* __restrict__ beta,
                       float invM) {
    long long t = (long long)blockIdx.x * blockDim.x + threadIdx.x;
    long long i = t >> 5;
    if (i >= n) return;
    int lane = (int)(t & 31);
    long long g;
    if (g_i64flag) g = ((const long long*)batch)[i];
    else           g = (long long)((const int*)batch)[i];
    int c = lane * 4;
    float sc[4], sh[4];
#pragma unroll
    for (int j = 0; j < 4; j++) {
        float m   = g_ssum2[c + j] * invM;
        float var = g_ssq2[c + j] * invM - m * m;
        sc[j] = gamma[c + j] * rsqrtf(var + 1e-5f);
        sh[j] = beta[c + j] - m * sc[j];
    }
    float4 v = ((const float4*)g_h2)[i * 32 + lane];
    float r0 = fmaxf(fmaf(v.x, sc[0], sh[0]), 0.f);
    float r1 = fmaxf(fmaf(v.y, sc[1], sh[1]), 0.f);
    float r2 = fmaxf(fmaf(v.z, sc[2], sh[2]), 0.f);
    float r3 = fmaxf(fmaf(v.w, sc[3], sh[3]), 0.f);
    float* ps = g_ps + g * 128 + c;
    asm volatile("red.global.add.v4.f32 [%0], {%1, %2, %3, %4};"
                 :: "l"(ps), "f"(r0), "f"(r1), "f"(r2), "f"(r3) : "memory");
    unsigned int* mx = (unsigned int*)(g_pmx + g * 128 + c);
    atomicMax(mx + 0, __float_as_uint(r0));
    atomicMax(mx + 1, __float_as_uint(r1));
    atomicMax(mx + 2, __float_as_uint(r2));
    atomicMax(mx + 3, __float_as_uint(r3));
    if (lane == 0) atomicAdd(&g_cnt[g], 1.0f);
}

// ---------------- classifier ----------------
__global__ void cgemm1_k(const float* __restrict__ cW1, const float* __restrict__ cb1) {
    int g = blockIdx.x;
    int j = threadIdx.x;
    __shared__ float z[384];
    float cnt = fmaxf(g_cnt[g], 1.0f);
    float sv = g_ps[g * 128 + j];
    z[j]       = sv;
    z[128 + j] = sv / cnt;
    z[256 + j] = g_pmx[g * 128 + j];
    __syncthreads();
    float acc = cb1[j];
#pragma unroll 8
    for (int k = 0; k < 384; k++)
        acc = fmaf(z[k], cW1[k * 128 + j], acc);
    g_z1[g * 128 + j] = acc;
}

__global__ void cstats_k(const float* __restrict__ cg, const float* __restrict__ cbeta) {
    int j = threadIdx.x;
    float s = 0.f, q = 0.f;
    for (int g = 0; g < GCNT; g++) {
        float v = g_z1[g * 128 + j];
        s += v; q += v * v;
    }
    float m   = s * (1.0f / GCNT);
    float var = q * (1.0f / GCNT) - m * m;
    float sc  = cg[j] * rsqrtf(var + 1e-5f);
    g_scale[j] = sc;
    g_shift[j] = cbeta[j] - m * sc;
}

__global__ void chead_k(const float* __restrict__ cW2, const float* __restrict__ cb2,
                        const float* __restrict__ cW3, const float* __restrict__ cb3,
                        float* __restrict__ out) {
    int g = blockIdx.x;
    int j = threadIdx.x;
    __shared__ float a[128];
    __shared__ float z2[64];
    for (int k = j; k < 128; k += 64)
        a[k] = fmaxf(fmaf(g_z1[g * 128 + k], g_scale[k], g_shift[k]), 0.f);
    __syncthreads();
    float acc = cb2[j];
#pragma unroll 8
    for (int k = 0; k < 128; k++)
        acc = fmaf(a[k], cW2[k * 64 + j], acc);
    z2[j] = fmaxf(acc, 0.f);
    __syncthreads();
    if (j < 2) {
        float o = cb3[j];
#pragma unroll 8
        for (int k = 0; k < 64; k++)
            o = fmaf(z2[k], cW3[k * 2 + j], o);
        out[g * 2 + j] = o;
    }
}

// ---------------- launcher ----------------
extern "C" void kernel_launch(void* const* d_in, const int* in_sizes, int n_in,
                              void* d_out, int out_size) {
    const float* x     = (const float*)d_in[0];
    const void*  ei    = d_in[1];
    const void*  batch = d_in[2];
    int base = (in_sizes[3] == 1) ? 4 : 3;
    const float* W1    = (const float*)d_in[base + 0];
    const float* b1    = (const float*)d_in[base + 1];
    const float* g1    = (const float*)d_in[base + 2];
    const float* be1   = (const float*)d_in[base + 3];
    const float* W2    = (const float*)d_in[base + 4];
    const float* b2    = (const float*)d_in[base + 5];
    const float* gbn   = (const float*)d_in[base + 6];
    const float* bbn   = (const float*)d_in[base + 7];
    const float* eps   = (const float*)d_in[base + 8];
    const float* cW1   = (const float*)d_in[base + 9];
    const float* cb1   = (const float*)d_in[base + 10];
    const float* cg    = (const float*)d_in[base + 11];
    const float* cbeta = (const float*)d_in[base + 12];
    const float* cW2   = (const float*)d_in[base + 13];
    const float* cb2   = (const float*)d_in[base + 14];
    const float* cW3   = (const float*)d_in[base + 15];
    const float* cb3   = (const float*)d_in[base + 16];

    int n = in_sizes[0] / 128;
    long long E = (long long)in_sizes[1] / 2;
    int n32 = n * 32;
    int nb = (n32 + 255) / 256;
    int gx = (n + 127) / 128;
    int pgrid = (gx < 296) ? gx : 296;
    int eblk = (int)((E + 255) / 256);
    int nscan = (n + 1023) / 1024;
    int ablk = (n * 32 + 255) / 256;
    float invM = 1.0f / (float)n;

    static int smem_set = 0;
    if (!smem_set) {
        cudaFuncSetAttribute(pass_k<1>, cudaFuncAttributeMaxDynamicSharedMemorySize, P_SMEM);
        cudaFuncSetAttribute(pass_k<2>, cudaFuncAttributeMaxDynamicSharedMemorySize, P_SMEM);
        smem_set = 1;
    }

    float *p_h2;
    uint8_t *p_ahi, *p_alo;
    __nv_bfloat16 *p_b1hi, *p_b1lo, *p_b2hi, *p_b2lo;
    cudaGetSymbolAddress((void**)&p_h2,  g_h2);
    cudaGetSymbolAddress((void**)&p_ahi, g_ahi);
    cudaGetSymbolAddress((void**)&p_alo, g_alo);
    cudaGetSymbolAddress((void**)&p_b1hi, g_b1hi);
    cudaGetSymbolAddress((void**)&p_b1lo, g_b1lo);
    cudaGetSymbolAddress((void**)&p_b2hi, g_b2hi);
    cudaGetSymbolAddress((void**)&p_b2lo, g_b2lo);

    detect_k<<<1, 1>>>((const unsigned int*)ei);
    wconv_k<<<(NLAYER * 256 * 128 + 255) / 256, 256>>>(W1, W2);
    zero_k<<<512, 256>>>(n, gx);

    // CSR build (once; edges shared by all layers)
    count_k<<<eblk, 256>>>(ei, E);
    scanA_k<<<nscan, 256>>>(n);
    scanB_k<<<1, 32>>>(nscan);
    scanC_k<<<nscan, 256>>>(n);
    fill_k<<<eblk, 256>>>(ei, E);

    for (int l = 0; l < 4; l++) {
        if (l == 0)
            agg_k<false><<<ablk, 256>>>(x, eps, l, n, nullptr, nullptr, invM);
        else
            agg_k<true><<<ablk, 256>>>(p_h2, eps, l, n,
                                       gbn + (l - 1) * 128, bbn + (l - 1) * 128, invM);

        pass_k<1><<<pgrid, 256, P_SMEM>>>(
            p_ahi, p_alo,
            p_b1hi + (size_t)l * 32768, p_b1lo + (size_t)l * 32768,
            p_b2hi + (size_t)l * 32768, p_b2lo + (size_t)l * 32768,
            b1 + l * 256, b2 + l * 128, g1 + l * 256, be1 + l * 256, invM,
            nullptr, n, gx);
        pass_k<2><<<pgrid, 256, P_SMEM>>>(
            p_ahi, p_alo,
            p_b1hi + (size_t)l * 32768, p_b1lo + (size_t)l * 32768,
            p_b2hi + (size_t)l * 32768, p_b2lo + (size_t)l * 32768,
            b1 + l * 256, b2 + l * 128, g1 + l * 256, be1 + l * 256, invM,
            p_h2, n, gx);
    }

    pool_k<<<nb, 256>>>(batch, n, gbn + 3 * 128, bbn + 3 * 128, invM);
    cgemm1_k<<<GCNT, 128>>>(cW1, cb1);
    cstats_k<<<1, 128>>>(cg, cbeta);
    chead_k<<<GCNT, 64>>>(cW2, cb2, cW3, cb3, (float*)d_out);
}